// round 8
// baseline (speedup 1.0000x reference)
#include <cuda_runtime.h>
#include <cuda_bf16.h>
#include <cstdint>

#define BB 4
#define NN 4096
#define CC 1024
#define HH 16
#define DH 64
#define RR 266
#define RP 288
#define EPSF 1e-3f
#define BHN (BB*HH)   // 64
#define GM (BB*NN)    // 16384
#define GK 1024
#define GN 1024
#define KC 32
#define NCH (GK/KC)        // 32 chunks
#define MAT_BYTES (128*80) // 128 rows x 80B
#define STAGE_BYTES (4*MAT_BYTES)  // 40960
#define NSTAGE 4
#define SMEM_DYN (NSTAGE*STAGE_BYTES)   // 163840
// featmap smem: A h/l (2*128*144) + proj h/l (2*320*144)
#define FM_SMEM (2*128*144 + 2*320*144)  // 129024
// qkv smem
#define QKV_STAGE (2*128*80 + 2*64*80)   // 30720
#define QKV_SMEM (2*QKV_STAGE)           // 61440

// ---------------- scratch (device globals; no allocation allowed) ----------
__device__ float g_v [GM*GK];
__device__ float g_ksum[BHN*RP];
__device__ float g_dinv[BHN*NN];
__device__ __nv_bfloat16 g_xh[(size_t)GM*GK];
__device__ __nv_bfloat16 g_xl[(size_t)GM*GK];
__device__ __nv_bfloat16 g_qh[(size_t)GM*GK];
__device__ __nv_bfloat16 g_ql[(size_t)GM*GK];
__device__ __nv_bfloat16 g_kh[(size_t)GM*GK];
__device__ __nv_bfloat16 g_kl[(size_t)GM*GK];
__device__ __nv_bfloat16 g_omh[(size_t)GM*GK];
__device__ __nv_bfloat16 g_oml[(size_t)GM*GK];
__device__ __nv_bfloat16 g_wth[(size_t)4*GN*GK];
__device__ __nv_bfloat16 g_wtl[(size_t)4*GN*GK];
__device__ __nv_bfloat16 g_projh[320*64];
__device__ __nv_bfloat16 g_projl[320*64];
__device__ __nv_bfloat16 g_qph[(size_t)BHN*NN*RP];
__device__ __nv_bfloat16 g_qpl[(size_t)BHN*NN*RP];
__device__ __nv_bfloat16 g_kph[(size_t)BHN*NN*RP];
__device__ __nv_bfloat16 g_kpl[(size_t)BHN*NN*RP];
__device__ __nv_bfloat16 g_kvTh[BHN*64*RP];
__device__ __nv_bfloat16 g_kvTl[BHN*64*RP];

// ---------------- helpers ----------------------------------------------------
__device__ __forceinline__ uint32_t smem_u32(const void* p) {
    uint32_t a;
    asm("{ .reg .u64 t; cvta.to.shared.u64 t, %1; cvt.u32.u64 %0, t; }"
        : "=r"(a) : "l"(p));
    return a;
}
__device__ __forceinline__ void cpa16(uint32_t dst, const void* src) {
    asm volatile("cp.async.cg.shared.global [%0], [%1], 16;" :: "r"(dst), "l"(src));
}
__device__ __forceinline__ void ldsm4(uint32_t* r, uint32_t addr) {
    asm volatile("ldmatrix.sync.aligned.m8n8.x4.shared.b16 {%0,%1,%2,%3}, [%4];"
        : "=r"(r[0]), "=r"(r[1]), "=r"(r[2]), "=r"(r[3]) : "r"(addr));
}
__device__ __forceinline__ void mma16816(float* d, const uint32_t* a, const uint32_t* b) {
    asm volatile(
        "mma.sync.aligned.m16n8k16.row.col.f32.bf16.bf16.f32 "
        "{%0,%1,%2,%3}, {%4,%5,%6,%7}, {%8,%9}, {%0,%1,%2,%3};"
        : "+f"(d[0]), "+f"(d[1]), "+f"(d[2]), "+f"(d[3])
        : "r"(a[0]), "r"(a[1]), "r"(a[2]), "r"(a[3]), "r"(b[0]), "r"(b[1]));
}
__device__ __forceinline__ void split2(float v, __nv_bfloat16& h, __nv_bfloat16& l) {
    h = __float2bfloat16(v);
    l = __float2bfloat16(v - __bfloat162float(h));
}

// ---------------- HMMA split-bf16 GEMM, 4-stage pipeline ---------------------
// mode 0: merged QKV (grid x = 24): n<1024 -> g_qh/ql, <2048 -> g_kh/kl, else g_v fp32
// mode 1: final (grid x = 8): fp32 Cf + bias
__global__ __launch_bounds__(256) void gemm_hmma(
    const __nv_bfloat16* __restrict__ Ah, const __nv_bfloat16* __restrict__ Al,
    const __nv_bfloat16* __restrict__ Bh, const __nv_bfloat16* __restrict__ Bl,
    const float* __restrict__ bias, float* __restrict__ Cf, int mode)
{
    extern __shared__ char smem[];
    const int tid = threadIdx.x;
    const int wid = tid >> 5, lane = tid & 31;
    const int m0 = blockIdx.y * 128, n0 = blockIdx.x * 128;
    const int wr = wid >> 2, wc = wid & 3;

    const __nv_bfloat16* gsrc0 = Ah + (size_t)m0 * GK;
    const __nv_bfloat16* gsrc1 = Al + (size_t)m0 * GK;
    const __nv_bfloat16* gsrc2 = Bh + (size_t)n0 * GK;
    const __nv_bfloat16* gsrc3 = Bl + (size_t)n0 * GK;

    float acc[4][4][4] = {};

    auto load_stage = [&](int c, int st) {
        if (c < NCH) {
            const int k0 = c * KC;
            char* dstb = smem + st * STAGE_BYTES;
            #pragma unroll
            for (int i = 0; i < 8; i++) {
                int idx = tid + i * 256;
                int mat = idx >> 9;
                int row = (idx >> 2) & 127;
                int c16 = idx & 3;
                uint32_t dst = smem_u32(dstb + mat * MAT_BYTES + row * 80 + c16 * 16);
                const __nv_bfloat16* g =
                    (mat == 0) ? gsrc0 : (mat == 1) ? gsrc1 : (mat == 2) ? gsrc2 : gsrc3;
                cpa16(dst, g + (size_t)row * GK + k0 + c16 * 8);
            }
        }
        asm volatile("cp.async.commit_group;" ::: "memory");
    };

    load_stage(0, 0);
    load_stage(1, 1);
    load_stage(2, 2);

    for (int c = 0; c < NCH; c++) {
        asm volatile("cp.async.wait_group 2;" ::: "memory");
        __syncthreads();
        load_stage(c + 3, (c + 3) & (NSTAGE - 1));

        const int st = c & (NSTAGE - 1);
        const uint32_t aH = smem_u32(smem + st * STAGE_BYTES);
        const uint32_t aL = aH + MAT_BYTES;
        const uint32_t bH = aH + 2 * MAT_BYTES;
        const uint32_t bL = aH + 3 * MAT_BYTES;

        #pragma unroll
        for (int kt = 0; kt < 2; kt++) {
            uint32_t ah[4][4], al[4][4], bh[2][4], bl[2][4];
            const int arow = wr * 64 + (lane & 15);
            const uint32_t akoff = (uint32_t)(kt * 16 + (lane >> 4) * 8) * 2;
            #pragma unroll
            for (int mt = 0; mt < 4; mt++) {
                ldsm4(ah[mt], aH + (uint32_t)(arow + mt * 16) * 80 + akoff);
                ldsm4(al[mt], aL + (uint32_t)(arow + mt * 16) * 80 + akoff);
            }
            const int g = lane >> 3;
            const int brow = wc * 32 + (lane & 7) + (g >> 1) * 8;
            const uint32_t bkoff = (uint32_t)(kt * 16 + (g & 1) * 8) * 2;
            #pragma unroll
            for (int nt2 = 0; nt2 < 2; nt2++) {
                ldsm4(bh[nt2], bH + (uint32_t)(brow + nt2 * 16) * 80 + bkoff);
                ldsm4(bl[nt2], bL + (uint32_t)(brow + nt2 * 16) * 80 + bkoff);
            }
            #pragma unroll
            for (int mt = 0; mt < 4; mt++)
                #pragma unroll
                for (int nt = 0; nt < 4; nt++) {
                    const uint32_t* bhp = &bh[nt >> 1][(nt & 1) * 2];
                    const uint32_t* blp = &bl[nt >> 1][(nt & 1) * 2];
                    mma16816(acc[mt][nt], ah[mt], bhp);
                    mma16816(acc[mt][nt], ah[mt], blp);
                    mma16816(acc[mt][nt], al[mt], bhp);
                }
        }
        __syncthreads();
    }

    // ---- epilogue
    float* outf = nullptr;
    __nv_bfloat16 *och = nullptr, *ocl = nullptr;
    int cbase = n0;
    bool use_bias = false;
    if (mode == 1) { outf = Cf; use_bias = true; }
    else if (n0 < 1024) { och = g_qh; ocl = g_ql; }
    else if (n0 < 2048) { och = g_kh; ocl = g_kl; cbase = n0 - 1024; }
    else { outf = g_v; cbase = n0 - 2048; }

    const int qr = lane >> 2, qc = lane & 3;
    #pragma unroll
    for (int mt = 0; mt < 4; mt++) {
        #pragma unroll
        for (int nt = 0; nt < 4; nt++) {
            int row = m0 + wr * 64 + mt * 16 + qr;
            int col = cbase + wc * 32 + nt * 8 + qc * 2;
            if (outf) {
                float bx = 0.f, by = 0.f;
                if (use_bias) { bx = bias[col]; by = bias[col + 1]; }
                float2 v0 = {acc[mt][nt][0] + bx, acc[mt][nt][1] + by};
                float2 v1 = {acc[mt][nt][2] + bx, acc[mt][nt][3] + by};
                *(float2*)&outf[(size_t)row * GN + col] = v0;
                *(float2*)&outf[(size_t)(row + 8) * GN + col] = v1;
            } else {
                #pragma unroll
                for (int hf = 0; hf < 2; hf++) {
                    int r = row + hf * 8;
                    __nv_bfloat16 h0, l0, h1, l1;
                    split2(acc[mt][nt][hf * 2 + 0], h0, l0);
                    split2(acc[mt][nt][hf * 2 + 1], h1, l1);
                    *(__nv_bfloat162*)&och[(size_t)r * GN + col] = __nv_bfloat162{h0, h1};
                    *(__nv_bfloat162*)&ocl[(size_t)r * GN + col] = __nv_bfloat162{l0, l1};
                }
            }
        }
    }
}

// ---------------- fp32 -> bf16 hi/lo split (x only) --------------------------
__global__ __launch_bounds__(256) void split_kernel(
    const float* __restrict__ in, __nv_bfloat16* __restrict__ hi,
    __nv_bfloat16* __restrict__ lo, int n4)
{
    int i = blockIdx.x * blockDim.x + threadIdx.x;
    if (i >= n4) return;
    float4 v = ((const float4*)in)[i];
    float vv[4] = {v.x, v.y, v.z, v.w};
    __nv_bfloat16 h[4], l[4];
    #pragma unroll
    for (int j = 0; j < 4; j++) split2(vv[j], h[j], l[j]);
    ((__nv_bfloat162*)hi)[2*i+0] = __nv_bfloat162{h[0], h[1]};
    ((__nv_bfloat162*)hi)[2*i+1] = __nv_bfloat162{h[2], h[3]};
    ((__nv_bfloat162*)lo)[2*i+0] = __nv_bfloat162{l[0], l[1]};
    ((__nv_bfloat162*)lo)[2*i+1] = __nv_bfloat162{l[2], l[3]};
}

// ---------------- transpose + split weights: W[K][N] -> Wt hi/lo [N][K] -----
__global__ void wsplit_t(const float* __restrict__ W,
                         __nv_bfloat16* __restrict__ th,
                         __nv_bfloat16* __restrict__ tl)
{
    __shared__ float t[32][33];
    const int k0 = blockIdx.y * 32, n0 = blockIdx.x * 32;
    for (int i = threadIdx.y; i < 32; i += 8)
        t[i][threadIdx.x] = W[(size_t)(k0 + i) * GN + n0 + threadIdx.x];
    __syncthreads();
    for (int i = threadIdx.y; i < 32; i += 8) {
        float v = t[threadIdx.x][i];
        __nv_bfloat16 h, l;
        split2(v, h, l);
        size_t o = (size_t)(n0 + i) * GK + k0 + threadIdx.x;
        th[o] = h;
        tl[o] = l;
    }
}

// ---------------- proj split (padded to 320 rows, zero fill) -----------------
__global__ void psplit(const float* __restrict__ proj)
{
    int i = blockIdx.x * 256 + threadIdx.x;
    if (i >= 320 * 64) return;
    int r = i >> 6, d = i & 63;
    float v = (r < RR) ? proj[r * 64 + d] : 0.0f;
    __nv_bfloat16 h, l;
    split2(v, h, l);
    g_projh[i] = h;
    g_projl[i] = l;
}

// ---------------- featmap HMMA: all 5 r0 tiles per block ---------------------
// grid (32, 128), 256 threads, dyn smem FM_SMEM
__global__ __launch_bounds__(256) void featmap_hmma()
{
    extern __shared__ char smem[];
    const int tid = threadIdx.x, wid = tid >> 5, lane = tid & 31;
    const int n0 = blockIdx.x * 128;
    const int z = blockIdx.y;
    const int which = z >> 6, bh = z & 63;
    const int b = bh >> 4, h = bh & 15;
    const __nv_bfloat16* __restrict__ Ahg = which ? g_kh : g_qh;
    const __nv_bfloat16* __restrict__ Alg = which ? g_kl : g_ql;
    __nv_bfloat16* __restrict__ dsth = which ? g_kph : g_qph;
    __nv_bfloat16* __restrict__ dstl = which ? g_kpl : g_qpl;
    const size_t abase = ((size_t)(b * NN + n0)) * GK + h * 64;

    const uint32_t sA_h = smem_u32(smem);
    const uint32_t sA_l = sA_h + 128 * 144;
    const uint32_t sP_h = sA_h + 2 * 128 * 144;
    const uint32_t sP_l = sP_h + 320 * 144;

    #pragma unroll
    for (int i = 0; i < 28; i++) {
        int idx = tid + i * 256;           // [0, 7168)
        if (idx < 1024) {
            int row = idx >> 3, c = idx & 7;
            cpa16(sA_h + row * 144 + c * 16, Ahg + abase + (size_t)row * GK + c * 8);
        } else if (idx < 2048) {
            int j = idx - 1024; int row = j >> 3, c = j & 7;
            cpa16(sA_l + row * 144 + c * 16, Alg + abase + (size_t)row * GK + c * 8);
        } else if (idx < 4608) {
            int j = idx - 2048; int row = j >> 3, c = j & 7;
            cpa16(sP_h + row * 144 + c * 16, g_projh + row * 64 + c * 8);
        } else {
            int j = idx - 4608; int row = j >> 3, c = j & 7;
            cpa16(sP_l + row * 144 + c * 16, g_projl + row * 64 + c * 8);
        }
    }
    asm volatile("cp.async.commit_group;" ::: "memory");
    asm volatile("cp.async.wait_group 0;" ::: "memory");
    __syncthreads();

    const int wr = wid >> 2, wc = wid & 3;
    const int qr = lane >> 2, qc = lane & 3;

    for (int r0i = 0; r0i < 5; r0i++) {
        const int r0 = r0i * 64;
        float acc[4][2][4] = {};

        #pragma unroll
        for (int kt = 0; kt < 4; kt++) {
            uint32_t ah[4][4], al[4][4], bh1[4], bl1[4];
            const int arow = wr * 64 + (lane & 15);
            const uint32_t ak = (uint32_t)(kt * 16 + (lane >> 4) * 8) * 2;
            #pragma unroll
            for (int mt = 0; mt < 4; mt++) {
                ldsm4(ah[mt], sA_h + (uint32_t)(arow + mt * 16) * 144 + ak);
                ldsm4(al[mt], sA_l + (uint32_t)(arow + mt * 16) * 144 + ak);
            }
            const int g = lane >> 3;
            const int brow = r0 + wc * 16 + (lane & 7) + (g >> 1) * 8;
            const uint32_t bk = (uint32_t)(kt * 16 + (g & 1) * 8) * 2;
            ldsm4(bh1, sP_h + (uint32_t)brow * 144 + bk);
            ldsm4(bl1, sP_l + (uint32_t)brow * 144 + bk);
            #pragma unroll
            for (int mt = 0; mt < 4; mt++)
                #pragma unroll
                for (int nt = 0; nt < 2; nt++) {
                    mma16816(acc[mt][nt], ah[mt], &bh1[nt * 2]);
                    mma16816(acc[mt][nt], ah[mt], &bl1[nt * 2]);
                    mma16816(acc[mt][nt], al[mt], &bh1[nt * 2]);
                }
        }

        #pragma unroll
        for (int mt = 0; mt < 4; mt++)
            #pragma unroll
            for (int nt = 0; nt < 2; nt++) {
                int r = r0 + wc * 16 + nt * 8 + qc * 2;
                if (r >= RP) continue;
                bool valid = (r < RR);
                #pragma unroll
                for (int hf = 0; hf < 2; hf++) {
                    int nrow = n0 + wr * 64 + mt * 16 + qr + hf * 8;
                    float v0 = acc[mt][nt][hf * 2 + 0];
                    float v1 = acc[mt][nt][hf * 2 + 1];
                    v0 = valid ? (fmaxf(v0, 0.0f) + EPSF) : 0.0f;
                    v1 = valid ? (fmaxf(v1, 0.0f) + EPSF) : 0.0f;
                    __nv_bfloat16 h0, l0, h1, l1;
                    split2(v0, h0, l0);
                    split2(v1, h1, l1);
                    size_t o = ((size_t)bh * NN + nrow) * RP + r;
                    *(__nv_bfloat162*)&dsth[o] = __nv_bfloat162{h0, h1};
                    *(__nv_bfloat162*)&dstl[o] = __nv_bfloat162{l0, l1};
                }
            }
    }
}

// ---------------- k_sum = sum_n kp -------------------------------------------
__global__ void ksum_kernel()
{
    const int bh = blockIdx.x;
    const int r = blockIdx.y * 128 + threadIdx.x;
    if (r >= RR) return;
    const int n0 = blockIdx.z * 256;
    const __nv_bfloat16* __restrict__ bh_ = g_kph + (size_t)bh * NN * RP;
    const __nv_bfloat16* __restrict__ bl_ = g_kpl + (size_t)bh * NN * RP;
    float s = 0.f;
    #pragma unroll 4
    for (int n = n0; n < n0 + 256; n++) {
        size_t o = (size_t)n * RP + r;
        s += __bfloat162float(bh_[o]) + __bfloat162float(bl_[o]);
    }
    atomicAdd(&g_ksum[bh * RP + r], s);
}

// ---------------- d_inv = 1 / (qp . k_sum) -----------------------------------
__global__ void dinv_kernel()
{
    const int gw = (blockIdx.x * blockDim.x + threadIdx.x) >> 5;
    const int lane = threadIdx.x & 31;
    const int bh = gw >> 12;
    const int n = gw & 4095;
    const __nv_bfloat16* __restrict__ qh_ = g_qph + ((size_t)bh * NN + n) * RP;
    const __nv_bfloat16* __restrict__ ql_ = g_qpl + ((size_t)bh * NN + n) * RP;
    const float* __restrict__ ks = g_ksum + bh * RP;
    float s = 0.f;
    for (int r = lane; r < RR; r += 32)
        s += (__bfloat162float(qh_[r]) + __bfloat162float(ql_[r])) * ks[r];
    #pragma unroll
    for (int o = 16; o; o >>= 1) s += __shfl_xor_sync(0xffffffffu, s, o);
    if (lane == 0) g_dinv[(size_t)bh * NN + n] = 1.0f / s;
}

// ---------------- kv = kp^T @ v per head; writes kvT[d][r] h/l ---------------
__global__ __launch_bounds__(256) void kv_kernel()
{
    const int bh = blockIdx.x;
    const int b = bh >> 4, h = bh & 15;
    const int r0 = blockIdx.y * 64;

    __shared__ float kps[64][65];
    __shared__ float vs[64][64];
    const int tid = threadIdx.x;
    const int rlo = tid >> 3;
    const int c0 = (tid & 7) * 8;

    float acc0[8] = {}, acc1[8] = {};
    const __nv_bfloat16* __restrict__ kph_ = g_kph + (size_t)bh * NN * RP;
    const __nv_bfloat16* __restrict__ kpl_ = g_kpl + (size_t)bh * NN * RP;
    const float* __restrict__ vb = g_v + (size_t)b * NN * CC + h * 64;

    for (int n0 = 0; n0 < NN; n0 += 64) {
        #pragma unroll
        for (int t = 0; t < 16; t++) {
            int e = tid + t * 256;
            int nn = e >> 6, rl = e & 63;
            int rr = r0 + rl;
            float val = 0.f;
            if (rr < RP) {
                size_t o = (size_t)(n0 + nn) * RP + rr;
                val = __bfloat162float(kph_[o]) + __bfloat162float(kpl_[o]);
            }
            kps[nn][rl] = val;
        }
        #pragma unroll
        for (int t = 0; t < 16; t++) {
            int e = tid + t * 256;
            int nn = e >> 6, c = e & 63;
            vs[nn][c] = vb[(size_t)(n0 + nn) * CC + c];
        }
        __syncthreads();
        #pragma unroll 8
        for (int nn = 0; nn < 64; nn++) {
            float a0 = kps[nn][rlo];
            float a1 = kps[nn][rlo + 32];
            float4 v0 = *(const float4*)&vs[nn][c0];
            float4 v1 = *(const float4*)&vs[nn][c0 + 4];
            acc0[0] += a0 * v0.x; acc0[1] += a0 * v0.y;
            acc0[2] += a0 * v0.z; acc0[3] += a0 * v0.w;
            acc0[4] += a0 * v1.x; acc0[5] += a0 * v1.y;
            acc0[6] += a0 * v1.z; acc0[7] += a0 * v1.w;
            acc1[0] += a1 * v0.x; acc1[1] += a1 * v0.y;
            acc1[2] += a1 * v0.z; acc1[3] += a1 * v0.w;
            acc1[4] += a1 * v1.x; acc1[5] += a1 * v1.y;
            acc1[6] += a1 * v1.z; acc1[7] += a1 * v1.w;
        }
        __syncthreads();
    }

    int rr0 = r0 + rlo, rr1 = rr0 + 32;
    if (rr0 < RR) {
        #pragma unroll
        for (int j = 0; j < 8; j++) {
            __nv_bfloat16 hh, ll;
            split2(acc0[j], hh, ll);
            size_t o = ((size_t)bh * 64 + c0 + j) * RP + rr0;
            g_kvTh[o] = hh; g_kvTl[o] = ll;
        }
    }
    if (rr1 < RR) {
        #pragma unroll
        for (int j = 0; j < 8; j++) {
            __nv_bfloat16 hh, ll;
            split2(acc1[j], hh, ll);
            size_t o = ((size_t)bh * 64 + c0 + j) * RP + rr1;
            g_kvTh[o] = hh; g_kvTl[o] = ll;
        }
    }
}

// ---------------- qkv HMMA: om = (qp @ kvT^T) * d_inv, h/l out ---------------
__global__ __launch_bounds__(256) void qkv_hmma()
{
    extern __shared__ char smem[];
    const int tid = threadIdx.x, wid = tid >> 5, lane = tid & 31;
    const int n0 = blockIdx.x * 128;
    const int bh = blockIdx.y;
    const int b = bh >> 4, h = bh & 15;

    const __nv_bfloat16* __restrict__ Ahg = g_qph + ((size_t)bh * NN + n0) * RP;
    const __nv_bfloat16* __restrict__ Alg = g_qpl + ((size_t)bh * NN + n0) * RP;
    const __nv_bfloat16* __restrict__ Bhg = g_kvTh + (size_t)bh * 64 * RP;
    const __nv_bfloat16* __restrict__ Blg = g_kvTl + (size_t)bh * 64 * RP;

    float acc[4][2][4] = {};

    auto load_stage = [&](int c, int st) {
        const int k0 = c * KC;
        char* dstb = smem + st * QKV_STAGE;
        #pragma unroll
        for (int i = 0; i < 6; i++) {
            int idx = tid + i * 256;
            uint32_t dst;
            const __nv_bfloat16* src;
            if (idx < 512) {
                int row = idx >> 2, cc = idx & 3;
                dst = smem_u32(dstb + row * 80 + cc * 16);
                src = Ahg + (size_t)row * RP + k0 + cc * 8;
            } else if (idx < 1024) {
                int j = idx - 512; int row = j >> 2, cc = j & 3;
                dst = smem_u32(dstb + 128 * 80 + row * 80 + cc * 16);
                src = Alg + (size_t)row * RP + k0 + cc * 8;
            } else if (idx < 1280) {
                int j = idx - 1024; int row = j >> 2, cc = j & 3;
                dst = smem_u32(dstb + 2 * 128 * 80 + row * 80 + cc * 16);
                src = Bhg + (size_t)row * RP + k0 + cc * 8;
            } else {
                int j = idx - 1280; int row = j >> 2, cc = j & 3;
                dst = smem_u32(dstb + 2 * 128 * 80 + 64 * 80 + row * 80 + cc * 16);
                src = Blg + (size_t)row * RP + k0 + cc * 8;
            }
            cpa16(dst, src);
        }
        asm volatile("cp.async.commit_group;" ::: "memory");
    };

    const int NCH2 = RP / KC;  // 9
    load_stage(0, 0);

    for (int c = 0; c < NCH2; c++) {
        if (c + 1 < NCH2) {
            load_stage(c + 1, (c + 1) & 1);
            asm volatile("cp.async.wait_group 1;" ::: "memory");
        } else {
            asm volatile("cp.async.wait_group 0;" ::: "memory");
        }
        __syncthreads();

        const int st = c & 1;
        const uint32_t aH = smem_u32(smem + st * QKV_STAGE);
        const uint32_t aL = aH + 128 * 80;
        const uint32_t bH = aH + 2 * 128 * 80;
        const uint32_t bL = bH + 64 * 80;
        const int wr = wid >> 2, wc = wid & 3;

        #pragma unroll
        for (int kt = 0; kt < 2; kt++) {
            uint32_t ah[4][4], al[4][4], bh1[4], bl1[4];
            const int arow = wr * 64 + (lane & 15);
            const uint32_t ak = (uint32_t)(kt * 16 + (lane >> 4) * 8) * 2;
            #pragma unroll
            for (int mt = 0; mt < 4; mt++) {
                ldsm4(ah[mt], aH + (uint32_t)(arow + mt * 16) * 80 + ak);
                ldsm4(al[mt], aL + (uint32_t)(arow + mt * 16) * 80 + ak);
            }
            const int g = lane >> 3;
            const int brow = wc * 16 + (lane & 7) + (g >> 1) * 8;
            const uint32_t bk = (uint32_t)(kt * 16 + (g & 1) * 8) * 2;
            ldsm4(bh1, bH + (uint32_t)brow * 80 + bk);
            ldsm4(bl1, bL + (uint32_t)brow * 80 + bk);
            #pragma unroll
            for (int mt = 0; mt < 4; mt++)
                #pragma unroll
                for (int nt = 0; nt < 2; nt++) {
                    mma16816(acc[mt][nt], ah[mt], &bh1[nt * 2]);
                    mma16816(acc[mt][nt], ah[mt], &bl1[nt * 2]);
                    mma16816(acc[mt][nt], al[mt], &bh1[nt * 2]);
                }
        }
        __syncthreads();
    }

    const int wr = wid >> 2, wc = wid & 3;
    const int qr = lane >> 2, qc = lane & 3;
    #pragma unroll
    for (int mt = 0; mt < 4; mt++)
        #pragma unroll
        for (int nt = 0; nt < 2; nt++) {
            int d = wc * 16 + nt * 8 + qc * 2;
            #pragma unroll
            for (int hf = 0; hf < 2; hf++) {
                int nrow = n0 + wr * 64 + mt * 16 + qr + hf * 8;
                float di = g_dinv[(size_t)bh * NN + nrow];
                float v0 = acc[mt][nt][hf * 2 + 0] * di;
                float v1 = acc[mt][nt][hf * 2 + 1] * di;
                __nv_bfloat16 h0, l0, h1, l1;
                split2(v0, h0, l0);
                split2(v1, h1, l1);
                size_t o = ((size_t)(b * NN + nrow)) * GK + h * 64 + d;
                *(__nv_bfloat162*)&g_omh[o] = __nv_bfloat162{h0, h1};
                *(__nv_bfloat162*)&g_oml[o] = __nv_bfloat162{l0, l1};
            }
        }
}

// ---------------- launch -----------------------------------------------------
extern "C" void kernel_launch(void* const* d_in, const int* in_sizes, int n_in,
                              void* d_out, int out_size)
{
    const float* x    = (const float*)d_in[0];
    const float* Wq   = (const float*)d_in[1];
    const float* Wk   = (const float*)d_in[2];
    const float* Wv   = (const float*)d_in[3];
    const float* Wo   = (const float*)d_in[4];
    const float* bo   = (const float*)d_in[5];
    const float* proj = (const float*)d_in[6];

    float *ksum;
    __nv_bfloat16 *xh, *xl, *omh, *oml, *wth, *wtl, *kvth, *kvtl;
    cudaGetSymbolAddress((void**)&ksum, g_ksum);
    cudaGetSymbolAddress((void**)&xh,   g_xh);
    cudaGetSymbolAddress((void**)&xl,   g_xl);
    cudaGetSymbolAddress((void**)&omh,  g_omh);
    cudaGetSymbolAddress((void**)&oml,  g_oml);
    cudaGetSymbolAddress((void**)&wth,  g_wth);
    cudaGetSymbolAddress((void**)&wtl,  g_wtl);
    cudaGetSymbolAddress((void**)&kvth, g_kvTh);
    cudaGetSymbolAddress((void**)&kvtl, g_kvTl);

    cudaFuncSetAttribute(gemm_hmma,
                         cudaFuncAttributeMaxDynamicSharedMemorySize, SMEM_DYN);
    cudaFuncSetAttribute(featmap_hmma,
                         cudaFuncAttributeMaxDynamicSharedMemorySize, FM_SMEM);
    cudaFuncSetAttribute(qkv_hmma,
                         cudaFuncAttributeMaxDynamicSharedMemorySize, QKV_SMEM);

    const int n4 = GM * GK / 4;

    split_kernel<<<(n4 + 255) / 256, 256>>>(x, xh, xl, n4);
    wsplit_t<<<dim3(32, 32), dim3(32, 8)>>>(Wq, wth + 0 * (size_t)GN * GK, wtl + 0 * (size_t)GN * GK);
    wsplit_t<<<dim3(32, 32), dim3(32, 8)>>>(Wk, wth + 1 * (size_t)GN * GK, wtl + 1 * (size_t)GN * GK);
    wsplit_t<<<dim3(32, 32), dim3(32, 8)>>>(Wv, wth + 2 * (size_t)GN * GK, wtl + 2 * (size_t)GN * GK);
    wsplit_t<<<dim3(32, 32), dim3(32, 8)>>>(Wo, wth + 3 * (size_t)GN * GK, wtl + 3 * (size_t)GN * GK);
    psplit<<<80, 256>>>(proj);

    // merged Q/K/V GEMM over N = 3072
    gemm_hmma<<<dim3(24, GM / 128), 256, SMEM_DYN>>>(xh, xl, wth, wtl,
                                                     nullptr, nullptr, 0);

    featmap_hmma<<<dim3(32, 128), 256, FM_SMEM>>>();

    cudaMemsetAsync(ksum, 0, BHN * RP * sizeof(float));
    ksum_kernel<<<dim3(BHN, 3, NN / 256), 128>>>();

    dinv_kernel<<<(BHN * NN) / 8, 256>>>();

    cudaMemsetAsync(kvth, 0, BHN * 64 * RP * sizeof(__nv_bfloat16));
    cudaMemsetAsync(kvtl, 0, BHN * 64 * RP * sizeof(__nv_bfloat16));
    kv_kernel<<<dim3(BHN, 5), 256>>>();

    qkv_hmma<<<dim3(32, BHN), 256, QKV_SMEM>>>();

    gemm_hmma<<<dim3(8, GM / 128), 256, SMEM_DYN>>>(omh, oml,
        wth + 3 * (size_t)GN * GK, wtl + 3 * (size_t)GN * GK,
        bo, (float*)d_out, 1);
}

// round 9
// speedup vs baseline: 1.0944x; 1.0944x over previous
#include <cuda_runtime.h>
#include <cuda_bf16.h>
#include <cstdint>

#define BB 4
#define NN 4096
#define CC 1024
#define HH 16
#define DH 64
#define RR 266
#define RP 288
#define EPSF 1e-3f
#define BHN (BB*HH)   // 64
#define GM (BB*NN)    // 16384
#define GK 1024
#define GN 1024
#define KC 32
#define NCH (GK/KC)        // 32 chunks
#define MAT_BYTES (128*80) // 128 rows x 80B
#define STAGE_BYTES (4*MAT_BYTES)  // 40960
#define SMEM_DYN (2*STAGE_BYTES)   // 81920
// featmap smem
#define FM_SMEM (2*128*144 + 2*64*144)   // 55296
// qkv smem
#define QKV_STAGE (2*128*80 + 2*64*80)   // 30720
#define QKV_SMEM (2*QKV_STAGE)           // 61440

// ---------------- scratch (device globals; no allocation allowed) ----------
__device__ float g_v [GM*GK];
__device__ float g_ksum[BHN*RP];
__device__ float g_dinv[BHN*NN];
__device__ __nv_bfloat16 g_xh[(size_t)GM*GK];
__device__ __nv_bfloat16 g_xl[(size_t)GM*GK];
__device__ __nv_bfloat16 g_qh[(size_t)GM*GK];
__device__ __nv_bfloat16 g_ql[(size_t)GM*GK];
__device__ __nv_bfloat16 g_kh[(size_t)GM*GK];
__device__ __nv_bfloat16 g_kl[(size_t)GM*GK];
__device__ __nv_bfloat16 g_omh[(size_t)GM*GK];
__device__ __nv_bfloat16 g_oml[(size_t)GM*GK];
__device__ __nv_bfloat16 g_wth[(size_t)4*GN*GK];
__device__ __nv_bfloat16 g_wtl[(size_t)4*GN*GK];
__device__ __nv_bfloat16 g_projh[320*64];
__device__ __nv_bfloat16 g_projl[320*64];
__device__ __nv_bfloat16 g_qph[(size_t)BHN*NN*RP];
__device__ __nv_bfloat16 g_qpl[(size_t)BHN*NN*RP];
__device__ __nv_bfloat16 g_kph[(size_t)BHN*NN*RP];
__device__ __nv_bfloat16 g_kpl[(size_t)BHN*NN*RP];
__device__ __nv_bfloat16 g_kvTh[BHN*64*RP];
__device__ __nv_bfloat16 g_kvTl[BHN*64*RP];

// ---------------- helpers ----------------------------------------------------
__device__ __forceinline__ uint32_t smem_u32(const void* p) {
    uint32_t a;
    asm("{ .reg .u64 t; cvta.to.shared.u64 t, %1; cvt.u32.u64 %0, t; }"
        : "=r"(a) : "l"(p));
    return a;
}
__device__ __forceinline__ void cpa16(uint32_t dst, const void* src) {
    asm volatile("cp.async.cg.shared.global [%0], [%1], 16;" :: "r"(dst), "l"(src));
}
__device__ __forceinline__ void ldsm4(uint32_t* r, uint32_t addr) {
    asm volatile("ldmatrix.sync.aligned.m8n8.x4.shared.b16 {%0,%1,%2,%3}, [%4];"
        : "=r"(r[0]), "=r"(r[1]), "=r"(r[2]), "=r"(r[3]) : "r"(addr));
}
__device__ __forceinline__ void mma16816(float* d, const uint32_t* a, const uint32_t* b) {
    asm volatile(
        "mma.sync.aligned.m16n8k16.row.col.f32.bf16.bf16.f32 "
        "{%0,%1,%2,%3}, {%4,%5,%6,%7}, {%8,%9}, {%0,%1,%2,%3};"
        : "+f"(d[0]), "+f"(d[1]), "+f"(d[2]), "+f"(d[3])
        : "r"(a[0]), "r"(a[1]), "r"(a[2]), "r"(a[3]), "r"(b[0]), "r"(b[1]));
}
__device__ __forceinline__ void split2(float v, __nv_bfloat16& h, __nv_bfloat16& l) {
    h = __float2bfloat16(v);
    l = __float2bfloat16(v - __bfloat162float(h));
}

// ---------------- HMMA split-bf16 GEMM, 2-stage, 2 CTAs/SM -------------------
// mode 0: merged QKV (grid x = 24): n<1024 -> g_qh/ql, <2048 -> g_kh/kl, else g_v fp32
// mode 1: final (grid x = 8): fp32 Cf + bias
__global__ __launch_bounds__(256, 2) void gemm_hmma(
    const __nv_bfloat16* __restrict__ Ah, const __nv_bfloat16* __restrict__ Al,
    const __nv_bfloat16* __restrict__ Bh, const __nv_bfloat16* __restrict__ Bl,
    const float* __restrict__ bias, float* __restrict__ Cf, int mode)
{
    extern __shared__ char smem[];
    const int tid = threadIdx.x;
    const int wid = tid >> 5, lane = tid & 31;
    const int m0 = blockIdx.y * 128, n0 = blockIdx.x * 128;
    const int wr = wid >> 2, wc = wid & 3;

    const __nv_bfloat16* gsrc0 = Ah + (size_t)m0 * GK;
    const __nv_bfloat16* gsrc1 = Al + (size_t)m0 * GK;
    const __nv_bfloat16* gsrc2 = Bh + (size_t)n0 * GK;
    const __nv_bfloat16* gsrc3 = Bl + (size_t)n0 * GK;

    float acc[4][4][4] = {};

    auto load_stage = [&](int c, int st) {
        const int k0 = c * KC;
        char* dstb = smem + st * STAGE_BYTES;
        #pragma unroll
        for (int i = 0; i < 8; i++) {
            int idx = tid + i * 256;
            int mat = idx >> 9;
            int row = (idx >> 2) & 127;
            int c16 = idx & 3;
            uint32_t dst = smem_u32(dstb + mat * MAT_BYTES + row * 80 + c16 * 16);
            const __nv_bfloat16* g =
                (mat == 0) ? gsrc0 : (mat == 1) ? gsrc1 : (mat == 2) ? gsrc2 : gsrc3;
            cpa16(dst, g + (size_t)row * GK + k0 + c16 * 8);
        }
        asm volatile("cp.async.commit_group;" ::: "memory");
    };

    load_stage(0, 0);

    for (int c = 0; c < NCH; c++) {
        if (c + 1 < NCH) {
            load_stage(c + 1, (c + 1) & 1);
            asm volatile("cp.async.wait_group 1;" ::: "memory");
        } else {
            asm volatile("cp.async.wait_group 0;" ::: "memory");
        }
        __syncthreads();

        const int st = c & 1;
        const uint32_t aH = smem_u32(smem + st * STAGE_BYTES);
        const uint32_t aL = aH + MAT_BYTES;
        const uint32_t bH = aH + 2 * MAT_BYTES;
        const uint32_t bL = aH + 3 * MAT_BYTES;

        #pragma unroll
        for (int kt = 0; kt < 2; kt++) {
            // B fragments first (16 regs, live across mt loop)
            uint32_t bh[2][4], bl[2][4];
            const int g = lane >> 3;
            const int brow = wc * 32 + (lane & 7) + (g >> 1) * 8;
            const uint32_t bkoff = (uint32_t)(kt * 16 + (g & 1) * 8) * 2;
            #pragma unroll
            for (int nt2 = 0; nt2 < 2; nt2++) {
                ldsm4(bh[nt2], bH + (uint32_t)(brow + nt2 * 16) * 80 + bkoff);
                ldsm4(bl[nt2], bL + (uint32_t)(brow + nt2 * 16) * 80 + bkoff);
            }
            const int arow = wr * 64 + (lane & 15);
            const uint32_t akoff = (uint32_t)(kt * 16 + (lane >> 4) * 8) * 2;
            #pragma unroll
            for (int mt = 0; mt < 4; mt++) {
                uint32_t ah[4], al[4];   // 8 regs, per-mt
                ldsm4(ah, aH + (uint32_t)(arow + mt * 16) * 80 + akoff);
                ldsm4(al, aL + (uint32_t)(arow + mt * 16) * 80 + akoff);
                #pragma unroll
                for (int nt = 0; nt < 4; nt++) {
                    const uint32_t* bhp = &bh[nt >> 1][(nt & 1) * 2];
                    const uint32_t* blp = &bl[nt >> 1][(nt & 1) * 2];
                    mma16816(acc[mt][nt], ah, bhp);
                    mma16816(acc[mt][nt], ah, blp);
                    mma16816(acc[mt][nt], al, bhp);
                }
            }
        }
        __syncthreads();
    }

    // ---- epilogue
    float* outf = nullptr;
    __nv_bfloat16 *och = nullptr, *ocl = nullptr;
    int cbase = n0;
    bool use_bias = false;
    if (mode == 1) { outf = Cf; use_bias = true; }
    else if (n0 < 1024) { och = g_qh; ocl = g_ql; }
    else if (n0 < 2048) { och = g_kh; ocl = g_kl; cbase = n0 - 1024; }
    else { outf = g_v; cbase = n0 - 2048; }

    const int qr = lane >> 2, qc = lane & 3;
    #pragma unroll
    for (int mt = 0; mt < 4; mt++) {
        #pragma unroll
        for (int nt = 0; nt < 4; nt++) {
            int row = m0 + wr * 64 + mt * 16 + qr;
            int col = cbase + wc * 32 + nt * 8 + qc * 2;
            if (outf) {
                float bx = 0.f, by = 0.f;
                if (use_bias) { bx = bias[col]; by = bias[col + 1]; }
                float2 v0 = {acc[mt][nt][0] + bx, acc[mt][nt][1] + by};
                float2 v1 = {acc[mt][nt][2] + bx, acc[mt][nt][3] + by};
                *(float2*)&outf[(size_t)row * GN + col] = v0;
                *(float2*)&outf[(size_t)(row + 8) * GN + col] = v1;
            } else {
                #pragma unroll
                for (int hf = 0; hf < 2; hf++) {
                    int r = row + hf * 8;
                    __nv_bfloat16 h0, l0, h1, l1;
                    split2(acc[mt][nt][hf * 2 + 0], h0, l0);
                    split2(acc[mt][nt][hf * 2 + 1], h1, l1);
                    *(__nv_bfloat162*)&och[(size_t)r * GN + col] = __nv_bfloat162{h0, h1};
                    *(__nv_bfloat162*)&ocl[(size_t)r * GN + col] = __nv_bfloat162{l0, l1};
                }
            }
        }
    }
}

// ---------------- fp32 -> bf16 hi/lo split (x only) --------------------------
__global__ __launch_bounds__(256) void split_kernel(
    const float* __restrict__ in, __nv_bfloat16* __restrict__ hi,
    __nv_bfloat16* __restrict__ lo, int n4)
{
    int i = blockIdx.x * blockDim.x + threadIdx.x;
    if (i >= n4) return;
    float4 v = ((const float4*)in)[i];
    float vv[4] = {v.x, v.y, v.z, v.w};
    __nv_bfloat16 h[4], l[4];
    #pragma unroll
    for (int j = 0; j < 4; j++) split2(vv[j], h[j], l[j]);
    ((__nv_bfloat162*)hi)[2*i+0] = __nv_bfloat162{h[0], h[1]};
    ((__nv_bfloat162*)hi)[2*i+1] = __nv_bfloat162{h[2], h[3]};
    ((__nv_bfloat162*)lo)[2*i+0] = __nv_bfloat162{l[0], l[1]};
    ((__nv_bfloat162*)lo)[2*i+1] = __nv_bfloat162{l[2], l[3]};
}

// ---------------- transpose + split weights: W[K][N] -> Wt hi/lo [N][K] -----
__global__ void wsplit_t(const float* __restrict__ W,
                         __nv_bfloat16* __restrict__ th,
                         __nv_bfloat16* __restrict__ tl)
{
    __shared__ float t[32][33];
    const int k0 = blockIdx.y * 32, n0 = blockIdx.x * 32;
    for (int i = threadIdx.y; i < 32; i += 8)
        t[i][threadIdx.x] = W[(size_t)(k0 + i) * GN + n0 + threadIdx.x];
    __syncthreads();
    for (int i = threadIdx.y; i < 32; i += 8) {
        float v = t[threadIdx.x][i];
        __nv_bfloat16 h, l;
        split2(v, h, l);
        size_t o = (size_t)(n0 + i) * GK + k0 + threadIdx.x;
        th[o] = h;
        tl[o] = l;
    }
}

// ---------------- proj split (padded to 320 rows, zero fill) -----------------
__global__ void psplit(const float* __restrict__ proj)
{
    int i = blockIdx.x * 256 + threadIdx.x;
    if (i >= 320 * 64) return;
    int r = i >> 6, d = i & 63;
    float v = (r < RR) ? proj[r * 64 + d] : 0.0f;
    __nv_bfloat16 h, l;
    split2(v, h, l);
    g_projh[i] = h;
    g_projl[i] = l;
}

// ---------------- featmap HMMA: qp/kp = relu(head @ proj^T)+eps, h/l out -----
// grid (5, 32, 128), 256 threads, dyn smem FM_SMEM
__global__ __launch_bounds__(256, 2) void featmap_hmma()
{
    extern __shared__ char smem[];
    const int tid = threadIdx.x, wid = tid >> 5, lane = tid & 31;
    const int r0 = blockIdx.x * 64;
    const int n0 = blockIdx.y * 128;
    const int z = blockIdx.z;
    const int which = z >> 6, bh = z & 63;
    const int b = bh >> 4, h = bh & 15;
    const __nv_bfloat16* __restrict__ Ahg = which ? g_kh : g_qh;
    const __nv_bfloat16* __restrict__ Alg = which ? g_kl : g_ql;
    __nv_bfloat16* __restrict__ dsth = which ? g_kph : g_qph;
    __nv_bfloat16* __restrict__ dstl = which ? g_kpl : g_qpl;
    const size_t abase = ((size_t)(b * NN + n0)) * GK + h * 64;

    const uint32_t sA_h = smem_u32(smem);
    const uint32_t sA_l = sA_h + 128 * 144;
    const uint32_t sB_h = sA_h + 2 * 128 * 144;
    const uint32_t sB_l = sB_h + 64 * 144;

    #pragma unroll
    for (int i = 0; i < 12; i++) {
        int idx = tid + i * 256;
        if (idx < 1024) {
            int row = idx >> 3, c = idx & 7;
            cpa16(sA_h + row * 144 + c * 16, Ahg + abase + (size_t)row * GK + c * 8);
        } else if (idx < 2048) {
            int j = idx - 1024; int row = j >> 3, c = j & 7;
            cpa16(sA_l + row * 144 + c * 16, Alg + abase + (size_t)row * GK + c * 8);
        } else if (idx < 2560) {
            int j = idx - 2048; int row = j >> 3, c = j & 7;
            cpa16(sB_h + row * 144 + c * 16, g_projh + (r0 + row) * 64 + c * 8);
        } else {
            int j = idx - 2560; int row = j >> 3, c = j & 7;
            cpa16(sB_l + row * 144 + c * 16, g_projl + (r0 + row) * 64 + c * 8);
        }
    }
    asm volatile("cp.async.commit_group;" ::: "memory");
    asm volatile("cp.async.wait_group 0;" ::: "memory");
    __syncthreads();

    const int wr = wid >> 2, wc = wid & 3;
    float acc[4][2][4] = {};

    #pragma unroll
    for (int kt = 0; kt < 4; kt++) {
        uint32_t bh1[4], bl1[4];
        const int g = lane >> 3;
        const int brow = wc * 16 + (lane & 7) + (g >> 1) * 8;
        const uint32_t bk = (uint32_t)(kt * 16 + (g & 1) * 8) * 2;
        ldsm4(bh1, sB_h + (uint32_t)brow * 144 + bk);
        ldsm4(bl1, sB_l + (uint32_t)brow * 144 + bk);
        const int arow = wr * 64 + (lane & 15);
        const uint32_t ak = (uint32_t)(kt * 16 + (lane >> 4) * 8) * 2;
        #pragma unroll
        for (int mt = 0; mt < 4; mt++) {
            uint32_t ah[4], al[4];
            ldsm4(ah, sA_h + (uint32_t)(arow + mt * 16) * 144 + ak);
            ldsm4(al, sA_l + (uint32_t)(arow + mt * 16) * 144 + ak);
            #pragma unroll
            for (int nt = 0; nt < 2; nt++) {
                mma16816(acc[mt][nt], ah, &bh1[nt * 2]);
                mma16816(acc[mt][nt], ah, &bl1[nt * 2]);
                mma16816(acc[mt][nt], al, &bh1[nt * 2]);
            }
        }
    }

    const int qr = lane >> 2, qc = lane & 3;
    #pragma unroll
    for (int mt = 0; mt < 4; mt++)
        #pragma unroll
        for (int nt = 0; nt < 2; nt++) {
            int r = r0 + wc * 16 + nt * 8 + qc * 2;
            if (r >= RP) continue;
            bool valid = (r < RR);
            #pragma unroll
            for (int hf = 0; hf < 2; hf++) {
                int nrow = n0 + wr * 64 + mt * 16 + qr + hf * 8;
                float v0 = acc[mt][nt][hf * 2 + 0];
                float v1 = acc[mt][nt][hf * 2 + 1];
                v0 = valid ? (fmaxf(v0, 0.0f) + EPSF) : 0.0f;
                v1 = valid ? (fmaxf(v1, 0.0f) + EPSF) : 0.0f;
                __nv_bfloat16 h0, l0, h1, l1;
                split2(v0, h0, l0);
                split2(v1, h1, l1);
                size_t o = ((size_t)bh * NN + nrow) * RP + r;
                *(__nv_bfloat162*)&dsth[o] = __nv_bfloat162{h0, h1};
                *(__nv_bfloat162*)&dstl[o] = __nv_bfloat162{l0, l1};
            }
        }
}

// ---------------- k_sum = sum_n kp -------------------------------------------
__global__ void ksum_kernel()
{
    const int bh = blockIdx.x;
    const int r = blockIdx.y * 128 + threadIdx.x;
    if (r >= RR) return;
    const int n0 = blockIdx.z * 256;
    const __nv_bfloat16* __restrict__ bh_ = g_kph + (size_t)bh * NN * RP;
    const __nv_bfloat16* __restrict__ bl_ = g_kpl + (size_t)bh * NN * RP;
    float s = 0.f;
    #pragma unroll 4
    for (int n = n0; n < n0 + 256; n++) {
        size_t o = (size_t)n * RP + r;
        s += __bfloat162float(bh_[o]) + __bfloat162float(bl_[o]);
    }
    atomicAdd(&g_ksum[bh * RP + r], s);
}

// ---------------- d_inv = 1 / (qp . k_sum) -----------------------------------
__global__ void dinv_kernel()
{
    const int gw = (blockIdx.x * blockDim.x + threadIdx.x) >> 5;
    const int lane = threadIdx.x & 31;
    const int bh = gw >> 12;
    const int n = gw & 4095;
    const __nv_bfloat16* __restrict__ qh_ = g_qph + ((size_t)bh * NN + n) * RP;
    const __nv_bfloat16* __restrict__ ql_ = g_qpl + ((size_t)bh * NN + n) * RP;
    const float* __restrict__ ks = g_ksum + bh * RP;
    float s = 0.f;
    for (int r = lane; r < RR; r += 32)
        s += (__bfloat162float(qh_[r]) + __bfloat162float(ql_[r])) * ks[r];
    #pragma unroll
    for (int o = 16; o; o >>= 1) s += __shfl_xor_sync(0xffffffffu, s, o);
    if (lane == 0) g_dinv[(size_t)bh * NN + n] = 1.0f / s;
}

// ---------------- kv = kp^T @ v per head; writes kvT[d][r] h/l ---------------
__global__ __launch_bounds__(256) void kv_kernel()
{
    const int bh = blockIdx.x;
    const int b = bh >> 4, h = bh & 15;
    const int r0 = blockIdx.y * 64;

    __shared__ float kps[64][65];
    __shared__ float vs[64][64];
    const int tid = threadIdx.x;
    const int rlo = tid >> 3;
    const int c0 = (tid & 7) * 8;

    float acc0[8] = {}, acc1[8] = {};
    const __nv_bfloat16* __restrict__ kph_ = g_kph + (size_t)bh * NN * RP;
    const __nv_bfloat16* __restrict__ kpl_ = g_kpl + (size_t)bh * NN * RP;
    const float* __restrict__ vb = g_v + (size_t)b * NN * CC + h * 64;

    for (int n0 = 0; n0 < NN; n0 += 64) {
        #pragma unroll
        for (int t = 0; t < 16; t++) {
            int e = tid + t * 256;
            int nn = e >> 6, rl = e & 63;
            int rr = r0 + rl;
            float val = 0.f;
            if (rr < RP) {
                size_t o = (size_t)(n0 + nn) * RP + rr;
                val = __bfloat162float(kph_[o]) + __bfloat162float(kpl_[o]);
            }
            kps[nn][rl] = val;
        }
        #pragma unroll
        for (int t = 0; t < 16; t++) {
            int e = tid + t * 256;
            int nn = e >> 6, c = e & 63;
            vs[nn][c] = vb[(size_t)(n0 + nn) * CC + c];
        }
        __syncthreads();
        #pragma unroll 8
        for (int nn = 0; nn < 64; nn++) {
            float a0 = kps[nn][rlo];
            float a1 = kps[nn][rlo + 32];
            float4 v0 = *(const float4*)&vs[nn][c0];
            float4 v1 = *(const float4*)&vs[nn][c0 + 4];
            acc0[0] += a0 * v0.x; acc0[1] += a0 * v0.y;
            acc0[2] += a0 * v0.z; acc0[3] += a0 * v0.w;
            acc0[4] += a0 * v1.x; acc0[5] += a0 * v1.y;
            acc0[6] += a0 * v1.z; acc0[7] += a0 * v1.w;
            acc1[0] += a1 * v0.x; acc1[1] += a1 * v0.y;
            acc1[2] += a1 * v0.z; acc1[3] += a1 * v0.w;
            acc1[4] += a1 * v1.x; acc1[5] += a1 * v1.y;
            acc1[6] += a1 * v1.z; acc1[7] += a1 * v1.w;
        }
        __syncthreads();
    }

    int rr0 = r0 + rlo, rr1 = rr0 + 32;
    if (rr0 < RR) {
        #pragma unroll
        for (int j = 0; j < 8; j++) {
            __nv_bfloat16 hh, ll;
            split2(acc0[j], hh, ll);
            size_t o = ((size_t)bh * 64 + c0 + j) * RP + rr0;
            g_kvTh[o] = hh; g_kvTl[o] = ll;
        }
    }
    if (rr1 < RR) {
        #pragma unroll
        for (int j = 0; j < 8; j++) {
            __nv_bfloat16 hh, ll;
            split2(acc1[j], hh, ll);
            size_t o = ((size_t)bh * 64 + c0 + j) * RP + rr1;
            g_kvTh[o] = hh; g_kvTl[o] = ll;
        }
    }
}

// ---------------- qkv HMMA: om = (qp @ kvT^T) * d_inv, h/l out ---------------
__global__ __launch_bounds__(256, 2) void qkv_hmma()
{
    extern __shared__ char smem[];
    const int tid = threadIdx.x, wid = tid >> 5, lane = tid & 31;
    const int n0 = blockIdx.x * 128;
    const int bh = blockIdx.y;
    const int b = bh >> 4, h = bh & 15;

    const __nv_bfloat16* __restrict__ Ahg = g_qph + ((size_t)bh * NN + n0) * RP;
    const __nv_bfloat16* __restrict__ Alg = g_qpl + ((size_t)bh * NN + n0) * RP;
    const __nv_bfloat16* __restrict__ Bhg = g_kvTh + (size_t)bh * 64 * RP;
    const __nv_bfloat16* __restrict__ Blg = g_kvTl + (size_t)bh * 64 * RP;

    float acc[4][2][4] = {};

    auto load_stage = [&](int c, int st) {
        const int k0 = c * KC;
        char* dstb = smem + st * QKV_STAGE;
        #pragma unroll
        for (int i = 0; i < 6; i++) {
            int idx = tid + i * 256;
            uint32_t dst;
            const __nv_bfloat16* src;
            if (idx < 512) {
                int row = idx >> 2, cc = idx & 3;
                dst = smem_u32(dstb + row * 80 + cc * 16);
                src = Ahg + (size_t)row * RP + k0 + cc * 8;
            } else if (idx < 1024) {
                int j = idx - 512; int row = j >> 2, cc = j & 3;
                dst = smem_u32(dstb + 128 * 80 + row * 80 + cc * 16);
                src = Alg + (size_t)row * RP + k0 + cc * 8;
            } else if (idx < 1280) {
                int j = idx - 1024; int row = j >> 2, cc = j & 3;
                dst = smem_u32(dstb + 2 * 128 * 80 + row * 80 + cc * 16);
                src = Bhg + (size_t)row * RP + k0 + cc * 8;
            } else {
                int j = idx - 1280; int row = j >> 2, cc = j & 3;
                dst = smem_u32(dstb + 2 * 128 * 80 + 64 * 80 + row * 80 + cc * 16);
                src = Blg + (size_t)row * RP + k0 + cc * 8;
            }
            cpa16(dst, src);
        }
        asm volatile("cp.async.commit_group;" ::: "memory");
    };

    const int NCH2 = RP / KC;  // 9
    load_stage(0, 0);

    for (int c = 0; c < NCH2; c++) {
        if (c + 1 < NCH2) {
            load_stage(c + 1, (c + 1) & 1);
            asm volatile("cp.async.wait_group 1;" ::: "memory");
        } else {
            asm volatile("cp.async.wait_group 0;" ::: "memory");
        }
        __syncthreads();

        const int st = c & 1;
        const uint32_t aH = smem_u32(smem + st * QKV_STAGE);
        const uint32_t aL = aH + 128 * 80;
        const uint32_t bH = aH + 2 * 128 * 80;
        const uint32_t bL = bH + 64 * 80;
        const int wr = wid >> 2, wc = wid & 3;

        #pragma unroll
        for (int kt = 0; kt < 2; kt++) {
            uint32_t bh1[4], bl1[4];
            const int g = lane >> 3;
            const int brow = wc * 16 + (lane & 7) + (g >> 1) * 8;
            const uint32_t bk = (uint32_t)(kt * 16 + (g & 1) * 8) * 2;
            ldsm4(bh1, bH + (uint32_t)brow * 80 + bk);
            ldsm4(bl1, bL + (uint32_t)brow * 80 + bk);
            const int arow = wr * 64 + (lane & 15);
            const uint32_t ak = (uint32_t)(kt * 16 + (lane >> 4) * 8) * 2;
            #pragma unroll
            for (int mt = 0; mt < 4; mt++) {
                uint32_t ah[4], al[4];
                ldsm4(ah, aH + (uint32_t)(arow + mt * 16) * 80 + ak);
                ldsm4(al, aL + (uint32_t)(arow + mt * 16) * 80 + ak);
                #pragma unroll
                for (int nt = 0; nt < 2; nt++) {
                    mma16816(acc[mt][nt], ah, &bh1[nt * 2]);
                    mma16816(acc[mt][nt], ah, &bl1[nt * 2]);
                    mma16816(acc[mt][nt], al, &bh1[nt * 2]);
                }
            }
        }
        __syncthreads();
    }

    const int wr = wid >> 2, wc = wid & 3;
    const int qr = lane >> 2, qc = lane & 3;
    #pragma unroll
    for (int mt = 0; mt < 4; mt++)
        #pragma unroll
        for (int nt = 0; nt < 2; nt++) {
            int d = wc * 16 + nt * 8 + qc * 2;
            #pragma unroll
            for (int hf = 0; hf < 2; hf++) {
                int nrow = n0 + wr * 64 + mt * 16 + qr + hf * 8;
                float di = g_dinv[(size_t)bh * NN + nrow];
                float v0 = acc[mt][nt][hf * 2 + 0] * di;
                float v1 = acc[mt][nt][hf * 2 + 1] * di;
                __nv_bfloat16 h0, l0, h1, l1;
                split2(v0, h0, l0);
                split2(v1, h1, l1);
                size_t o = ((size_t)(b * NN + nrow)) * GK + h * 64 + d;
                *(__nv_bfloat162*)&g_omh[o] = __nv_bfloat162{h0, h1};
                *(__nv_bfloat162*)&g_oml[o] = __nv_bfloat162{l0, l1};
            }
        }
}

// ---------------- launch -----------------------------------------------------
extern "C" void kernel_launch(void* const* d_in, const int* in_sizes, int n_in,
                              void* d_out, int out_size)
{
    const float* x    = (const float*)d_in[0];
    const float* Wq   = (const float*)d_in[1];
    const float* Wk   = (const float*)d_in[2];
    const float* Wv   = (const float*)d_in[3];
    const float* Wo   = (const float*)d_in[4];
    const float* bo   = (const float*)d_in[5];
    const float* proj = (const float*)d_in[6];

    float *ksum;
    __nv_bfloat16 *xh, *xl, *omh, *oml, *wth, *wtl, *kvth, *kvtl;
    cudaGetSymbolAddress((void**)&ksum, g_ksum);
    cudaGetSymbolAddress((void**)&xh,   g_xh);
    cudaGetSymbolAddress((void**)&xl,   g_xl);
    cudaGetSymbolAddress((void**)&omh,  g_omh);
    cudaGetSymbolAddress((void**)&oml,  g_oml);
    cudaGetSymbolAddress((void**)&wth,  g_wth);
    cudaGetSymbolAddress((void**)&wtl,  g_wtl);
    cudaGetSymbolAddress((void**)&kvth, g_kvTh);
    cudaGetSymbolAddress((void**)&kvtl, g_kvTl);

    cudaFuncSetAttribute(gemm_hmma,
                         cudaFuncAttributeMaxDynamicSharedMemorySize, SMEM_DYN);
    cudaFuncSetAttribute(featmap_hmma,
                         cudaFuncAttributeMaxDynamicSharedMemorySize, FM_SMEM);
    cudaFuncSetAttribute(qkv_hmma,
                         cudaFuncAttributeMaxDynamicSharedMemorySize, QKV_SMEM);

    const int n4 = GM * GK / 4;

    split_kernel<<<(n4 + 255) / 256, 256>>>(x, xh, xl, n4);
    wsplit_t<<<dim3(32, 32), dim3(32, 8)>>>(Wq, wth + 0 * (size_t)GN * GK, wtl + 0 * (size_t)GN * GK);
    wsplit_t<<<dim3(32, 32), dim3(32, 8)>>>(Wk, wth + 1 * (size_t)GN * GK, wtl + 1 * (size_t)GN * GK);
    wsplit_t<<<dim3(32, 32), dim3(32, 8)>>>(Wv, wth + 2 * (size_t)GN * GK, wtl + 2 * (size_t)GN * GK);
    wsplit_t<<<dim3(32, 32), dim3(32, 8)>>>(Wo, wth + 3 * (size_t)GN * GK, wtl + 3 * (size_t)GN * GK);
    psplit<<<80, 256>>>(proj);

    // merged Q/K/V GEMM over N = 3072
    gemm_hmma<<<dim3(24, GM / 128), 256, SMEM_DYN>>>(xh, xl, wth, wtl,
                                                     nullptr, nullptr, 0);

    featmap_hmma<<<dim3(5, 32, 128), 256, FM_SMEM>>>();

    cudaMemsetAsync(ksum, 0, BHN * RP * sizeof(float));
    ksum_kernel<<<dim3(BHN, 3, NN / 256), 128>>>();

    dinv_kernel<<<(BHN * NN) / 8, 256>>>();

    cudaMemsetAsync(kvth, 0, BHN * 64 * RP * sizeof(__nv_bfloat16));
    cudaMemsetAsync(kvtl, 0, BHN * 64 * RP * sizeof(__nv_bfloat16));
    kv_kernel<<<dim3(BHN, 5), 256>>>();

    qkv_hmma<<<dim3(32, BHN), 256, QKV_SMEM>>>();

    gemm_hmma<<<dim3(8, GM / 128), 256, SMEM_DYN>>>(omh, oml,
        wth + 3 * (size_t)GN * GK, wtl + 3 * (size_t)GN * GK,
        bo, (float*)d_out, 1);
}

// round 10
// speedup vs baseline: 1.2180x; 1.1129x over previous
#include <cuda_runtime.h>
#include <cuda_bf16.h>
#include <cstdint>

#define BB 4
#define NN 4096
#define CC 1024
#define HH 16
#define DH 64
#define RR 266
#define RP 288
#define EPSF 1e-3f
#define BHN (BB*HH)   // 64
#define GM (BB*NN)    // 16384
#define GK 1024
#define GN 1024
#define KC 32
#define NCH (GK/KC)        // 32 chunks
#define MAT_BYTES (128*80) // 128 rows x 80B
#define STAGE_BYTES (4*MAT_BYTES)  // 40960
#define SMEM_DYN (2*STAGE_BYTES)   // 81920
// featmap smem
#define FM_SMEM (2*128*144 + 2*64*144)   // 55296
// qkv smem
#define QKV_STAGE (2*128*80 + 2*64*80)   // 30720
#define QKV_SMEM (2*QKV_STAGE)           // 61440

// ---------------- scratch (device globals; no allocation allowed) ----------
__device__ float g_v [GM*GK];
__device__ float g_ksum[BHN*RP];
__device__ __nv_bfloat16 g_xh[(size_t)GM*GK];
__device__ __nv_bfloat16 g_xl[(size_t)GM*GK];
__device__ __nv_bfloat16 g_qh[(size_t)GM*GK];
__device__ __nv_bfloat16 g_ql[(size_t)GM*GK];
__device__ __nv_bfloat16 g_kh[(size_t)GM*GK];
__device__ __nv_bfloat16 g_kl[(size_t)GM*GK];
__device__ __nv_bfloat16 g_omh[(size_t)GM*GK];
__device__ __nv_bfloat16 g_oml[(size_t)GM*GK];
__device__ __nv_bfloat16 g_wth[(size_t)4*GN*GK];
__device__ __nv_bfloat16 g_wtl[(size_t)4*GN*GK];
__device__ __nv_bfloat16 g_projh[320*64];
__device__ __nv_bfloat16 g_projl[320*64];
__device__ __nv_bfloat16 g_qph[(size_t)BHN*NN*RP];
__device__ __nv_bfloat16 g_qpl[(size_t)BHN*NN*RP];
__device__ __nv_bfloat16 g_kph[(size_t)BHN*NN*RP];
__device__ __nv_bfloat16 g_kpl[(size_t)BHN*NN*RP];
__device__ __nv_bfloat16 g_kvTh[BHN*64*RP];
__device__ __nv_bfloat16 g_kvTl[BHN*64*RP];

// ---------------- helpers ----------------------------------------------------
__device__ __forceinline__ uint32_t smem_u32(const void* p) {
    uint32_t a;
    asm("{ .reg .u64 t; cvta.to.shared.u64 t, %1; cvt.u32.u64 %0, t; }"
        : "=r"(a) : "l"(p));
    return a;
}
__device__ __forceinline__ void cpa16(uint32_t dst, const void* src) {
    asm volatile("cp.async.cg.shared.global [%0], [%1], 16;" :: "r"(dst), "l"(src));
}
__device__ __forceinline__ void ldsm4(uint32_t* r, uint32_t addr) {
    asm volatile("ldmatrix.sync.aligned.m8n8.x4.shared.b16 {%0,%1,%2,%3}, [%4];"
        : "=r"(r[0]), "=r"(r[1]), "=r"(r[2]), "=r"(r[3]) : "r"(addr));
}
__device__ __forceinline__ void mma16816(float* d, const uint32_t* a, const uint32_t* b) {
    asm volatile(
        "mma.sync.aligned.m16n8k16.row.col.f32.bf16.bf16.f32 "
        "{%0,%1,%2,%3}, {%4,%5,%6,%7}, {%8,%9}, {%0,%1,%2,%3};"
        : "+f"(d[0]), "+f"(d[1]), "+f"(d[2]), "+f"(d[3])
        : "r"(a[0]), "r"(a[1]), "r"(a[2]), "r"(a[3]), "r"(b[0]), "r"(b[1]));
}
__device__ __forceinline__ void split2(float v, __nv_bfloat16& h, __nv_bfloat16& l) {
    h = __float2bfloat16(v);
    l = __float2bfloat16(v - __bfloat162float(h));
}

// ---------------- HMMA split-bf16 GEMM, 2-stage, 2 CTAs/SM -------------------
// mode 0: merged QKV (grid x = 24): n<1024 -> g_qh/ql, <2048 -> g_kh/kl, else g_v fp32
// mode 1: final (grid x = 8): fp32 Cf + bias
__global__ __launch_bounds__(256, 2) void gemm_hmma(
    const __nv_bfloat16* __restrict__ Ah, const __nv_bfloat16* __restrict__ Al,
    const __nv_bfloat16* __restrict__ Bh, const __nv_bfloat16* __restrict__ Bl,
    const float* __restrict__ bias, float* __restrict__ Cf, int mode)
{
    extern __shared__ char smem[];
    const int tid = threadIdx.x;
    const int wid = tid >> 5, lane = tid & 31;
    const int m0 = blockIdx.y * 128, n0 = blockIdx.x * 128;
    const int wr = wid >> 2, wc = wid & 3;

    const __nv_bfloat16* gsrc0 = Ah + (size_t)m0 * GK;
    const __nv_bfloat16* gsrc1 = Al + (size_t)m0 * GK;
    const __nv_bfloat16* gsrc2 = Bh + (size_t)n0 * GK;
    const __nv_bfloat16* gsrc3 = Bl + (size_t)n0 * GK;

    float acc[4][4][4] = {};

    auto load_stage = [&](int c, int st) {
        const int k0 = c * KC;
        char* dstb = smem + st * STAGE_BYTES;
        #pragma unroll
        for (int i = 0; i < 8; i++) {
            int idx = tid + i * 256;
            int mat = idx >> 9;
            int row = (idx >> 2) & 127;
            int c16 = idx & 3;
            uint32_t dst = smem_u32(dstb + mat * MAT_BYTES + row * 80 + c16 * 16);
            const __nv_bfloat16* g =
                (mat == 0) ? gsrc0 : (mat == 1) ? gsrc1 : (mat == 2) ? gsrc2 : gsrc3;
            cpa16(dst, g + (size_t)row * GK + k0 + c16 * 8);
        }
        asm volatile("cp.async.commit_group;" ::: "memory");
    };

    load_stage(0, 0);

    for (int c = 0; c < NCH; c++) {
        if (c + 1 < NCH) {
            load_stage(c + 1, (c + 1) & 1);
            asm volatile("cp.async.wait_group 1;" ::: "memory");
        } else {
            asm volatile("cp.async.wait_group 0;" ::: "memory");
        }
        __syncthreads();

        const int st = c & 1;
        const uint32_t aH = smem_u32(smem + st * STAGE_BYTES);
        const uint32_t aL = aH + MAT_BYTES;
        const uint32_t bH = aH + 2 * MAT_BYTES;
        const uint32_t bL = aH + 3 * MAT_BYTES;

        #pragma unroll
        for (int kt = 0; kt < 2; kt++) {
            uint32_t bh[2][4], bl[2][4];
            const int g = lane >> 3;
            const int brow = wc * 32 + (lane & 7) + (g >> 1) * 8;
            const uint32_t bkoff = (uint32_t)(kt * 16 + (g & 1) * 8) * 2;
            #pragma unroll
            for (int nt2 = 0; nt2 < 2; nt2++) {
                ldsm4(bh[nt2], bH + (uint32_t)(brow + nt2 * 16) * 80 + bkoff);
                ldsm4(bl[nt2], bL + (uint32_t)(brow + nt2 * 16) * 80 + bkoff);
            }
            const int arow = wr * 64 + (lane & 15);
            const uint32_t akoff = (uint32_t)(kt * 16 + (lane >> 4) * 8) * 2;
            #pragma unroll
            for (int mt = 0; mt < 4; mt++) {
                uint32_t ah[4], al[4];
                ldsm4(ah, aH + (uint32_t)(arow + mt * 16) * 80 + akoff);
                ldsm4(al, aL + (uint32_t)(arow + mt * 16) * 80 + akoff);
                #pragma unroll
                for (int nt = 0; nt < 4; nt++) {
                    const uint32_t* bhp = &bh[nt >> 1][(nt & 1) * 2];
                    const uint32_t* blp = &bl[nt >> 1][(nt & 1) * 2];
                    mma16816(acc[mt][nt], ah, bhp);
                    mma16816(acc[mt][nt], ah, blp);
                    mma16816(acc[mt][nt], al, bhp);
                }
            }
        }
        __syncthreads();
    }

    // ---- epilogue
    float* outf = nullptr;
    __nv_bfloat16 *och = nullptr, *ocl = nullptr;
    int cbase = n0;
    bool use_bias = false;
    if (mode == 1) { outf = Cf; use_bias = true; }
    else if (n0 < 1024) { och = g_qh; ocl = g_ql; }
    else if (n0 < 2048) { och = g_kh; ocl = g_kl; cbase = n0 - 1024; }
    else { outf = g_v; cbase = n0 - 2048; }

    const int qr = lane >> 2, qc = lane & 3;
    #pragma unroll
    for (int mt = 0; mt < 4; mt++) {
        #pragma unroll
        for (int nt = 0; nt < 4; nt++) {
            int row = m0 + wr * 64 + mt * 16 + qr;
            int col = cbase + wc * 32 + nt * 8 + qc * 2;
            if (outf) {
                float bx = 0.f, by = 0.f;
                if (use_bias) { bx = bias[col]; by = bias[col + 1]; }
                float2 v0 = {acc[mt][nt][0] + bx, acc[mt][nt][1] + by};
                float2 v1 = {acc[mt][nt][2] + bx, acc[mt][nt][3] + by};
                *(float2*)&outf[(size_t)row * GN + col] = v0;
                *(float2*)&outf[(size_t)(row + 8) * GN + col] = v1;
            } else {
                #pragma unroll
                for (int hf = 0; hf < 2; hf++) {
                    int r = row + hf * 8;
                    __nv_bfloat16 h0, l0, h1, l1;
                    split2(acc[mt][nt][hf * 2 + 0], h0, l0);
                    split2(acc[mt][nt][hf * 2 + 1], h1, l1);
                    *(__nv_bfloat162*)&och[(size_t)r * GN + col] = __nv_bfloat162{h0, h1};
                    *(__nv_bfloat162*)&ocl[(size_t)r * GN + col] = __nv_bfloat162{l0, l1};
                }
            }
        }
    }
}

// ---------------- fp32 -> bf16 hi/lo split (x only) --------------------------
__global__ __launch_bounds__(256) void split_kernel(
    const float* __restrict__ in, __nv_bfloat16* __restrict__ hi,
    __nv_bfloat16* __restrict__ lo, int n4)
{
    int i = blockIdx.x * blockDim.x + threadIdx.x;
    if (i >= n4) return;
    float4 v = ((const float4*)in)[i];
    float vv[4] = {v.x, v.y, v.z, v.w};
    __nv_bfloat16 h[4], l[4];
    #pragma unroll
    for (int j = 0; j < 4; j++) split2(vv[j], h[j], l[j]);
    ((__nv_bfloat162*)hi)[2*i+0] = __nv_bfloat162{h[0], h[1]};
    ((__nv_bfloat162*)hi)[2*i+1] = __nv_bfloat162{h[2], h[3]};
    ((__nv_bfloat162*)lo)[2*i+0] = __nv_bfloat162{l[0], l[1]};
    ((__nv_bfloat162*)lo)[2*i+1] = __nv_bfloat162{l[2], l[3]};
}

// ---------------- transpose + split weights: W[K][N] -> Wt hi/lo [N][K] -----
__global__ void wsplit_t(const float* __restrict__ W,
                         __nv_bfloat16* __restrict__ th,
                         __nv_bfloat16* __restrict__ tl)
{
    __shared__ float t[32][33];
    const int k0 = blockIdx.y * 32, n0 = blockIdx.x * 32;
    for (int i = threadIdx.y; i < 32; i += 8)
        t[i][threadIdx.x] = W[(size_t)(k0 + i) * GN + n0 + threadIdx.x];
    __syncthreads();
    for (int i = threadIdx.y; i < 32; i += 8) {
        float v = t[threadIdx.x][i];
        __nv_bfloat16 h, l;
        split2(v, h, l);
        size_t o = (size_t)(n0 + i) * GK + k0 + threadIdx.x;
        th[o] = h;
        tl[o] = l;
    }
}

// ---------------- proj split (padded to 320 rows, zero fill) -----------------
__global__ void psplit(const float* __restrict__ proj)
{
    int i = blockIdx.x * 256 + threadIdx.x;
    if (i >= 320 * 64) return;
    int r = i >> 6, d = i & 63;
    float v = (r < RR) ? proj[r * 64 + d] : 0.0f;
    __nv_bfloat16 h, l;
    split2(v, h, l);
    g_projh[i] = h;
    g_projl[i] = l;
}

// ---------------- featmap HMMA: qp/kp = relu(head @ proj^T)+eps, h/l out -----
// grid (5, 32, 128), 256 threads, dyn smem FM_SMEM
__global__ __launch_bounds__(256, 2) void featmap_hmma()
{
    extern __shared__ char smem[];
    const int tid = threadIdx.x, wid = tid >> 5, lane = tid & 31;
    const int r0 = blockIdx.x * 64;
    const int n0 = blockIdx.y * 128;
    const int z = blockIdx.z;
    const int which = z >> 6, bh = z & 63;
    const int b = bh >> 4, h = bh & 15;
    const __nv_bfloat16* __restrict__ Ahg = which ? g_kh : g_qh;
    const __nv_bfloat16* __restrict__ Alg = which ? g_kl : g_ql;
    __nv_bfloat16* __restrict__ dsth = which ? g_kph : g_qph;
    __nv_bfloat16* __restrict__ dstl = which ? g_kpl : g_qpl;
    const size_t abase = ((size_t)(b * NN + n0)) * GK + h * 64;

    const uint32_t sA_h = smem_u32(smem);
    const uint32_t sA_l = sA_h + 128 * 144;
    const uint32_t sB_h = sA_h + 2 * 128 * 144;
    const uint32_t sB_l = sB_h + 64 * 144;

    #pragma unroll
    for (int i = 0; i < 12; i++) {
        int idx = tid + i * 256;
        if (idx < 1024) {
            int row = idx >> 3, c = idx & 7;
            cpa16(sA_h + row * 144 + c * 16, Ahg + abase + (size_t)row * GK + c * 8);
        } else if (idx < 2048) {
            int j = idx - 1024; int row = j >> 3, c = j & 7;
            cpa16(sA_l + row * 144 + c * 16, Alg + abase + (size_t)row * GK + c * 8);
        } else if (idx < 2560) {
            int j = idx - 2048; int row = j >> 3, c = j & 7;
            cpa16(sB_h + row * 144 + c * 16, g_projh + (r0 + row) * 64 + c * 8);
        } else {
            int j = idx - 2560; int row = j >> 3, c = j & 7;
            cpa16(sB_l + row * 144 + c * 16, g_projl + (r0 + row) * 64 + c * 8);
        }
    }
    asm volatile("cp.async.commit_group;" ::: "memory");
    asm volatile("cp.async.wait_group 0;" ::: "memory");
    __syncthreads();

    const int wr = wid >> 2, wc = wid & 3;
    float acc[4][2][4] = {};

    #pragma unroll
    for (int kt = 0; kt < 4; kt++) {
        uint32_t bh1[4], bl1[4];
        const int g = lane >> 3;
        const int brow = wc * 16 + (lane & 7) + (g >> 1) * 8;
        const uint32_t bk = (uint32_t)(kt * 16 + (g & 1) * 8) * 2;
        ldsm4(bh1, sB_h + (uint32_t)brow * 144 + bk);
        ldsm4(bl1, sB_l + (uint32_t)brow * 144 + bk);
        const int arow = wr * 64 + (lane & 15);
        const uint32_t ak = (uint32_t)(kt * 16 + (lane >> 4) * 8) * 2;
        #pragma unroll
        for (int mt = 0; mt < 4; mt++) {
            uint32_t ah[4], al[4];
            ldsm4(ah, sA_h + (uint32_t)(arow + mt * 16) * 144 + ak);
            ldsm4(al, sA_l + (uint32_t)(arow + mt * 16) * 144 + ak);
            #pragma unroll
            for (int nt = 0; nt < 2; nt++) {
                mma16816(acc[mt][nt], ah, &bh1[nt * 2]);
                mma16816(acc[mt][nt], ah, &bl1[nt * 2]);
                mma16816(acc[mt][nt], al, &bh1[nt * 2]);
            }
        }
    }

    const int qr = lane >> 2, qc = lane & 3;
    #pragma unroll
    for (int mt = 0; mt < 4; mt++)
        #pragma unroll
        for (int nt = 0; nt < 2; nt++) {
            int r = r0 + wc * 16 + nt * 8 + qc * 2;
            if (r >= RP) continue;
            bool valid = (r < RR);
            #pragma unroll
            for (int hf = 0; hf < 2; hf++) {
                int nrow = n0 + wr * 64 + mt * 16 + qr + hf * 8;
                float v0 = acc[mt][nt][hf * 2 + 0];
                float v1 = acc[mt][nt][hf * 2 + 1];
                v0 = valid ? (fmaxf(v0, 0.0f) + EPSF) : 0.0f;
                v1 = valid ? (fmaxf(v1, 0.0f) + EPSF) : 0.0f;
                __nv_bfloat16 h0, l0, h1, l1;
                split2(v0, h0, l0);
                split2(v1, h1, l1);
                size_t o = ((size_t)bh * NN + nrow) * RP + r;
                *(__nv_bfloat162*)&dsth[o] = __nv_bfloat162{h0, h1};
                *(__nv_bfloat162*)&dstl[o] = __nv_bfloat162{l0, l1};
            }
        }
}

// ---------------- kv = kp^T @ v per head; writes kvT[d][r] h/l + ksum --------
// grid (BHN, 5), 256 threads. ksum fused: each (bh, r) owned by exactly 1 CTA.
__global__ __launch_bounds__(256) void kv_kernel()
{
    const int bh = blockIdx.x;
    const int b = bh >> 4, h = bh & 15;
    const int r0 = blockIdx.y * 64;

    __shared__ float kps[64][65];
    __shared__ float vs[64][64];
    __shared__ float sred[4][64];
    const int tid = threadIdx.x;
    const int rlo = tid >> 3;
    const int c0 = (tid & 7) * 8;

    float acc0[8] = {}, acc1[8] = {};
    float sk = 0.f;   // partial ksum for rl = tid & 63
    const __nv_bfloat16* __restrict__ kph_ = g_kph + (size_t)bh * NN * RP;
    const __nv_bfloat16* __restrict__ kpl_ = g_kpl + (size_t)bh * NN * RP;
    const float* __restrict__ vb = g_v + (size_t)b * NN * CC + h * 64;

    for (int n0 = 0; n0 < NN; n0 += 64) {
        #pragma unroll
        for (int t = 0; t < 16; t++) {
            int e = tid + t * 256;
            int nn = e >> 6, rl = e & 63;   // rl == tid & 63 (256 % 64 == 0)
            int rr = r0 + rl;
            float val = 0.f;
            if (rr < RP) {
                size_t o = (size_t)(n0 + nn) * RP + rr;
                val = __bfloat162float(kph_[o]) + __bfloat162float(kpl_[o]);
            }
            kps[nn][rl] = val;
            sk += val;
        }
        #pragma unroll
        for (int t = 0; t < 16; t++) {
            int e = tid + t * 256;
            int nn = e >> 6, c = e & 63;
            vs[nn][c] = vb[(size_t)(n0 + nn) * CC + c];
        }
        __syncthreads();
        #pragma unroll 8
        for (int nn = 0; nn < 64; nn++) {
            float a0 = kps[nn][rlo];
            float a1 = kps[nn][rlo + 32];
            float4 v0 = *(const float4*)&vs[nn][c0];
            float4 v1 = *(const float4*)&vs[nn][c0 + 4];
            acc0[0] += a0 * v0.x; acc0[1] += a0 * v0.y;
            acc0[2] += a0 * v0.z; acc0[3] += a0 * v0.w;
            acc0[4] += a0 * v1.x; acc0[5] += a0 * v1.y;
            acc0[6] += a0 * v1.z; acc0[7] += a0 * v1.w;
            acc1[0] += a1 * v0.x; acc1[1] += a1 * v0.y;
            acc1[2] += a1 * v0.z; acc1[3] += a1 * v0.w;
            acc1[4] += a1 * v1.x; acc1[5] += a1 * v1.y;
            acc1[6] += a1 * v1.z; acc1[7] += a1 * v1.w;
        }
        __syncthreads();
    }

    // ksum reduce: 4 groups (tid>>6) share each rl
    sred[tid >> 6][tid & 63] = sk;
    __syncthreads();
    if (tid < 64) {
        int r = r0 + tid;
        if (r < RP)
            g_ksum[bh * RP + r] = sred[0][tid] + sred[1][tid] + sred[2][tid] + sred[3][tid];
    }

    int rr0 = r0 + rlo, rr1 = rr0 + 32;
    if (rr0 < RR) {
        #pragma unroll
        for (int j = 0; j < 8; j++) {
            __nv_bfloat16 hh, ll;
            split2(acc0[j], hh, ll);
            size_t o = ((size_t)bh * 64 + c0 + j) * RP + rr0;
            g_kvTh[o] = hh; g_kvTl[o] = ll;
        }
    }
    if (rr1 < RR) {
        #pragma unroll
        for (int j = 0; j < 8; j++) {
            __nv_bfloat16 hh, ll;
            split2(acc1[j], hh, ll);
            size_t o = ((size_t)bh * 64 + c0 + j) * RP + rr1;
            g_kvTh[o] = hh; g_kvTl[o] = ll;
        }
    }
}

// ---------------- qkv HMMA: om = (qp @ kvT^T) * d_inv, dinv fused ------------
__global__ __launch_bounds__(256, 2) void qkv_hmma()
{
    extern __shared__ char smem[];
    __shared__ float ksumS[RP];
    __shared__ float dpart[2][128];
    __shared__ float dinvS[128];
    const int tid = threadIdx.x, wid = tid >> 5, lane = tid & 31;
    const int n0 = blockIdx.x * 128;
    const int bh = blockIdx.y;
    const int b = bh >> 4, h = bh & 15;

    const __nv_bfloat16* __restrict__ Ahg = g_qph + ((size_t)bh * NN + n0) * RP;
    const __nv_bfloat16* __restrict__ Alg = g_qpl + ((size_t)bh * NN + n0) * RP;
    const __nv_bfloat16* __restrict__ Bhg = g_kvTh + (size_t)bh * 64 * RP;
    const __nv_bfloat16* __restrict__ Blg = g_kvTl + (size_t)bh * 64 * RP;

    for (int i = tid; i < RP; i += 256) ksumS[i] = g_ksum[bh * RP + i];

    float acc[4][2][4] = {};
    float myd = 0.f;    // partial qp.ksum dot for row tid&127, k-half tid>>7
    const int drow = tid & 127, dhalf = tid >> 7;

    auto load_stage = [&](int c, int st) {
        const int k0 = c * KC;
        char* dstb = smem + st * QKV_STAGE;
        #pragma unroll
        for (int i = 0; i < 6; i++) {
            int idx = tid + i * 256;
            uint32_t dst;
            const __nv_bfloat16* src;
            if (idx < 512) {
                int row = idx >> 2, cc = idx & 3;
                dst = smem_u32(dstb + row * 80 + cc * 16);
                src = Ahg + (size_t)row * RP + k0 + cc * 8;
            } else if (idx < 1024) {
                int j = idx - 512; int row = j >> 2, cc = j & 3;
                dst = smem_u32(dstb + 128 * 80 + row * 80 + cc * 16);
                src = Alg + (size_t)row * RP + k0 + cc * 8;
            } else if (idx < 1280) {
                int j = idx - 1024; int row = j >> 2, cc = j & 3;
                dst = smem_u32(dstb + 2 * 128 * 80 + row * 80 + cc * 16);
                src = Bhg + (size_t)row * RP + k0 + cc * 8;
            } else {
                int j = idx - 1280; int row = j >> 2, cc = j & 3;
                dst = smem_u32(dstb + 2 * 128 * 80 + 64 * 80 + row * 80 + cc * 16);
                src = Blg + (size_t)row * RP + k0 + cc * 8;
            }
            cpa16(dst, src);
        }
        asm volatile("cp.async.commit_group;" ::: "memory");
    };

    const int NCH2 = RP / KC;  // 9
    load_stage(0, 0);

    for (int c = 0; c < NCH2; c++) {
        if (c + 1 < NCH2) {
            load_stage(c + 1, (c + 1) & 1);
            asm volatile("cp.async.wait_group 1;" ::: "memory");
        } else {
            asm volatile("cp.async.wait_group 0;" ::: "memory");
        }
        __syncthreads();

        const int st = c & 1;
        const uint32_t aH = smem_u32(smem + st * QKV_STAGE);
        const uint32_t aL = aH + 128 * 80;
        const uint32_t bH = aH + 2 * 128 * 80;
        const uint32_t bL = bH + 64 * 80;
        const int wr = wid >> 2, wc = wid & 3;

        // fused dinv partial dot from staged A tiles
        {
            const __nv_bfloat16* ph = (const __nv_bfloat16*)(smem + st * QKV_STAGE
                                        + drow * 80 + dhalf * 32);
            const __nv_bfloat16* pl = (const __nv_bfloat16*)(smem + st * QKV_STAGE
                                        + 128 * 80 + drow * 80 + dhalf * 32);
            const float* ksp = ksumS + c * KC + dhalf * 16;
            #pragma unroll
            for (int kk = 0; kk < 16; kk++) {
                float v = __bfloat162float(ph[kk]) + __bfloat162float(pl[kk]);
                myd += v * ksp[kk];
            }
        }

        #pragma unroll
        for (int kt = 0; kt < 2; kt++) {
            uint32_t bh1[4], bl1[4];
            const int g = lane >> 3;
            const int brow = wc * 16 + (lane & 7) + (g >> 1) * 8;
            const uint32_t bk = (uint32_t)(kt * 16 + (g & 1) * 8) * 2;
            ldsm4(bh1, bH + (uint32_t)brow * 80 + bk);
            ldsm4(bl1, bL + (uint32_t)brow * 80 + bk);
            const int arow = wr * 64 + (lane & 15);
            const uint32_t ak = (uint32_t)(kt * 16 + (lane >> 4) * 8) * 2;
            #pragma unroll
            for (int mt = 0; mt < 4; mt++) {
                uint32_t ah[4], al[4];
                ldsm4(ah, aH + (uint32_t)(arow + mt * 16) * 80 + ak);
                ldsm4(al, aL + (uint32_t)(arow + mt * 16) * 80 + ak);
                #pragma unroll
                for (int nt = 0; nt < 2; nt++) {
                    mma16816(acc[mt][nt], ah, &bh1[nt * 2]);
                    mma16816(acc[mt][nt], ah, &bl1[nt * 2]);
                    mma16816(acc[mt][nt], al, &bh1[nt * 2]);
                }
            }
        }
        __syncthreads();
    }

    dpart[dhalf][drow] = myd;
    __syncthreads();
    if (tid < 128) dinvS[tid] = 1.0f / (dpart[0][tid] + dpart[1][tid]);
    __syncthreads();

    const int wr = wid >> 2, wc = wid & 3;
    const int qr = lane >> 2, qc = lane & 3;
    #pragma unroll
    for (int mt = 0; mt < 4; mt++)
        #pragma unroll
        for (int nt = 0; nt < 2; nt++) {
            int d = wc * 16 + nt * 8 + qc * 2;
            #pragma unroll
            for (int hf = 0; hf < 2; hf++) {
                int lrow = wr * 64 + mt * 16 + qr + hf * 8;
                int nrow = n0 + lrow;
                float di = dinvS[lrow];
                float v0 = acc[mt][nt][hf * 2 + 0] * di;
                float v1 = acc[mt][nt][hf * 2 + 1] * di;
                __nv_bfloat16 h0, l0, h1, l1;
                split2(v0, h0, l0);
                split2(v1, h1, l1);
                size_t o = ((size_t)(b * NN + nrow)) * GK + h * 64 + d;
                *(__nv_bfloat162*)&g_omh[o] = __nv_bfloat162{h0, h1};
                *(__nv_bfloat162*)&g_oml[o] = __nv_bfloat162{l0, l1};
            }
        }
}

// ---------------- launch -----------------------------------------------------
extern "C" void kernel_launch(void* const* d_in, const int* in_sizes, int n_in,
                              void* d_out, int out_size)
{
    const float* x    = (const float*)d_in[0];
    const float* Wq   = (const float*)d_in[1];
    const float* Wk   = (const float*)d_in[2];
    const float* Wv   = (const float*)d_in[3];
    const float* Wo   = (const float*)d_in[4];
    const float* bo   = (const float*)d_in[5];
    const float* proj = (const float*)d_in[6];

    __nv_bfloat16 *xh, *xl, *omh, *oml, *wth, *wtl, *kvth, *kvtl;
    cudaGetSymbolAddress((void**)&xh,   g_xh);
    cudaGetSymbolAddress((void**)&xl,   g_xl);
    cudaGetSymbolAddress((void**)&omh,  g_omh);
    cudaGetSymbolAddress((void**)&oml,  g_oml);
    cudaGetSymbolAddress((void**)&wth,  g_wth);
    cudaGetSymbolAddress((void**)&wtl,  g_wtl);
    cudaGetSymbolAddress((void**)&kvth, g_kvTh);
    cudaGetSymbolAddress((void**)&kvtl, g_kvTl);

    cudaFuncSetAttribute(gemm_hmma,
                         cudaFuncAttributeMaxDynamicSharedMemorySize, SMEM_DYN);
    cudaFuncSetAttribute(featmap_hmma,
                         cudaFuncAttributeMaxDynamicSharedMemorySize, FM_SMEM);
    cudaFuncSetAttribute(qkv_hmma,
                         cudaFuncAttributeMaxDynamicSharedMemorySize, QKV_SMEM);

    const int n4 = GM * GK / 4;

    split_kernel<<<(n4 + 255) / 256, 256>>>(x, xh, xl, n4);
    wsplit_t<<<dim3(32, 32), dim3(32, 8)>>>(Wq, wth + 0 * (size_t)GN * GK, wtl + 0 * (size_t)GN * GK);
    wsplit_t<<<dim3(32, 32), dim3(32, 8)>>>(Wk, wth + 1 * (size_t)GN * GK, wtl + 1 * (size_t)GN * GK);
    wsplit_t<<<dim3(32, 32), dim3(32, 8)>>>(Wv, wth + 2 * (size_t)GN * GK, wtl + 2 * (size_t)GN * GK);
    wsplit_t<<<dim3(32, 32), dim3(32, 8)>>>(Wo, wth + 3 * (size_t)GN * GK, wtl + 3 * (size_t)GN * GK);
    psplit<<<80, 256>>>(proj);

    // merged Q/K/V GEMM over N = 3072
    gemm_hmma<<<dim3(24, GM / 128), 256, SMEM_DYN>>>(xh, xl, wth, wtl,
                                                     nullptr, nullptr, 0);

    featmap_hmma<<<dim3(5, 32, 128), 256, FM_SMEM>>>();

    cudaMemsetAsync(kvth, 0, BHN * 64 * RP * sizeof(__nv_bfloat16));
    cudaMemsetAsync(kvtl, 0, BHN * 64 * RP * sizeof(__nv_bfloat16));
    kv_kernel<<<dim3(BHN, 5), 256>>>();   // also produces g_ksum

    qkv_hmma<<<dim3(32, BHN), 256, QKV_SMEM>>>();   // dinv fused

    gemm_hmma<<<dim3(8, GM / 128), 256, SMEM_DYN>>>(omh, oml,
        wth + 3 * (size_t)GN * GK, wtl + 3 * (size_t)GN * GK,
        bo, (float*)d_out, 1);
}

// round 11
// speedup vs baseline: 1.8568x; 1.5245x over previous
#include <cuda_runtime.h>
#include <cuda_bf16.h>
#include <cstdint>

#define BB 4
#define NN 4096
#define CC 1024
#define HH 16
#define DH 64
#define RR 266
#define RP 288
#define RT 320
#define EPSF 1e-3f
#define BHN (BB*HH)   // 64
#define GM (BB*NN)    // 16384
#define GK 1024
#define GN 1024
#define KC 32
#define NCH (GK/KC)        // 32 chunks
#define MAT_BYTES (128*80)
#define STAGE_BYTES (4*MAT_BYTES)  // 40960
#define SMEM_DYN (2*STAGE_BYTES)   // 81920
// featmap smem: A h/l (2*128*144) + 2 proj slots (2*(64*144*2))
#define FM_SMEM (2*128*144 + 2*2*64*144)   // 73728
// qkv smem
#define QKV_STAGE (2*128*80 + 2*64*80)   // 30720
#define QKV_SMEM (2*QKV_STAGE)           // 61440
// kv smem: A h/l (2*160*80) + B h/l (2*32*144)
#define KV_STAGE (2*160*80 + 2*32*144)   // 34816
#define KV_SMEM (2*KV_STAGE)             // 69632

// ---------------- scratch (device globals; no allocation allowed) ----------
__device__ float g_ksum[BHN*RP];
__device__ float g_kvacc[(size_t)2*BHN*RT*64];
__device__ __nv_bfloat16 g_xh[(size_t)GM*GK];
__device__ __nv_bfloat16 g_xl[(size_t)GM*GK];
__device__ __nv_bfloat16 g_qh[(size_t)GM*GK];
__device__ __nv_bfloat16 g_ql[(size_t)GM*GK];
__device__ __nv_bfloat16 g_kh[(size_t)GM*GK];
__device__ __nv_bfloat16 g_kl[(size_t)GM*GK];
__device__ __nv_bfloat16 g_vh[(size_t)GM*GK];
__device__ __nv_bfloat16 g_vl[(size_t)GM*GK];
__device__ __nv_bfloat16 g_omh[(size_t)GM*GK];
__device__ __nv_bfloat16 g_oml[(size_t)GM*GK];
__device__ __nv_bfloat16 g_wth[(size_t)4*GN*GK];
__device__ __nv_bfloat16 g_wtl[(size_t)4*GN*GK];
__device__ __nv_bfloat16 g_projh[RT*64];
__device__ __nv_bfloat16 g_projl[RT*64];
__device__ __nv_bfloat16 g_qph[(size_t)BHN*NN*RP];
__device__ __nv_bfloat16 g_qpl[(size_t)BHN*NN*RP];
__device__ __nv_bfloat16 g_kpTh[(size_t)BHN*RT*NN];
__device__ __nv_bfloat16 g_kpTl[(size_t)BHN*RT*NN];
__device__ __nv_bfloat16 g_kvTh[BHN*64*RP];
__device__ __nv_bfloat16 g_kvTl[BHN*64*RP];

// ---------------- helpers ----------------------------------------------------
__device__ __forceinline__ uint32_t smem_u32(const void* p) {
    uint32_t a;
    asm("{ .reg .u64 t; cvta.to.shared.u64 t, %1; cvt.u32.u64 %0, t; }"
        : "=r"(a) : "l"(p));
    return a;
}
__device__ __forceinline__ void cpa16(uint32_t dst, const void* src) {
    asm volatile("cp.async.cg.shared.global [%0], [%1], 16;" :: "r"(dst), "l"(src));
}
__device__ __forceinline__ void ldsm4(uint32_t* r, uint32_t addr) {
    asm volatile("ldmatrix.sync.aligned.m8n8.x4.shared.b16 {%0,%1,%2,%3}, [%4];"
        : "=r"(r[0]), "=r"(r[1]), "=r"(r[2]), "=r"(r[3]) : "r"(addr));
}
__device__ __forceinline__ void ldsm4t(uint32_t* r, uint32_t addr) {
    asm volatile("ldmatrix.sync.aligned.m8n8.x4.trans.shared.b16 {%0,%1,%2,%3}, [%4];"
        : "=r"(r[0]), "=r"(r[1]), "=r"(r[2]), "=r"(r[3]) : "r"(addr));
}
__device__ __forceinline__ void mma16816(float* d, const uint32_t* a, const uint32_t* b) {
    asm volatile(
        "mma.sync.aligned.m16n8k16.row.col.f32.bf16.bf16.f32 "
        "{%0,%1,%2,%3}, {%4,%5,%6,%7}, {%8,%9}, {%0,%1,%2,%3};"
        : "+f"(d[0]), "+f"(d[1]), "+f"(d[2]), "+f"(d[3])
        : "r"(a[0]), "r"(a[1]), "r"(a[2]), "r"(a[3]), "r"(b[0]), "r"(b[1]));
}
__device__ __forceinline__ void split2(float v, __nv_bfloat16& h, __nv_bfloat16& l) {
    h = __float2bfloat16(v);
    l = __float2bfloat16(v - __bfloat162float(h));
}

// ---------------- HMMA split-bf16 GEMM, 2-stage, 2 CTAs/SM -------------------
// mode 0: merged QKV (grid x = 24): q, k, v all bf16 h/l out
// mode 1: final (grid x = 8): fp32 Cf + bias
__global__ __launch_bounds__(256, 2) void gemm_hmma(
    const __nv_bfloat16* __restrict__ Ah, const __nv_bfloat16* __restrict__ Al,
    const __nv_bfloat16* __restrict__ Bh, const __nv_bfloat16* __restrict__ Bl,
    const float* __restrict__ bias, float* __restrict__ Cf, int mode)
{
    extern __shared__ char smem[];
    const int tid = threadIdx.x;
    const int wid = tid >> 5, lane = tid & 31;
    const int m0 = blockIdx.y * 128, n0 = blockIdx.x * 128;
    const int wr = wid >> 2, wc = wid & 3;

    const __nv_bfloat16* gsrc0 = Ah + (size_t)m0 * GK;
    const __nv_bfloat16* gsrc1 = Al + (size_t)m0 * GK;
    const __nv_bfloat16* gsrc2 = Bh + (size_t)n0 * GK;
    const __nv_bfloat16* gsrc3 = Bl + (size_t)n0 * GK;

    float acc[4][4][4] = {};

    auto load_stage = [&](int c, int st) {
        const int k0 = c * KC;
        char* dstb = smem + st * STAGE_BYTES;
        #pragma unroll
        for (int i = 0; i < 8; i++) {
            int idx = tid + i * 256;
            int mat = idx >> 9;
            int row = (idx >> 2) & 127;
            int c16 = idx & 3;
            uint32_t dst = smem_u32(dstb + mat * MAT_BYTES + row * 80 + c16 * 16);
            const __nv_bfloat16* g =
                (mat == 0) ? gsrc0 : (mat == 1) ? gsrc1 : (mat == 2) ? gsrc2 : gsrc3;
            cpa16(dst, g + (size_t)row * GK + k0 + c16 * 8);
        }
        asm volatile("cp.async.commit_group;" ::: "memory");
    };

    load_stage(0, 0);

    for (int c = 0; c < NCH; c++) {
        if (c + 1 < NCH) {
            load_stage(c + 1, (c + 1) & 1);
            asm volatile("cp.async.wait_group 1;" ::: "memory");
        } else {
            asm volatile("cp.async.wait_group 0;" ::: "memory");
        }
        __syncthreads();

        const int st = c & 1;
        const uint32_t aH = smem_u32(smem + st * STAGE_BYTES);
        const uint32_t aL = aH + MAT_BYTES;
        const uint32_t bH = aH + 2 * MAT_BYTES;
        const uint32_t bL = aH + 3 * MAT_BYTES;

        #pragma unroll
        for (int kt = 0; kt < 2; kt++) {
            uint32_t bh[2][4], bl[2][4];
            const int g = lane >> 3;
            const int brow = wc * 32 + (lane & 7) + (g >> 1) * 8;
            const uint32_t bkoff = (uint32_t)(kt * 16 + (g & 1) * 8) * 2;
            #pragma unroll
            for (int nt2 = 0; nt2 < 2; nt2++) {
                ldsm4(bh[nt2], bH + (uint32_t)(brow + nt2 * 16) * 80 + bkoff);
                ldsm4(bl[nt2], bL + (uint32_t)(brow + nt2 * 16) * 80 + bkoff);
            }
            const int arow = wr * 64 + (lane & 15);
            const uint32_t akoff = (uint32_t)(kt * 16 + (lane >> 4) * 8) * 2;
            #pragma unroll
            for (int mt = 0; mt < 4; mt++) {
                uint32_t ah[4], al[4];
                ldsm4(ah, aH + (uint32_t)(arow + mt * 16) * 80 + akoff);
                ldsm4(al, aL + (uint32_t)(arow + mt * 16) * 80 + akoff);
                #pragma unroll
                for (int nt = 0; nt < 4; nt++) {
                    const uint32_t* bhp = &bh[nt >> 1][(nt & 1) * 2];
                    const uint32_t* blp = &bl[nt >> 1][(nt & 1) * 2];
                    mma16816(acc[mt][nt], ah, bhp);
                    mma16816(acc[mt][nt], ah, blp);
                    mma16816(acc[mt][nt], al, bhp);
                }
            }
        }
        __syncthreads();
    }

    // ---- epilogue
    const int qr = lane >> 2, qc = lane & 3;
    if (mode == 1) {
        #pragma unroll
        for (int mt = 0; mt < 4; mt++)
            #pragma unroll
            for (int nt = 0; nt < 4; nt++) {
                int row = m0 + wr * 64 + mt * 16 + qr;
                int col = n0 + wc * 32 + nt * 8 + qc * 2;
                float bx = bias[col], by = bias[col + 1];
                float2 v0 = {acc[mt][nt][0] + bx, acc[mt][nt][1] + by};
                float2 v1 = {acc[mt][nt][2] + bx, acc[mt][nt][3] + by};
                *(float2*)&Cf[(size_t)row * GN + col] = v0;
                *(float2*)&Cf[(size_t)(row + 8) * GN + col] = v1;
            }
    } else {
        __nv_bfloat16 *och, *ocl;
        int cbase;
        if (n0 < 1024)      { och = g_qh; ocl = g_ql; cbase = n0; }
        else if (n0 < 2048) { och = g_kh; ocl = g_kl; cbase = n0 - 1024; }
        else                { och = g_vh; ocl = g_vl; cbase = n0 - 2048; }
        #pragma unroll
        for (int mt = 0; mt < 4; mt++)
            #pragma unroll
            for (int nt = 0; nt < 4; nt++) {
                int row = m0 + wr * 64 + mt * 16 + qr;
                int col = cbase + wc * 32 + nt * 8 + qc * 2;
                #pragma unroll
                for (int hf = 0; hf < 2; hf++) {
                    int r = row + hf * 8;
                    __nv_bfloat16 h0, l0, h1, l1;
                    split2(acc[mt][nt][hf * 2 + 0], h0, l0);
                    split2(acc[mt][nt][hf * 2 + 1], h1, l1);
                    *(__nv_bfloat162*)&och[(size_t)r * GN + col] = __nv_bfloat162{h0, h1};
                    *(__nv_bfloat162*)&ocl[(size_t)r * GN + col] = __nv_bfloat162{l0, l1};
                }
            }
    }
}

// ---------------- fp32 -> bf16 hi/lo split (x only) --------------------------
__global__ __launch_bounds__(256) void split_kernel(
    const float* __restrict__ in, __nv_bfloat16* __restrict__ hi,
    __nv_bfloat16* __restrict__ lo, int n4)
{
    int i = blockIdx.x * blockDim.x + threadIdx.x;
    if (i >= n4) return;
    float4 v = ((const float4*)in)[i];
    float vv[4] = {v.x, v.y, v.z, v.w};
    __nv_bfloat16 h[4], l[4];
    #pragma unroll
    for (int j = 0; j < 4; j++) split2(vv[j], h[j], l[j]);
    ((__nv_bfloat162*)hi)[2*i+0] = __nv_bfloat162{h[0], h[1]};
    ((__nv_bfloat162*)hi)[2*i+1] = __nv_bfloat162{h[2], h[3]};
    ((__nv_bfloat162*)lo)[2*i+0] = __nv_bfloat162{l[0], l[1]};
    ((__nv_bfloat162*)lo)[2*i+1] = __nv_bfloat162{l[2], l[3]};
}

// ---------------- transpose + split weights: W[K][N] -> Wt hi/lo [N][K] -----
__global__ void wsplit_t(const float* __restrict__ W,
                         __nv_bfloat16* __restrict__ th,
                         __nv_bfloat16* __restrict__ tl)
{
    __shared__ float t[32][33];
    const int k0 = blockIdx.y * 32, n0 = blockIdx.x * 32;
    for (int i = threadIdx.y; i < 32; i += 8)
        t[i][threadIdx.x] = W[(size_t)(k0 + i) * GN + n0 + threadIdx.x];
    __syncthreads();
    for (int i = threadIdx.y; i < 32; i += 8) {
        float v = t[threadIdx.x][i];
        __nv_bfloat16 h, l;
        split2(v, h, l);
        size_t o = (size_t)(n0 + i) * GK + k0 + threadIdx.x;
        th[o] = h;
        tl[o] = l;
    }
}

// ---------------- proj split (padded to RT rows, zero fill) ------------------
__global__ void psplit(const float* __restrict__ proj)
{
    int i = blockIdx.x * 256 + threadIdx.x;
    if (i >= RT * 64) return;
    int r = i >> 6, d = i & 63;
    float v = (r < RR) ? proj[r * 64 + d] : 0.0f;
    __nv_bfloat16 h, l;
    split2(v, h, l);
    g_projh[i] = h;
    g_projl[i] = l;
}

// ---------------- featmap HMMA: A resident, r0 loop, kpT + ksum for k --------
// grid (32 n0, 128 z), 256 threads, dyn smem FM_SMEM
__global__ __launch_bounds__(256, 2) void featmap_hmma()
{
    extern __shared__ char smem[];
    const int tid = threadIdx.x, wid = tid >> 5, lane = tid & 31;
    const int n0 = blockIdx.x * 128;
    const int z = blockIdx.y;
    const int which = z >> 6, bh = z & 63;
    const int b = bh >> 4, h = bh & 15;
    const __nv_bfloat16* __restrict__ Ahg = which ? g_kh : g_qh;
    const __nv_bfloat16* __restrict__ Alg = which ? g_kl : g_ql;
    const size_t abase = ((size_t)(b * NN + n0)) * GK + h * 64;

    const uint32_t sA_h = smem_u32(smem);
    const uint32_t sA_l = sA_h + 128 * 144;
    const uint32_t sP   = sA_h + 2 * 128 * 144;   // two 18432B slots (h|l)

    auto load_proj = [&](int r0i, int slot) {
        #pragma unroll
        for (int i = 0; i < 4; i++) {
            int idx = tid + i * 256;     // 0..1023
            int row = (idx & 511) >> 3, c = idx & 7;
            uint32_t dst = sP + slot * 18432 + (idx < 512 ? 0 : 9216)
                         + row * 144 + c * 16;
            const __nv_bfloat16* src = (idx < 512 ? g_projh : g_projl)
                                       + (r0i * 64 + row) * 64 + c * 8;
            cpa16(dst, src);
        }
        asm volatile("cp.async.commit_group;" ::: "memory");
    };

    // A load + proj slot0 -> group0 ; proj slot1 -> group1
    #pragma unroll
    for (int i = 0; i < 8; i++) {
        int idx = tid + i * 256;     // 0..2047
        int row = (idx & 1023) >> 3, c = idx & 7;
        uint32_t dst = (idx < 1024 ? sA_h : sA_l) + row * 144 + c * 16;
        const __nv_bfloat16* src = (idx < 1024 ? Ahg : Alg) + abase
                                   + (size_t)row * GK + c * 8;
        cpa16(dst, src);
    }
    load_proj(0, 0);
    load_proj(1, 1);

    const int wr = wid >> 2, wc = wid & 3;
    const int qr = lane >> 2, qc = lane & 3;

    for (int r0i = 0; r0i < 5; r0i++) {
        if (r0i < 4) { asm volatile("cp.async.wait_group 1;" ::: "memory"); }
        else         { asm volatile("cp.async.wait_group 0;" ::: "memory"); }
        __syncthreads();

        const uint32_t pH = sP + (r0i & 1) * 18432;
        const uint32_t pL = pH + 9216;

        float acc[4][2][4] = {};
        #pragma unroll
        for (int kt = 0; kt < 4; kt++) {
            uint32_t bh1[4], bl1[4];
            const int g = lane >> 3;
            const int brow = wc * 16 + (lane & 7) + (g >> 1) * 8;
            const uint32_t bk = (uint32_t)(kt * 16 + (g & 1) * 8) * 2;
            ldsm4(bh1, pH + (uint32_t)brow * 144 + bk);
            ldsm4(bl1, pL + (uint32_t)brow * 144 + bk);
            const int arow = wr * 64 + (lane & 15);
            const uint32_t ak = (uint32_t)(kt * 16 + (lane >> 4) * 8) * 2;
            #pragma unroll
            for (int mt = 0; mt < 4; mt++) {
                uint32_t ah[4], al[4];
                ldsm4(ah, sA_h + (uint32_t)(arow + mt * 16) * 144 + ak);
                ldsm4(al, sA_l + (uint32_t)(arow + mt * 16) * 144 + ak);
                #pragma unroll
                for (int nt = 0; nt < 2; nt++) {
                    mma16816(acc[mt][nt], ah, &bh1[nt * 2]);
                    mma16816(acc[mt][nt], ah, &bl1[nt * 2]);
                    mma16816(acc[mt][nt], al, &bh1[nt * 2]);
                }
            }
        }
        __syncthreads();
        if (r0i + 2 < 5) load_proj(r0i + 2, r0i & 1);

        // ---- epilogue for this r0
        if (which == 0) {
            #pragma unroll
            for (int mt = 0; mt < 4; mt++)
                #pragma unroll
                for (int nt = 0; nt < 2; nt++) {
                    int r = r0i * 64 + wc * 16 + nt * 8 + qc * 2;
                    if (r >= RP) continue;
                    bool valid = (r < RR);
                    #pragma unroll
                    for (int hf = 0; hf < 2; hf++) {
                        int nrow = n0 + wr * 64 + mt * 16 + qr + hf * 8;
                        float v0 = acc[mt][nt][hf * 2 + 0];
                        float v1 = acc[mt][nt][hf * 2 + 1];
                        v0 = valid ? (fmaxf(v0, 0.0f) + EPSF) : 0.0f;
                        v1 = valid ? (fmaxf(v1, 0.0f) + EPSF) : 0.0f;
                        __nv_bfloat16 h0, l0, h1, l1;
                        split2(v0, h0, l0);
                        split2(v1, h1, l1);
                        size_t o = ((size_t)bh * NN + nrow) * RP + r;
                        *(__nv_bfloat162*)&g_qph[o] = __nv_bfloat162{h0, h1};
                        *(__nv_bfloat162*)&g_qpl[o] = __nv_bfloat162{l0, l1};
                    }
                }
        } else {
            const size_t kb = (size_t)bh * RT * NN;
            #pragma unroll
            for (int nt = 0; nt < 2; nt++) {
                int r = r0i * 64 + wc * 16 + nt * 8 + qc * 2;
                bool valid = (r < RR);
                float s0 = 0.f, s1 = 0.f;
                #pragma unroll
                for (int mt = 0; mt < 4; mt++)
                    #pragma unroll
                    for (int hf = 0; hf < 2; hf++) {
                        int nrow = n0 + wr * 64 + mt * 16 + qr + hf * 8;
                        float v0 = acc[mt][nt][hf * 2 + 0];
                        float v1 = acc[mt][nt][hf * 2 + 1];
                        v0 = valid ? (fmaxf(v0, 0.0f) + EPSF) : 0.0f;
                        v1 = valid ? (fmaxf(v1, 0.0f) + EPSF) : 0.0f;
                        __nv_bfloat16 h0, l0, h1, l1;
                        split2(v0, h0, l0);
                        split2(v1, h1, l1);
                        g_kpTh[kb + (size_t)r * NN + nrow] = h0;
                        g_kpTl[kb + (size_t)r * NN + nrow] = l0;
                        g_kpTh[kb + (size_t)(r + 1) * NN + nrow] = h1;
                        g_kpTl[kb + (size_t)(r + 1) * NN + nrow] = l1;
                        s0 += v0;
                        s1 += v1;
                    }
                if (valid) {
                    atomicAdd(&g_ksum[bh * RP + r], s0);
                    atomicAdd(&g_ksum[bh * RP + r + 1], s1);
                }
            }
        }
    }
}

// ---------------- kv HMMA: kvacc[khalf][bh][r][d] = kpT @ v ------------------
// grid (BHN, 2 rhalf, 2 khalf), 256 threads, dyn smem KV_SMEM
__global__ __launch_bounds__(256, 2) void kv_hmma()
{
    extern __shared__ char smem[];
    const int tid = threadIdx.x, wid = tid >> 5, lane = tid & 31;
    const int bh = blockIdx.x, rhalf = blockIdx.y, khalf = blockIdx.z;
    const int b = bh >> 4, h = bh & 15;

    const __nv_bfloat16* __restrict__ Ahb =
        g_kpTh + ((size_t)bh * RT + rhalf * 160) * NN + khalf * 2048;
    const __nv_bfloat16* __restrict__ Alb =
        g_kpTl + ((size_t)bh * RT + rhalf * 160) * NN + khalf * 2048;
    const __nv_bfloat16* __restrict__ Bhb =
        g_vh + ((size_t)(b * NN + khalf * 2048)) * GK + h * 64;
    const __nv_bfloat16* __restrict__ Blb =
        g_vl + ((size_t)(b * NN + khalf * 2048)) * GK + h * 64;

    const int wm = wid >> 2, wn = wid & 3;   // 2 x 4 warps; warp tile 80r x 16d
    float acc[5][2][4] = {};

    auto load_stage = [&](int c, int st) {
        const int k0 = c * 32;
        char* sb = smem + st * KV_STAGE;
        #pragma unroll
        for (int i = 0; i < 7; i++) {
            int idx = tid + i * 256;    // 0..1791
            uint32_t dst;
            const __nv_bfloat16* src;
            if (idx < 640) {
                int row = idx >> 2, cc = idx & 3;
                dst = smem_u32(sb + row * 80 + cc * 16);
                src = Ahb + (size_t)row * NN + k0 + cc * 8;
            } else if (idx < 1280) {
                int j = idx - 640; int row = j >> 2, cc = j & 3;
                dst = smem_u32(sb + 12800 + row * 80 + cc * 16);
                src = Alb + (size_t)row * NN + k0 + cc * 8;
            } else if (idx < 1536) {
                int j = idx - 1280; int row = j >> 3, cc = j & 7;
                dst = smem_u32(sb + 25600 + row * 144 + cc * 16);
                src = Bhb + (size_t)(k0 + row) * GK + cc * 8;
            } else {
                int j = idx - 1536; int row = j >> 3, cc = j & 7;
                dst = smem_u32(sb + 25600 + 4608 + row * 144 + cc * 16);
                src = Blb + (size_t)(k0 + row) * GK + cc * 8;
            }
            cpa16(dst, src);
        }
        asm volatile("cp.async.commit_group;" ::: "memory");
    };

    load_stage(0, 0);

    for (int c = 0; c < 64; c++) {
        if (c + 1 < 64) {
            load_stage(c + 1, (c + 1) & 1);
            asm volatile("cp.async.wait_group 1;" ::: "memory");
        } else {
            asm volatile("cp.async.wait_group 0;" ::: "memory");
        }
        __syncthreads();

        const int st = c & 1;
        const uint32_t aH = smem_u32(smem + st * KV_STAGE);
        const uint32_t aL = aH + 12800;
        const uint32_t bHs = aH + 25600;
        const uint32_t bLs = bHs + 4608;

        #pragma unroll
        for (int kt = 0; kt < 2; kt++) {
            uint32_t bhf[4], blf[4];
            const int g = lane >> 3;
            const int browk = kt * 16 + (g & 1) * 8 + (lane & 7);
            const uint32_t bc = (uint32_t)(wn * 16 + (g >> 1) * 8) * 2;
            ldsm4t(bhf, bHs + (uint32_t)browk * 144 + bc);
            ldsm4t(blf, bLs + (uint32_t)browk * 144 + bc);
            const int arow = wm * 80 + (lane & 15);
            const uint32_t ak = (uint32_t)(kt * 16 + (lane >> 4) * 8) * 2;
            #pragma unroll
            for (int mt = 0; mt < 5; mt++) {
                uint32_t ah[4], al[4];
                ldsm4(ah, aH + (uint32_t)(arow + mt * 16) * 80 + ak);
                ldsm4(al, aL + (uint32_t)(arow + mt * 16) * 80 + ak);
                #pragma unroll
                for (int nt = 0; nt < 2; nt++) {
                    mma16816(acc[mt][nt], ah, &bhf[nt * 2]);
                    mma16816(acc[mt][nt], ah, &blf[nt * 2]);
                    mma16816(acc[mt][nt], al, &bhf[nt * 2]);
                }
            }
        }
        __syncthreads();
    }

    const int qr = lane >> 2, qc = lane & 3;
    float* outp = g_kvacc + ((size_t)(khalf * BHN + bh)) * RT * 64;
    #pragma unroll
    for (int mt = 0; mt < 5; mt++)
        #pragma unroll
        for (int nt = 0; nt < 2; nt++) {
            int r = rhalf * 160 + wm * 80 + mt * 16 + qr;
            int d = wn * 16 + nt * 8 + qc * 2;
            #pragma unroll
            for (int hf = 0; hf < 2; hf++) {
                float2 v = {acc[mt][nt][hf * 2 + 0], acc[mt][nt][hf * 2 + 1]};
                *(float2*)&outp[(size_t)(r + hf * 8) * 64 + d] = v;
            }
        }
}

// ---------------- kv finalize: sum khalves, transpose -> kvT[d][r] h/l -------
// grid (BHN, 5), block 256
__global__ void kv_finalize()
{
    __shared__ float t[64][65];
    const int bh = blockIdx.x, rblk = blockIdx.y;
    const int tid = threadIdx.x;
    const float* a0 = g_kvacc + ((size_t)bh * RT + rblk * 64) * 64;
    const float* a1 = g_kvacc + ((size_t)(BHN + bh) * RT + rblk * 64) * 64;
    #pragma unroll
    for (int i = 0; i < 16; i++) {
        int e = tid + i * 256;
        t[e >> 6][e & 63] = a0[e] + a1[e];
    }
    __syncthreads();
    const int d = tid >> 2, rs = (tid & 3) * 16;
    const size_t ob = ((size_t)bh * 64 + d) * RP;
    #pragma unroll
    for (int j = 0; j < 16; j += 2) {
        int rg = rblk * 64 + rs + j;
        if (rg >= RP) break;
        __nv_bfloat16 h0, l0, h1, l1;
        split2(t[rs + j][d], h0, l0);
        split2(t[rs + j + 1][d], h1, l1);
        *(__nv_bfloat162*)&g_kvTh[ob + rg] = __nv_bfloat162{h0, h1};
        *(__nv_bfloat162*)&g_kvTl[ob + rg] = __nv_bfloat162{l0, l1};
    }
}

// ---------------- qkv HMMA: om = (qp @ kvT^T) * d_inv, dinv fused ------------
__global__ __launch_bounds__(256, 2) void qkv_hmma()
{
    extern __shared__ char smem[];
    __shared__ float ksumS[RP];
    __shared__ float dpart[2][128];
    __shared__ float dinvS[128];
    const int tid = threadIdx.x, wid = tid >> 5, lane = tid & 31;
    const int n0 = blockIdx.x * 128;
    const int bh = blockIdx.y;
    const int b = bh >> 4, h = bh & 15;

    const __nv_bfloat16* __restrict__ Ahg = g_qph + ((size_t)bh * NN + n0) * RP;
    const __nv_bfloat16* __restrict__ Alg = g_qpl + ((size_t)bh * NN + n0) * RP;
    const __nv_bfloat16* __restrict__ Bhg = g_kvTh + (size_t)bh * 64 * RP;
    const __nv_bfloat16* __restrict__ Blg = g_kvTl + (size_t)bh * 64 * RP;

    for (int i = tid; i < RP; i += 256) ksumS[i] = g_ksum[bh * RP + i];

    float acc[4][2][4] = {};
    float myd = 0.f;
    const int drow = tid & 127, dhalf = tid >> 7;

    auto load_stage = [&](int c, int st) {
        const int k0 = c * KC;
        char* dstb = smem + st * QKV_STAGE;
        #pragma unroll
        for (int i = 0; i < 6; i++) {
            int idx = tid + i * 256;
            uint32_t dst;
            const __nv_bfloat16* src;
            if (idx < 512) {
                int row = idx >> 2, cc = idx & 3;
                dst = smem_u32(dstb + row * 80 + cc * 16);
                src = Ahg + (size_t)row * RP + k0 + cc * 8;
            } else if (idx < 1024) {
                int j = idx - 512; int row = j >> 2, cc = j & 3;
                dst = smem_u32(dstb + 128 * 80 + row * 80 + cc * 16);
                src = Alg + (size_t)row * RP + k0 + cc * 8;
            } else if (idx < 1280) {
                int j = idx - 1024; int row = j >> 2, cc = j & 3;
                dst = smem_u32(dstb + 2 * 128 * 80 + row * 80 + cc * 16);
                src = Bhg + (size_t)row * RP + k0 + cc * 8;
            } else {
                int j = idx - 1280; int row = j >> 2, cc = j & 3;
                dst = smem_u32(dstb + 2 * 128 * 80 + 64 * 80 + row * 80 + cc * 16);
                src = Blg + (size_t)row * RP + k0 + cc * 8;
            }
            cpa16(dst, src);
        }
        asm volatile("cp.async.commit_group;" ::: "memory");
    };

    const int NCH2 = RP / KC;  // 9
    load_stage(0, 0);

    for (int c = 0; c < NCH2; c++) {
        if (c + 1 < NCH2) {
            load_stage(c + 1, (c + 1) & 1);
            asm volatile("cp.async.wait_group 1;" ::: "memory");
        } else {
            asm volatile("cp.async.wait_group 0;" ::: "memory");
        }
        __syncthreads();

        const int st = c & 1;
        const uint32_t aH = smem_u32(smem + st * QKV_STAGE);
        const uint32_t aL = aH + 128 * 80;
        const uint32_t bH = aH + 2 * 128 * 80;
        const uint32_t bL = bH + 64 * 80;
        const int wr = wid >> 2, wc = wid & 3;

        {
            const __nv_bfloat16* ph = (const __nv_bfloat16*)(smem + st * QKV_STAGE
                                        + drow * 80 + dhalf * 32);
            const __nv_bfloat16* pl = (const __nv_bfloat16*)(smem + st * QKV_STAGE
                                        + 128 * 80 + drow * 80 + dhalf * 32);
            const float* ksp = ksumS + c * KC + dhalf * 16;
            #pragma unroll
            for (int kk = 0; kk < 16; kk++) {
                float v = __bfloat162float(ph[kk]) + __bfloat162float(pl[kk]);
                myd += v * ksp[kk];
            }
        }

        #pragma unroll
        for (int kt = 0; kt < 2; kt++) {
            uint32_t bh1[4], bl1[4];
            const int g = lane >> 3;
            const int brow = wc * 16 + (lane & 7) + (g >> 1) * 8;
            const uint32_t bk = (uint32_t)(kt * 16 + (g & 1) * 8) * 2;
            ldsm4(bh1, bH + (uint32_t)brow * 80 + bk);
            ldsm4(bl1, bL + (uint32_t)brow * 80 + bk);
            const int arow = wr * 64 + (lane & 15);
            const uint32_t ak = (uint32_t)(kt * 16 + (lane >> 4) * 8) * 2;
            #pragma unroll
            for (int mt = 0; mt < 4; mt++) {
                uint32_t ah[4], al[4];
                ldsm4(ah, aH + (uint32_t)(arow + mt * 16) * 80 + ak);
                ldsm4(al, aL + (uint32_t)(arow + mt * 16) * 80 + ak);
                #pragma unroll
                for (int nt = 0; nt < 2; nt++) {
                    mma16816(acc[mt][nt], ah, &bh1[nt * 2]);
                    mma16816(acc[mt][nt], ah, &bl1[nt * 2]);
                    mma16816(acc[mt][nt], al, &bh1[nt * 2]);
                }
            }
        }
        __syncthreads();
    }

    dpart[dhalf][drow] = myd;
    __syncthreads();
    if (tid < 128) dinvS[tid] = 1.0f / (dpart[0][tid] + dpart[1][tid]);
    __syncthreads();

    const int wr = wid >> 2, wc = wid & 3;
    const int qr = lane >> 2, qc = lane & 3;
    #pragma unroll
    for (int mt = 0; mt < 4; mt++)
        #pragma unroll
        for (int nt = 0; nt < 2; nt++) {
            int d = wc * 16 + nt * 8 + qc * 2;
            #pragma unroll
            for (int hf = 0; hf < 2; hf++) {
                int lrow = wr * 64 + mt * 16 + qr + hf * 8;
                int nrow = n0 + lrow;
                float di = dinvS[lrow];
                float v0 = acc[mt][nt][hf * 2 + 0] * di;
                float v1 = acc[mt][nt][hf * 2 + 1] * di;
                __nv_bfloat16 h0, l0, h1, l1;
                split2(v0, h0, l0);
                split2(v1, h1, l1);
                size_t o = ((size_t)(b * NN + nrow)) * GK + h * 64 + d;
                *(__nv_bfloat162*)&g_omh[o] = __nv_bfloat162{h0, h1};
                *(__nv_bfloat162*)&g_oml[o] = __nv_bfloat162{l0, l1};
            }
        }
}

// ---------------- launch -----------------------------------------------------
extern "C" void kernel_launch(void* const* d_in, const int* in_sizes, int n_in,
                              void* d_out, int out_size)
{
    const float* x    = (const float*)d_in[0];
    const float* Wq   = (const float*)d_in[1];
    const float* Wk   = (const float*)d_in[2];
    const float* Wv   = (const float*)d_in[3];
    const float* Wo   = (const float*)d_in[4];
    const float* bo   = (const float*)d_in[5];
    const float* proj = (const float*)d_in[6];

    float* ksum;
    __nv_bfloat16 *xh, *xl, *omh, *oml, *wth, *wtl;
    cudaGetSymbolAddress((void**)&ksum, g_ksum);
    cudaGetSymbolAddress((void**)&xh,   g_xh);
    cudaGetSymbolAddress((void**)&xl,   g_xl);
    cudaGetSymbolAddress((void**)&omh,  g_omh);
    cudaGetSymbolAddress((void**)&oml,  g_oml);
    cudaGetSymbolAddress((void**)&wth,  g_wth);
    cudaGetSymbolAddress((void**)&wtl,  g_wtl);

    cudaFuncSetAttribute(gemm_hmma,
                         cudaFuncAttributeMaxDynamicSharedMemorySize, SMEM_DYN);
    cudaFuncSetAttribute(featmap_hmma,
                         cudaFuncAttributeMaxDynamicSharedMemorySize, FM_SMEM);
    cudaFuncSetAttribute(kv_hmma,
                         cudaFuncAttributeMaxDynamicSharedMemorySize, KV_SMEM);
    cudaFuncSetAttribute(qkv_hmma,
                         cudaFuncAttributeMaxDynamicSharedMemorySize, QKV_SMEM);

    const int n4 = GM * GK / 4;

    split_kernel<<<(n4 + 255) / 256, 256>>>(x, xh, xl, n4);
    wsplit_t<<<dim3(32, 32), dim3(32, 8)>>>(Wq, wth + 0 * (size_t)GN * GK, wtl + 0 * (size_t)GN * GK);
    wsplit_t<<<dim3(32, 32), dim3(32, 8)>>>(Wk, wth + 1 * (size_t)GN * GK, wtl + 1 * (size_t)GN * GK);
    wsplit_t<<<dim3(32, 32), dim3(32, 8)>>>(Wv, wth + 2 * (size_t)GN * GK, wtl + 2 * (size_t)GN * GK);
    wsplit_t<<<dim3(32, 32), dim3(32, 8)>>>(Wo, wth + 3 * (size_t)GN * GK, wtl + 3 * (size_t)GN * GK);
    psplit<<<80, 256>>>(proj);

    cudaMemsetAsync(ksum, 0, BHN * RP * sizeof(float));

    // merged Q/K/V GEMM over N = 3072 (bf16 h/l outputs incl. V)
    gemm_hmma<<<dim3(24, GM / 128), 256, SMEM_DYN>>>(xh, xl, wth, wtl,
                                                     nullptr, nullptr, 0);

    featmap_hmma<<<dim3(32, 128), 256, FM_SMEM>>>();   // qp, kpT, ksum

    kv_hmma<<<dim3(BHN, 2, 2), 256, KV_SMEM>>>();      // kvacc partials

    kv_finalize<<<dim3(BHN, 5), 256>>>();              // kvT h/l

    qkv_hmma<<<dim3(32, BHN), 256, QKV_SMEM>>>();      // om h/l (dinv fused)

    gemm_hmma<<<dim3(8, GM / 128), 256, SMEM_DYN>>>(omh, oml,
        wth + 3 * (size_t)GN * GK, wtl + 3 * (size_t)GN * GK,
        bo, (float*)d_out, 1);
}

// round 12
// speedup vs baseline: 1.9469x; 1.0485x over previous
#include <cuda_runtime.h>
#include <cuda_bf16.h>
#include <cstdint>

#define BB 4
#define NN 4096
#define CC 1024
#define HH 16
#define DH 64
#define RR 266
#define RP 288
#define RT 320
#define EPSF 1e-3f
#define BHN (BB*HH)   // 64
#define GM (BB*NN)    // 16384
#define GK 1024
#define GN 1024
#define KC 32
#define NCH (GK/KC)        // 32 chunks
#define MAT_BYTES (128*80)
#define STAGE_BYTES (4*MAT_BYTES)  // 40960
#define SMEM_DYN (2*STAGE_BYTES)   // 81920
// featmap smem: A h/l (2*128*144) + 2 proj slots (2*(64*144*2))
#define FM_SMEM (2*128*144 + 2*2*64*144)   // 73728
// kv smem: A h/l (2*160*80) + B h/l (2*32*144)
#define KV_STAGE (2*160*80 + 2*32*144)   // 34816
#define KV_SMEM (2*KV_STAGE)             // 69632
// qkv_fused smem layout
#define QF_SQH  0
#define QF_SQL  18432
#define QF_SQPH 36864
#define QF_SQPL 47104
#define QF_PROJ 57344          // 2 slots x (4608 h + 4608 l)
#define QF_KVT  75776          // 2 slots x (5120 h + 5120 l)
#define QF_SMEM 96256

// ---------------- scratch (device globals; no allocation allowed) ----------
__device__ float g_ksum[BHN*RP];
__device__ float g_kvacc[(size_t)2*BHN*RT*64];
__device__ __nv_bfloat16 g_xh[(size_t)GM*GK];
__device__ __nv_bfloat16 g_xl[(size_t)GM*GK];
__device__ __nv_bfloat16 g_qh[(size_t)GM*GK];
__device__ __nv_bfloat16 g_ql[(size_t)GM*GK];
__device__ __nv_bfloat16 g_kh[(size_t)GM*GK];
__device__ __nv_bfloat16 g_kl[(size_t)GM*GK];
__device__ __nv_bfloat16 g_vh[(size_t)GM*GK];
__device__ __nv_bfloat16 g_vl[(size_t)GM*GK];
__device__ __nv_bfloat16 g_omh[(size_t)GM*GK];
__device__ __nv_bfloat16 g_oml[(size_t)GM*GK];
__device__ __nv_bfloat16 g_wth[(size_t)4*GN*GK];
__device__ __nv_bfloat16 g_wtl[(size_t)4*GN*GK];
__device__ __nv_bfloat16 g_projh[RT*64];
__device__ __nv_bfloat16 g_projl[RT*64];
__device__ __nv_bfloat16 g_kpTh[(size_t)BHN*RT*NN];
__device__ __nv_bfloat16 g_kpTl[(size_t)BHN*RT*NN];
__device__ __nv_bfloat16 g_kvTh[BHN*64*RP];
__device__ __nv_bfloat16 g_kvTl[BHN*64*RP];

// ---------------- helpers ----------------------------------------------------
__device__ __forceinline__ uint32_t smem_u32(const void* p) {
    uint32_t a;
    asm("{ .reg .u64 t; cvta.to.shared.u64 t, %1; cvt.u32.u64 %0, t; }"
        : "=r"(a) : "l"(p));
    return a;
}
__device__ __forceinline__ void cpa16(uint32_t dst, const void* src) {
    asm volatile("cp.async.cg.shared.global [%0], [%1], 16;" :: "r"(dst), "l"(src));
}
__device__ __forceinline__ void ldsm4(uint32_t* r, uint32_t addr) {
    asm volatile("ldmatrix.sync.aligned.m8n8.x4.shared.b16 {%0,%1,%2,%3}, [%4];"
        : "=r"(r[0]), "=r"(r[1]), "=r"(r[2]), "=r"(r[3]) : "r"(addr));
}
__device__ __forceinline__ void ldsm4t(uint32_t* r, uint32_t addr) {
    asm volatile("ldmatrix.sync.aligned.m8n8.x4.trans.shared.b16 {%0,%1,%2,%3}, [%4];"
        : "=r"(r[0]), "=r"(r[1]), "=r"(r[2]), "=r"(r[3]) : "r"(addr));
}
__device__ __forceinline__ void mma16816(float* d, const uint32_t* a, const uint32_t* b) {
    asm volatile(
        "mma.sync.aligned.m16n8k16.row.col.f32.bf16.bf16.f32 "
        "{%0,%1,%2,%3}, {%4,%5,%6,%7}, {%8,%9}, {%0,%1,%2,%3};"
        : "+f"(d[0]), "+f"(d[1]), "+f"(d[2]), "+f"(d[3])
        : "r"(a[0]), "r"(a[1]), "r"(a[2]), "r"(a[3]), "r"(b[0]), "r"(b[1]));
}
__device__ __forceinline__ void split2(float v, __nv_bfloat16& h, __nv_bfloat16& l) {
    h = __float2bfloat16(v);
    l = __float2bfloat16(v - __bfloat162float(h));
}

// ---------------- HMMA split-bf16 GEMM, 2-stage, 2 CTAs/SM -------------------
__global__ __launch_bounds__(256, 2) void gemm_hmma(
    const __nv_bfloat16* __restrict__ Ah, const __nv_bfloat16* __restrict__ Al,
    const __nv_bfloat16* __restrict__ Bh, const __nv_bfloat16* __restrict__ Bl,
    const float* __restrict__ bias, float* __restrict__ Cf, int mode)
{
    extern __shared__ char smem[];
    const int tid = threadIdx.x;
    const int wid = tid >> 5, lane = tid & 31;
    const int m0 = blockIdx.y * 128, n0 = blockIdx.x * 128;
    const int wr = wid >> 2, wc = wid & 3;

    const __nv_bfloat16* gsrc0 = Ah + (size_t)m0 * GK;
    const __nv_bfloat16* gsrc1 = Al + (size_t)m0 * GK;
    const __nv_bfloat16* gsrc2 = Bh + (size_t)n0 * GK;
    const __nv_bfloat16* gsrc3 = Bl + (size_t)n0 * GK;

    float acc[4][4][4] = {};

    auto load_stage = [&](int c, int st) {
        const int k0 = c * KC;
        char* dstb = smem + st * STAGE_BYTES;
        #pragma unroll
        for (int i = 0; i < 8; i++) {
            int idx = tid + i * 256;
            int mat = idx >> 9;
            int row = (idx >> 2) & 127;
            int c16 = idx & 3;
            uint32_t dst = smem_u32(dstb + mat * MAT_BYTES + row * 80 + c16 * 16);
            const __nv_bfloat16* g =
                (mat == 0) ? gsrc0 : (mat == 1) ? gsrc1 : (mat == 2) ? gsrc2 : gsrc3;
            cpa16(dst, g + (size_t)row * GK + k0 + c16 * 8);
        }
        asm volatile("cp.async.commit_group;" ::: "memory");
    };

    load_stage(0, 0);

    for (int c = 0; c < NCH; c++) {
        if (c + 1 < NCH) {
            load_stage(c + 1, (c + 1) & 1);
            asm volatile("cp.async.wait_group 1;" ::: "memory");
        } else {
            asm volatile("cp.async.wait_group 0;" ::: "memory");
        }
        __syncthreads();

        const int st = c & 1;
        const uint32_t aH = smem_u32(smem + st * STAGE_BYTES);
        const uint32_t aL = aH + MAT_BYTES;
        const uint32_t bH = aH + 2 * MAT_BYTES;
        const uint32_t bL = aH + 3 * MAT_BYTES;

        #pragma unroll
        for (int kt = 0; kt < 2; kt++) {
            uint32_t bh[2][4], bl[2][4];
            const int g = lane >> 3;
            const int brow = wc * 32 + (lane & 7) + (g >> 1) * 8;
            const uint32_t bkoff = (uint32_t)(kt * 16 + (g & 1) * 8) * 2;
            #pragma unroll
            for (int nt2 = 0; nt2 < 2; nt2++) {
                ldsm4(bh[nt2], bH + (uint32_t)(brow + nt2 * 16) * 80 + bkoff);
                ldsm4(bl[nt2], bL + (uint32_t)(brow + nt2 * 16) * 80 + bkoff);
            }
            const int arow = wr * 64 + (lane & 15);
            const uint32_t akoff = (uint32_t)(kt * 16 + (lane >> 4) * 8) * 2;
            #pragma unroll
            for (int mt = 0; mt < 4; mt++) {
                uint32_t ah[4], al[4];
                ldsm4(ah, aH + (uint32_t)(arow + mt * 16) * 80 + akoff);
                ldsm4(al, aL + (uint32_t)(arow + mt * 16) * 80 + akoff);
                #pragma unroll
                for (int nt = 0; nt < 4; nt++) {
                    const uint32_t* bhp = &bh[nt >> 1][(nt & 1) * 2];
                    const uint32_t* blp = &bl[nt >> 1][(nt & 1) * 2];
                    mma16816(acc[mt][nt], ah, bhp);
                    mma16816(acc[mt][nt], ah, blp);
                    mma16816(acc[mt][nt], al, bhp);
                }
            }
        }
        __syncthreads();
    }

    const int qr = lane >> 2, qc = lane & 3;
    if (mode == 1) {
        #pragma unroll
        for (int mt = 0; mt < 4; mt++)
            #pragma unroll
            for (int nt = 0; nt < 4; nt++) {
                int row = m0 + wr * 64 + mt * 16 + qr;
                int col = n0 + wc * 32 + nt * 8 + qc * 2;
                float bx = bias[col], by = bias[col + 1];
                float2 v0 = {acc[mt][nt][0] + bx, acc[mt][nt][1] + by};
                float2 v1 = {acc[mt][nt][2] + bx, acc[mt][nt][3] + by};
                *(float2*)&Cf[(size_t)row * GN + col] = v0;
                *(float2*)&Cf[(size_t)(row + 8) * GN + col] = v1;
            }
    } else {
        __nv_bfloat16 *och, *ocl;
        int cbase;
        if (n0 < 1024)      { och = g_qh; ocl = g_ql; cbase = n0; }
        else if (n0 < 2048) { och = g_kh; ocl = g_kl; cbase = n0 - 1024; }
        else                { och = g_vh; ocl = g_vl; cbase = n0 - 2048; }
        #pragma unroll
        for (int mt = 0; mt < 4; mt++)
            #pragma unroll
            for (int nt = 0; nt < 4; nt++) {
                int row = m0 + wr * 64 + mt * 16 + qr;
                int col = cbase + wc * 32 + nt * 8 + qc * 2;
                #pragma unroll
                for (int hf = 0; hf < 2; hf++) {
                    int r = row + hf * 8;
                    __nv_bfloat16 h0, l0, h1, l1;
                    split2(acc[mt][nt][hf * 2 + 0], h0, l0);
                    split2(acc[mt][nt][hf * 2 + 1], h1, l1);
                    *(__nv_bfloat162*)&och[(size_t)r * GN + col] = __nv_bfloat162{h0, h1};
                    *(__nv_bfloat162*)&ocl[(size_t)r * GN + col] = __nv_bfloat162{l0, l1};
                }
            }
    }
}

// ---------------- fp32 -> bf16 hi/lo split (x only) --------------------------
__global__ __launch_bounds__(256) void split_kernel(
    const float* __restrict__ in, __nv_bfloat16* __restrict__ hi,
    __nv_bfloat16* __restrict__ lo, int n4)
{
    int i = blockIdx.x * blockDim.x + threadIdx.x;
    if (i >= n4) return;
    float4 v = ((const float4*)in)[i];
    float vv[4] = {v.x, v.y, v.z, v.w};
    __nv_bfloat16 h[4], l[4];
    #pragma unroll
    for (int j = 0; j < 4; j++) split2(vv[j], h[j], l[j]);
    ((__nv_bfloat162*)hi)[2*i+0] = __nv_bfloat162{h[0], h[1]};
    ((__nv_bfloat162*)hi)[2*i+1] = __nv_bfloat162{h[2], h[3]};
    ((__nv_bfloat162*)lo)[2*i+0] = __nv_bfloat162{l[0], l[1]};
    ((__nv_bfloat162*)lo)[2*i+1] = __nv_bfloat162{l[2], l[3]};
}

// ---------------- transpose + split weights: W[K][N] -> Wt hi/lo [N][K] -----
__global__ void wsplit_t(const float* __restrict__ W,
                         __nv_bfloat16* __restrict__ th,
                         __nv_bfloat16* __restrict__ tl)
{
    __shared__ float t[32][33];
    const int k0 = blockIdx.y * 32, n0 = blockIdx.x * 32;
    for (int i = threadIdx.y; i < 32; i += 8)
        t[i][threadIdx.x] = W[(size_t)(k0 + i) * GN + n0 + threadIdx.x];
    __syncthreads();
    for (int i = threadIdx.y; i < 32; i += 8) {
        float v = t[threadIdx.x][i];
        __nv_bfloat16 h, l;
        split2(v, h, l);
        size_t o = (size_t)(n0 + i) * GK + k0 + threadIdx.x;
        th[o] = h;
        tl[o] = l;
    }
}

// ---------------- proj split (padded to RT rows, zero fill) ------------------
__global__ void psplit(const float* __restrict__ proj)
{
    int i = blockIdx.x * 256 + threadIdx.x;
    if (i >= RT * 64) return;
    int r = i >> 6, d = i & 63;
    float v = (r < RR) ? proj[r * 64 + d] : 0.0f;
    __nv_bfloat16 h, l;
    split2(v, h, l);
    g_projh[i] = h;
    g_projl[i] = l;
}

// ---------------- featmap HMMA (k only): kpT + ksum ---------------------------
// grid (32 n0, 64 bh), 256 threads, dyn smem FM_SMEM
__global__ __launch_bounds__(256, 2) void featmap_hmma()
{
    extern __shared__ char smem[];
    const int tid = threadIdx.x, wid = tid >> 5, lane = tid & 31;
    const int n0 = blockIdx.x * 128;
    const int bh = blockIdx.y;
    const int b = bh >> 4, h = bh & 15;
    const size_t abase = ((size_t)(b * NN + n0)) * GK + h * 64;

    const uint32_t sA_h = smem_u32(smem);
    const uint32_t sA_l = sA_h + 128 * 144;
    const uint32_t sP   = sA_h + 2 * 128 * 144;

    auto load_proj = [&](int r0i, int slot) {
        #pragma unroll
        for (int i = 0; i < 4; i++) {
            int idx = tid + i * 256;
            int row = (idx & 511) >> 3, c = idx & 7;
            uint32_t dst = sP + slot * 18432 + (idx < 512 ? 0 : 9216)
                         + row * 144 + c * 16;
            const __nv_bfloat16* src = (idx < 512 ? g_projh : g_projl)
                                       + (r0i * 64 + row) * 64 + c * 8;
            cpa16(dst, src);
        }
        asm volatile("cp.async.commit_group;" ::: "memory");
    };

    #pragma unroll
    for (int i = 0; i < 8; i++) {
        int idx = tid + i * 256;
        int row = (idx & 1023) >> 3, c = idx & 7;
        uint32_t dst = (idx < 1024 ? sA_h : sA_l) + row * 144 + c * 16;
        const __nv_bfloat16* src = (idx < 1024 ? g_kh : g_kl) + abase
                                   + (size_t)row * GK + c * 8;
        cpa16(dst, src);
    }
    load_proj(0, 0);
    load_proj(1, 1);

    const int wr = wid >> 2, wc = wid & 3;
    const int qr = lane >> 2, qc = lane & 3;

    for (int r0i = 0; r0i < 5; r0i++) {
        if (r0i < 4) { asm volatile("cp.async.wait_group 1;" ::: "memory"); }
        else         { asm volatile("cp.async.wait_group 0;" ::: "memory"); }
        __syncthreads();

        const uint32_t pH = sP + (r0i & 1) * 18432;
        const uint32_t pL = pH + 9216;

        float acc[4][2][4] = {};
        #pragma unroll
        for (int kt = 0; kt < 4; kt++) {
            uint32_t bh1[4], bl1[4];
            const int g = lane >> 3;
            const int brow = wc * 16 + (lane & 7) + (g >> 1) * 8;
            const uint32_t bk = (uint32_t)(kt * 16 + (g & 1) * 8) * 2;
            ldsm4(bh1, pH + (uint32_t)brow * 144 + bk);
            ldsm4(bl1, pL + (uint32_t)brow * 144 + bk);
            const int arow = wr * 64 + (lane & 15);
            const uint32_t ak = (uint32_t)(kt * 16 + (lane >> 4) * 8) * 2;
            #pragma unroll
            for (int mt = 0; mt < 4; mt++) {
                uint32_t ah[4], al[4];
                ldsm4(ah, sA_h + (uint32_t)(arow + mt * 16) * 144 + ak);
                ldsm4(al, sA_l + (uint32_t)(arow + mt * 16) * 144 + ak);
                #pragma unroll
                for (int nt = 0; nt < 2; nt++) {
                    mma16816(acc[mt][nt], ah, &bh1[nt * 2]);
                    mma16816(acc[mt][nt], ah, &bl1[nt * 2]);
                    mma16816(acc[mt][nt], al, &bh1[nt * 2]);
                }
            }
        }
        __syncthreads();
        if (r0i + 2 < 5) load_proj(r0i + 2, r0i & 1);

        const size_t kb = (size_t)bh * RT * NN;
        #pragma unroll
        for (int nt = 0; nt < 2; nt++) {
            int r = r0i * 64 + wc * 16 + nt * 8 + qc * 2;
            bool valid = (r < RR);
            float s0 = 0.f, s1 = 0.f;
            #pragma unroll
            for (int mt = 0; mt < 4; mt++)
                #pragma unroll
                for (int hf = 0; hf < 2; hf++) {
                    int nrow = n0 + wr * 64 + mt * 16 + qr + hf * 8;
                    float v0 = acc[mt][nt][hf * 2 + 0];
                    float v1 = acc[mt][nt][hf * 2 + 1];
                    v0 = valid ? (fmaxf(v0, 0.0f) + EPSF) : 0.0f;
                    v1 = valid ? (fmaxf(v1, 0.0f) + EPSF) : 0.0f;
                    __nv_bfloat16 h0, l0, h1, l1;
                    split2(v0, h0, l0);
                    split2(v1, h1, l1);
                    g_kpTh[kb + (size_t)r * NN + nrow] = h0;
                    g_kpTl[kb + (size_t)r * NN + nrow] = l0;
                    g_kpTh[kb + (size_t)(r + 1) * NN + nrow] = h1;
                    g_kpTl[kb + (size_t)(r + 1) * NN + nrow] = l1;
                    s0 += v0;
                    s1 += v1;
                }
            if (valid) {
                atomicAdd(&g_ksum[bh * RP + r], s0);
                atomicAdd(&g_ksum[bh * RP + r + 1], s1);
            }
        }
    }
}

// ---------------- kv HMMA: kvacc[khalf][bh][r][d] = kpT @ v ------------------
__global__ __launch_bounds__(256, 2) void kv_hmma()
{
    extern __shared__ char smem[];
    const int tid = threadIdx.x, wid = tid >> 5, lane = tid & 31;
    const int bh = blockIdx.x, rhalf = blockIdx.y, khalf = blockIdx.z;
    const int b = bh >> 4, h = bh & 15;

    const __nv_bfloat16* __restrict__ Ahb =
        g_kpTh + ((size_t)bh * RT + rhalf * 160) * NN + khalf * 2048;
    const __nv_bfloat16* __restrict__ Alb =
        g_kpTl + ((size_t)bh * RT + rhalf * 160) * NN + khalf * 2048;
    const __nv_bfloat16* __restrict__ Bhb =
        g_vh + ((size_t)(b * NN + khalf * 2048)) * GK + h * 64;
    const __nv_bfloat16* __restrict__ Blb =
        g_vl + ((size_t)(b * NN + khalf * 2048)) * GK + h * 64;

    const int wm = wid >> 2, wn = wid & 3;
    float acc[5][2][4] = {};

    auto load_stage = [&](int c, int st) {
        const int k0 = c * 32;
        char* sb = smem + st * KV_STAGE;
        #pragma unroll
        for (int i = 0; i < 7; i++) {
            int idx = tid + i * 256;
            uint32_t dst;
            const __nv_bfloat16* src;
            if (idx < 640) {
                int row = idx >> 2, cc = idx & 3;
                dst = smem_u32(sb + row * 80 + cc * 16);
                src = Ahb + (size_t)row * NN + k0 + cc * 8;
            } else if (idx < 1280) {
                int j = idx - 640; int row = j >> 2, cc = j & 3;
                dst = smem_u32(sb + 12800 + row * 80 + cc * 16);
                src = Alb + (size_t)row * NN + k0 + cc * 8;
            } else if (idx < 1536) {
                int j = idx - 1280; int row = j >> 3, cc = j & 7;
                dst = smem_u32(sb + 25600 + row * 144 + cc * 16);
                src = Bhb + (size_t)(k0 + row) * GK + cc * 8;
            } else {
                int j = idx - 1536; int row = j >> 3, cc = j & 7;
                dst = smem_u32(sb + 25600 + 4608 + row * 144 + cc * 16);
                src = Blb + (size_t)(k0 + row) * GK + cc * 8;
            }
            cpa16(dst, src);
        }
        asm volatile("cp.async.commit_group;" ::: "memory");
    };

    load_stage(0, 0);

    for (int c = 0; c < 64; c++) {
        if (c + 1 < 64) {
            load_stage(c + 1, (c + 1) & 1);
            asm volatile("cp.async.wait_group 1;" ::: "memory");
        } else {
            asm volatile("cp.async.wait_group 0;" ::: "memory");
        }
        __syncthreads();

        const int st = c & 1;
        const uint32_t aH = smem_u32(smem + st * KV_STAGE);
        const uint32_t aL = aH + 12800;
        const uint32_t bHs = aH + 25600;
        const uint32_t bLs = bHs + 4608;

        #pragma unroll
        for (int kt = 0; kt < 2; kt++) {
            uint32_t bhf[4], blf[4];
            const int g = lane >> 3;
            const int browk = kt * 16 + (g & 1) * 8 + (lane & 7);
            const uint32_t bc = (uint32_t)(wn * 16 + (g >> 1) * 8) * 2;
            ldsm4t(bhf, bHs + (uint32_t)browk * 144 + bc);
            ldsm4t(blf, bLs + (uint32_t)browk * 144 + bc);
            const int arow = wm * 80 + (lane & 15);
            const uint32_t ak = (uint32_t)(kt * 16 + (lane >> 4) * 8) * 2;
            #pragma unroll
            for (int mt = 0; mt < 5; mt++) {
                uint32_t ah[4], al[4];
                ldsm4(ah, aH + (uint32_t)(arow + mt * 16) * 80 + ak);
                ldsm4(al, aL + (uint32_t)(arow + mt * 16) * 80 + ak);
                #pragma unroll
                for (int nt = 0; nt < 2; nt++) {
                    mma16816(acc[mt][nt], ah, &bhf[nt * 2]);
                    mma16816(acc[mt][nt], ah, &blf[nt * 2]);
                    mma16816(acc[mt][nt], al, &bhf[nt * 2]);
                }
            }
        }
        __syncthreads();
    }

    const int qr = lane >> 2, qc = lane & 3;
    float* outp = g_kvacc + ((size_t)(khalf * BHN + bh)) * RT * 64;
    #pragma unroll
    for (int mt = 0; mt < 5; mt++)
        #pragma unroll
        for (int nt = 0; nt < 2; nt++) {
            int r = rhalf * 160 + wm * 80 + mt * 16 + qr;
            int d = wn * 16 + nt * 8 + qc * 2;
            #pragma unroll
            for (int hf = 0; hf < 2; hf++) {
                float2 v = {acc[mt][nt][hf * 2 + 0], acc[mt][nt][hf * 2 + 1]};
                *(float2*)&outp[(size_t)(r + hf * 8) * 64 + d] = v;
            }
        }
}

// ---------------- kv finalize: sum khalves, transpose -> kvT[d][r] h/l -------
__global__ void kv_finalize()
{
    __shared__ float t[64][65];
    const int bh = blockIdx.x, rblk = blockIdx.y;
    const int tid = threadIdx.x;
    const float* a0 = g_kvacc + ((size_t)bh * RT + rblk * 64) * 64;
    const float* a1 = g_kvacc + ((size_t)(BHN + bh) * RT + rblk * 64) * 64;
    #pragma unroll
    for (int i = 0; i < 16; i++) {
        int e = tid + i * 256;
        t[e >> 6][e & 63] = a0[e] + a1[e];
    }
    __syncthreads();
    const int d = tid >> 2, rs = (tid & 3) * 16;
    const size_t ob = ((size_t)bh * 64 + d) * RP;
    #pragma unroll
    for (int j = 0; j < 16; j += 2) {
        int rg = rblk * 64 + rs + j;
        if (rg >= RP) break;
        __nv_bfloat16 h0, l0, h1, l1;
        split2(t[rs + j][d], h0, l0);
        split2(t[rs + j + 1][d], h1, l1);
        *(__nv_bfloat162*)&g_kvTh[ob + rg] = __nv_bfloat162{h0, h1};
        *(__nv_bfloat162*)&g_kvTl[ob + rg] = __nv_bfloat162{l0, l1};
    }
}

// ---------------- qkv_fused: QP = relu(q@projT)+eps in smem, om = QP@kvT*dinv -
// grid (32 n0, 64 bh), 256 threads, dyn smem QF_SMEM
__global__ __launch_bounds__(256, 2) void qkv_fused()
{
    extern __shared__ char smem[];
    __shared__ float ksumS[RP];
    __shared__ float dpart[2][128];
    __shared__ float dinvS[128];
    const int tid = threadIdx.x, wid = tid >> 5, lane = tid & 31;
    const int n0 = blockIdx.x * 128;
    const int bh = blockIdx.y;
    const int b = bh >> 4, h = bh & 15;
    const uint32_t sb = smem_u32(smem);

    const size_t qbase = ((size_t)(b * NN + n0)) * GK + h * 64;
    const __nv_bfloat16* __restrict__ Bhg = g_kvTh + (size_t)bh * 64 * RP;
    const __nv_bfloat16* __restrict__ Blg = g_kvTl + (size_t)bh * 64 * RP;

    for (int i = tid; i < RP; i += 256) ksumS[i] = g_ksum[bh * RP + i];

    // q tile (128 x 64 h/l, pitch 144)
    #pragma unroll
    for (int i = 0; i < 8; i++) {
        int idx = tid + i * 256;
        int row = (idx & 1023) >> 3, c = idx & 7;
        uint32_t dst = sb + (idx < 1024 ? QF_SQH : QF_SQL) + row * 144 + c * 16;
        const __nv_bfloat16* src = (idx < 1024 ? g_qh : g_ql) + qbase
                                   + (size_t)row * GK + c * 8;
        cpa16(dst, src);
    }

    auto load_chunk = [&](int c, int slot) {
        // proj rows [c*32, c*32+32) x 64d, pitch 144
        #pragma unroll
        for (int i = 0; i < 2; i++) {
            int idx = tid + i * 256;
            int row = (idx & 255) >> 3, cc = idx & 7;
            uint32_t dst = sb + QF_PROJ + slot * 9216 + (idx < 256 ? 0 : 4608)
                         + row * 144 + cc * 16;
            const __nv_bfloat16* src = (idx < 256 ? g_projh : g_projl)
                                       + (c * 32 + row) * 64 + cc * 8;
            cpa16(dst, src);
        }
        // kvT: 64 d-rows x 32 r (64B), pitch 80
        #pragma unroll
        for (int i = 0; i < 2; i++) {
            int idx = tid + i * 256;
            int row = (idx & 255) >> 2, cc = idx & 3;
            uint32_t dst = sb + QF_KVT + slot * 10240 + (idx < 256 ? 0 : 5120)
                         + row * 80 + cc * 16;
            const __nv_bfloat16* src = (idx < 256 ? Bhg : Blg)
                                       + (size_t)row * RP + c * 32 + cc * 8;
            cpa16(dst, src);
        }
        asm volatile("cp.async.commit_group;" ::: "memory");
    };

    load_chunk(0, 0);   // commits q-tile + chunk0 as group 0
    load_chunk(1, 1);   // group 1

    float accO[4][2][4] = {};
    float myd = 0.f;
    const int drow = tid & 127, dhalf = tid >> 7;
    const int wrq = wid >> 1, wcq = wid & 1;    // QP phase: 4x2 warps (32 x 16)
    const int wr = wid >> 2, wc = wid & 3;      // om phase: 2x4 warps (64 x 16)
    const int qr = lane >> 2, qc = lane & 3;

    for (int c = 0; c < 9; c++) {
        if (c < 8) { asm volatile("cp.async.wait_group 1;" ::: "memory"); }
        else       { asm volatile("cp.async.wait_group 0;" ::: "memory"); }
        __syncthreads();

        const uint32_t pH = sb + QF_PROJ + (c & 1) * 9216;
        const uint32_t pL = pH + 4608;

        // ---- QP chunk = relu(q @ proj^T) + eps   (128 x 32)
        float accQ[2][2][4] = {};
        #pragma unroll
        for (int kt = 0; kt < 4; kt++) {
            uint32_t bh1[4], bl1[4];
            const int g = lane >> 3;
            const int brow = wcq * 16 + (lane & 7) + (g >> 1) * 8;
            const uint32_t bk = (uint32_t)(kt * 16 + (g & 1) * 8) * 2;
            ldsm4(bh1, pH + (uint32_t)brow * 144 + bk);
            ldsm4(bl1, pL + (uint32_t)brow * 144 + bk);
            const int arow = wrq * 32 + (lane & 15);
            const uint32_t ak = (uint32_t)(kt * 16 + (lane >> 4) * 8) * 2;
            #pragma unroll
            for (int mt = 0; mt < 2; mt++) {
                uint32_t ah[4], al[4];
                ldsm4(ah, sb + QF_SQH + (uint32_t)(arow + mt * 16) * 144 + ak);
                ldsm4(al, sb + QF_SQL + (uint32_t)(arow + mt * 16) * 144 + ak);
                #pragma unroll
                for (int nt = 0; nt < 2; nt++) {
                    mma16816(accQ[mt][nt], ah, &bh1[nt * 2]);
                    mma16816(accQ[mt][nt], ah, &bl1[nt * 2]);
                    mma16816(accQ[mt][nt], al, &bh1[nt * 2]);
                }
            }
        }
        // relu+eps, split h/l, store chunk to smem
        #pragma unroll
        for (int mt = 0; mt < 2; mt++)
            #pragma unroll
            for (int nt = 0; nt < 2; nt++) {
                int rcol = wcq * 16 + nt * 8 + qc * 2;
                #pragma unroll
                for (int hf = 0; hf < 2; hf++) {
                    int row = wrq * 32 + mt * 16 + qr + hf * 8;
                    float v0 = fmaxf(accQ[mt][nt][hf * 2 + 0], 0.0f) + EPSF;
                    float v1 = fmaxf(accQ[mt][nt][hf * 2 + 1], 0.0f) + EPSF;
                    __nv_bfloat16 h0, l0, h1, l1;
                    split2(v0, h0, l0);
                    split2(v1, h1, l1);
                    *(__nv_bfloat162*)(smem + QF_SQPH + row * 80 + rcol * 2)
                        = __nv_bfloat162{h0, h1};
                    *(__nv_bfloat162*)(smem + QF_SQPL + row * 80 + rcol * 2)
                        = __nv_bfloat162{l0, l1};
                }
            }
        __syncthreads();

        // dinv partial from QP chunk
        {
            const __nv_bfloat16* ph = (const __nv_bfloat16*)(smem + QF_SQPH
                                        + drow * 80 + dhalf * 32);
            const __nv_bfloat16* pl = (const __nv_bfloat16*)(smem + QF_SQPL
                                        + drow * 80 + dhalf * 32);
            const float* ksp = ksumS + c * 32 + dhalf * 16;
            #pragma unroll
            for (int kk = 0; kk < 16; kk++) {
                float v = __bfloat162float(ph[kk]) + __bfloat162float(pl[kk]);
                myd += v * ksp[kk];
            }
        }

        // ---- om += QP @ kvT^T
        const uint32_t aH = sb + QF_SQPH, aL = sb + QF_SQPL;
        const uint32_t bHc = sb + QF_KVT + (c & 1) * 10240;
        const uint32_t bLc = bHc + 5120;
        #pragma unroll
        for (int kt = 0; kt < 2; kt++) {
            uint32_t bh1[4], bl1[4];
            const int g = lane >> 3;
            const int brow = wc * 16 + (lane & 7) + (g >> 1) * 8;
            const uint32_t bk = (uint32_t)(kt * 16 + (g & 1) * 8) * 2;
            ldsm4(bh1, bHc + (uint32_t)brow * 80 + bk);
            ldsm4(bl1, bLc + (uint32_t)brow * 80 + bk);
            const int arow = wr * 64 + (lane & 15);
            const uint32_t ak = (uint32_t)(kt * 16 + (lane >> 4) * 8) * 2;
            #pragma unroll
            for (int mt = 0; mt < 4; mt++) {
                uint32_t ah[4], al[4];
                ldsm4(ah, aH + (uint32_t)(arow + mt * 16) * 80 + ak);
                ldsm4(al, aL + (uint32_t)(arow + mt * 16) * 80 + ak);
                #pragma unroll
                for (int nt = 0; nt < 2; nt++) {
                    mma16816(accO[mt][nt], ah, &bh1[nt * 2]);
                    mma16816(accO[mt][nt], ah, &bl1[nt * 2]);
                    mma16816(accO[mt][nt], al, &bh1[nt * 2]);
                }
            }
        }
        __syncthreads();
        if (c + 2 < 9) load_chunk(c + 2, c & 1);
    }

    dpart[dhalf][drow] = myd;
    __syncthreads();
    if (tid < 128) dinvS[tid] = 1.0f / (dpart[0][tid] + dpart[1][tid]);
    __syncthreads();

    #pragma unroll
    for (int mt = 0; mt < 4; mt++)
        #pragma unroll
        for (int nt = 0; nt < 2; nt++) {
            int d = wc * 16 + nt * 8 + qc * 2;
            #pragma unroll
            for (int hf = 0; hf < 2; hf++) {
                int lrow = wr * 64 + mt * 16 + qr + hf * 8;
                int nrow = n0 + lrow;
                float di = dinvS[lrow];
                float v0 = accO[mt][nt][hf * 2 + 0] * di;
                float v1 = accO[mt][nt][hf * 2 + 1] * di;
                __nv_bfloat16 h0, l0, h1, l1;
                split2(v0, h0, l0);
                split2(v1, h1, l1);
                size_t o = ((size_t)(b * NN + nrow)) * GK + h * 64 + d;
                *(__nv_bfloat162*)&g_omh[o] = __nv_bfloat162{h0, h1};
                *(__nv_bfloat162*)&g_oml[o] = __nv_bfloat162{l0, l1};
            }
        }
}

// ---------------- launch -----------------------------------------------------
extern "C" void kernel_launch(void* const* d_in, const int* in_sizes, int n_in,
                              void* d_out, int out_size)
{
    const float* x    = (const float*)d_in[0];
    const float* Wq   = (const float*)d_in[1];
    const float* Wk   = (const float*)d_in[2];
    const float* Wv   = (const float*)d_in[3];
    const float* Wo   = (const float*)d_in[4];
    const float* bo   = (const float*)d_in[5];
    const float* proj = (const float*)d_in[6];

    float* ksum;
    __nv_bfloat16 *xh, *xl, *omh, *oml, *wth, *wtl;
    cudaGetSymbolAddress((void**)&ksum, g_ksum);
    cudaGetSymbolAddress((void**)&xh,   g_xh);
    cudaGetSymbolAddress((void**)&xl,   g_xl);
    cudaGetSymbolAddress((void**)&omh,  g_omh);
    cudaGetSymbolAddress((void**)&oml,  g_oml);
    cudaGetSymbolAddress((void**)&wth,  g_wth);
    cudaGetSymbolAddress((void**)&wtl,  g_wtl);

    cudaFuncSetAttribute(gemm_hmma,
                         cudaFuncAttributeMaxDynamicSharedMemorySize, SMEM_DYN);
    cudaFuncSetAttribute(featmap_hmma,
                         cudaFuncAttributeMaxDynamicSharedMemorySize, FM_SMEM);
    cudaFuncSetAttribute(kv_hmma,
                         cudaFuncAttributeMaxDynamicSharedMemorySize, KV_SMEM);
    cudaFuncSetAttribute(qkv_fused,
                         cudaFuncAttributeMaxDynamicSharedMemorySize, QF_SMEM);

    const int n4 = GM * GK / 4;

    split_kernel<<<(n4 + 255) / 256, 256>>>(x, xh, xl, n4);
    wsplit_t<<<dim3(32, 32), dim3(32, 8)>>>(Wq, wth + 0 * (size_t)GN * GK, wtl + 0 * (size_t)GN * GK);
    wsplit_t<<<dim3(32, 32), dim3(32, 8)>>>(Wk, wth + 1 * (size_t)GN * GK, wtl + 1 * (size_t)GN * GK);
    wsplit_t<<<dim3(32, 32), dim3(32, 8)>>>(Wv, wth + 2 * (size_t)GN * GK, wtl + 2 * (size_t)GN * GK);
    wsplit_t<<<dim3(32, 32), dim3(32, 8)>>>(Wo, wth + 3 * (size_t)GN * GK, wtl + 3 * (size_t)GN * GK);
    psplit<<<80, 256>>>(proj);

    cudaMemsetAsync(ksum, 0, BHN * RP * sizeof(float));

    // merged Q/K/V GEMM over N = 3072 (bf16 h/l outputs)
    gemm_hmma<<<dim3(24, GM / 128), 256, SMEM_DYN>>>(xh, xl, wth, wtl,
                                                     nullptr, nullptr, 0);

    featmap_hmma<<<dim3(32, 64), 256, FM_SMEM>>>();    // kpT + ksum (k only)

    kv_hmma<<<dim3(BHN, 2, 2), 256, KV_SMEM>>>();      // kvacc partials

    kv_finalize<<<dim3(BHN, 5), 256>>>();              // kvT h/l

    qkv_fused<<<dim3(32, BHN), 256, QF_SMEM>>>();      // QP in smem + om + dinv

    gemm_hmma<<<dim3(8, GM / 128), 256, SMEM_DYN>>>(omh, oml,
        wth + 3 * (size_t)GN * GK, wtl + 3 * (size_t)GN * GK,
        bo, (float*)d_out, 1);
}

// round 13
// speedup vs baseline: 2.0570x; 1.0566x over previous
#include <cuda_runtime.h>
#include <cuda_bf16.h>
#include <cstdint>

#define BB 4
#define NN 4096
#define CC 1024
#define HH 16
#define DH 64
#define RR 266
#define RP 288
#define RT 320
#define EPSF 1e-3f
#define BHN (BB*HH)   // 64
#define GM (BB*NN)    // 16384
#define GK 1024
#define GN 1024
#define KC 32
#define NCH (GK/KC)        // 32 chunks
#define MAT_BYTES (128*80)
#define STAGE_BYTES (4*MAT_BYTES)  // 40960
#define SMEM_DYN (2*STAGE_BYTES)   // 81920 (epilogue staging reuses this)
// featmap smem: A h/l (2*128*144) + 2 proj slots + kpT staging (2*64*272)
#define FM_STG 73728
#define FM_SMEM (FM_STG + 2*64*272)   // 108544
// kv smem: A h/l (2*160*80) + B h/l (2*32*144)
#define KV_STAGE (2*160*80 + 2*32*144)   // 34816
#define KV_SMEM (2*KV_STAGE)             // 69632
// qkv_fused smem layout
#define QF_SQH  0
#define QF_SQL  18432
#define QF_SQPH 36864
#define QF_SQPL 47104
#define QF_PROJ 57344          // 2 slots x (4608 h + 4608 l)
#define QF_KVT  75776          // 2 slots x (5120 h + 5120 l)
#define QF_STH  57344          // om staging (reuses PROJ/KVT after loop)
#define QF_STL  75776
#define QF_SMEM 96256

// ---------------- scratch (device globals; no allocation allowed) ----------
__device__ float g_ksum[BHN*RP];
__device__ float g_kvacc[(size_t)2*BHN*RT*64];
__device__ __nv_bfloat16 g_xh[(size_t)GM*GK];
__device__ __nv_bfloat16 g_xl[(size_t)GM*GK];
__device__ __nv_bfloat16 g_qh[(size_t)GM*GK];
__device__ __nv_bfloat16 g_ql[(size_t)GM*GK];
__device__ __nv_bfloat16 g_kh[(size_t)GM*GK];
__device__ __nv_bfloat16 g_kl[(size_t)GM*GK];
__device__ __nv_bfloat16 g_vh[(size_t)GM*GK];
__device__ __nv_bfloat16 g_vl[(size_t)GM*GK];
__device__ __nv_bfloat16 g_omh[(size_t)GM*GK];
__device__ __nv_bfloat16 g_oml[(size_t)GM*GK];
__device__ __nv_bfloat16 g_wth[(size_t)4*GN*GK];
__device__ __nv_bfloat16 g_wtl[(size_t)4*GN*GK];
__device__ __nv_bfloat16 g_projh[RT*64];
__device__ __nv_bfloat16 g_projl[RT*64];
__device__ __nv_bfloat16 g_kpTh[(size_t)BHN*RT*NN];
__device__ __nv_bfloat16 g_kpTl[(size_t)BHN*RT*NN];
__device__ __nv_bfloat16 g_kvTh[BHN*64*RP];
__device__ __nv_bfloat16 g_kvTl[BHN*64*RP];

// ---------------- helpers ----------------------------------------------------
__device__ __forceinline__ uint32_t smem_u32(const void* p) {
    uint32_t a;
    asm("{ .reg .u64 t; cvta.to.shared.u64 t, %1; cvt.u32.u64 %0, t; }"
        : "=r"(a) : "l"(p));
    return a;
}
__device__ __forceinline__ void cpa16(uint32_t dst, const void* src) {
    asm volatile("cp.async.cg.shared.global [%0], [%1], 16;" :: "r"(dst), "l"(src));
}
__device__ __forceinline__ void ldsm4(uint32_t* r, uint32_t addr) {
    asm volatile("ldmatrix.sync.aligned.m8n8.x4.shared.b16 {%0,%1,%2,%3}, [%4];"
        : "=r"(r[0]), "=r"(r[1]), "=r"(r[2]), "=r"(r[3]) : "r"(addr));
}
__device__ __forceinline__ void ldsm4t(uint32_t* r, uint32_t addr) {
    asm volatile("ldmatrix.sync.aligned.m8n8.x4.trans.shared.b16 {%0,%1,%2,%3}, [%4];"
        : "=r"(r[0]), "=r"(r[1]), "=r"(r[2]), "=r"(r[3]) : "r"(addr));
}
__device__ __forceinline__ void mma16816(float* d, const uint32_t* a, const uint32_t* b) {
    asm volatile(
        "mma.sync.aligned.m16n8k16.row.col.f32.bf16.bf16.f32 "
        "{%0,%1,%2,%3}, {%4,%5,%6,%7}, {%8,%9}, {%0,%1,%2,%3};"
        : "+f"(d[0]), "+f"(d[1]), "+f"(d[2]), "+f"(d[3])
        : "r"(a[0]), "r"(a[1]), "r"(a[2]), "r"(a[3]), "r"(b[0]), "r"(b[1]));
}
__device__ __forceinline__ void split2(float v, __nv_bfloat16& h, __nv_bfloat16& l) {
    h = __float2bfloat16(v);
    l = __float2bfloat16(v - __bfloat162float(h));
}

// ---------------- HMMA split-bf16 GEMM, 2-stage, 2 CTAs/SM -------------------
__global__ __launch_bounds__(256, 2) void gemm_hmma(
    const __nv_bfloat16* __restrict__ Ah, const __nv_bfloat16* __restrict__ Al,
    const __nv_bfloat16* __restrict__ Bh, const __nv_bfloat16* __restrict__ Bl,
    const float* __restrict__ bias, float* __restrict__ Cf, int mode)
{
    extern __shared__ char smem[];
    const int tid = threadIdx.x;
    const int wid = tid >> 5, lane = tid & 31;
    const int m0 = blockIdx.y * 128, n0 = blockIdx.x * 128;
    const int wr = wid >> 2, wc = wid & 3;

    const __nv_bfloat16* gsrc0 = Ah + (size_t)m0 * GK;
    const __nv_bfloat16* gsrc1 = Al + (size_t)m0 * GK;
    const __nv_bfloat16* gsrc2 = Bh + (size_t)n0 * GK;
    const __nv_bfloat16* gsrc3 = Bl + (size_t)n0 * GK;

    float acc[4][4][4] = {};

    auto load_stage = [&](int c, int st) {
        const int k0 = c * KC;
        char* dstb = smem + st * STAGE_BYTES;
        #pragma unroll
        for (int i = 0; i < 8; i++) {
            int idx = tid + i * 256;
            int mat = idx >> 9;
            int row = (idx >> 2) & 127;
            int c16 = idx & 3;
            uint32_t dst = smem_u32(dstb + mat * MAT_BYTES + row * 80 + c16 * 16);
            const __nv_bfloat16* g =
                (mat == 0) ? gsrc0 : (mat == 1) ? gsrc1 : (mat == 2) ? gsrc2 : gsrc3;
            cpa16(dst, g + (size_t)row * GK + k0 + c16 * 8);
        }
        asm volatile("cp.async.commit_group;" ::: "memory");
    };

    load_stage(0, 0);

    for (int c = 0; c < NCH; c++) {
        if (c + 1 < NCH) {
            load_stage(c + 1, (c + 1) & 1);
            asm volatile("cp.async.wait_group 1;" ::: "memory");
        } else {
            asm volatile("cp.async.wait_group 0;" ::: "memory");
        }
        __syncthreads();

        const int st = c & 1;
        const uint32_t aH = smem_u32(smem + st * STAGE_BYTES);
        const uint32_t aL = aH + MAT_BYTES;
        const uint32_t bH = aH + 2 * MAT_BYTES;
        const uint32_t bL = aH + 3 * MAT_BYTES;

        #pragma unroll
        for (int kt = 0; kt < 2; kt++) {
            uint32_t bh[2][4], bl[2][4];
            const int g = lane >> 3;
            const int brow = wc * 32 + (lane & 7) + (g >> 1) * 8;
            const uint32_t bkoff = (uint32_t)(kt * 16 + (g & 1) * 8) * 2;
            #pragma unroll
            for (int nt2 = 0; nt2 < 2; nt2++) {
                ldsm4(bh[nt2], bH + (uint32_t)(brow + nt2 * 16) * 80 + bkoff);
                ldsm4(bl[nt2], bL + (uint32_t)(brow + nt2 * 16) * 80 + bkoff);
            }
            const int arow = wr * 64 + (lane & 15);
            const uint32_t akoff = (uint32_t)(kt * 16 + (lane >> 4) * 8) * 2;
            #pragma unroll
            for (int mt = 0; mt < 4; mt++) {
                uint32_t ah[4], al[4];
                ldsm4(ah, aH + (uint32_t)(arow + mt * 16) * 80 + akoff);
                ldsm4(al, aL + (uint32_t)(arow + mt * 16) * 80 + akoff);
                #pragma unroll
                for (int nt = 0; nt < 4; nt++) {
                    const uint32_t* bhp = &bh[nt >> 1][(nt & 1) * 2];
                    const uint32_t* blp = &bl[nt >> 1][(nt & 1) * 2];
                    mma16816(acc[mt][nt], ah, bhp);
                    mma16816(acc[mt][nt], ah, blp);
                    mma16816(acc[mt][nt], al, bhp);
                }
            }
        }
        __syncthreads();
    }

    const int qr = lane >> 2, qc = lane & 3;
    if (mode == 1) {
        #pragma unroll
        for (int mt = 0; mt < 4; mt++)
            #pragma unroll
            for (int nt = 0; nt < 4; nt++) {
                int row = m0 + wr * 64 + mt * 16 + qr;
                int col = n0 + wc * 32 + nt * 8 + qc * 2;
                float bx = bias[col], by = bias[col + 1];
                float2 v0 = {acc[mt][nt][0] + bx, acc[mt][nt][1] + by};
                float2 v1 = {acc[mt][nt][2] + bx, acc[mt][nt][3] + by};
                *(float2*)&Cf[(size_t)row * GN + col] = v0;
                *(float2*)&Cf[(size_t)(row + 8) * GN + col] = v1;
            }
    } else {
        __nv_bfloat16 *och, *ocl;
        int cbase;
        if (n0 < 1024)      { och = g_qh; ocl = g_ql; cbase = n0; }
        else if (n0 < 2048) { och = g_kh; ocl = g_kl; cbase = n0 - 1024; }
        else                { och = g_vh; ocl = g_vl; cbase = n0 - 2048; }
        // stage h/l tiles in smem (pitch 272) then coalesced float4 stores
        #pragma unroll
        for (int mt = 0; mt < 4; mt++)
            #pragma unroll
            for (int nt = 0; nt < 4; nt++) {
                int coll = wc * 32 + nt * 8 + qc * 2;
                #pragma unroll
                for (int hf = 0; hf < 2; hf++) {
                    int rowl = wr * 64 + mt * 16 + qr + hf * 8;
                    __nv_bfloat16 h0, l0, h1, l1;
                    split2(acc[mt][nt][hf * 2 + 0], h0, l0);
                    split2(acc[mt][nt][hf * 2 + 1], h1, l1);
                    *(__nv_bfloat162*)(smem + rowl * 272 + coll * 2)
                        = __nv_bfloat162{h0, h1};
                    *(__nv_bfloat162*)(smem + 34816 + rowl * 272 + coll * 2)
                        = __nv_bfloat162{l0, l1};
                }
            }
        __syncthreads();
        #pragma unroll
        for (int j = 0; j < 8; j++) {
            int idx = tid + j * 256;
            int rr = idx >> 4, c16 = idx & 15;
            float4 vh = *(float4*)(smem + rr * 272 + c16 * 16);
            float4 vl = *(float4*)(smem + 34816 + rr * 272 + c16 * 16);
            *(float4*)&och[(size_t)(m0 + rr) * GN + cbase + c16 * 8] = vh;
            *(float4*)&ocl[(size_t)(m0 + rr) * GN + cbase + c16 * 8] = vl;
        }
    }
}

// ---------------- fp32 -> bf16 hi/lo split (x only) --------------------------
__global__ __launch_bounds__(256) void split_kernel(
    const float* __restrict__ in, __nv_bfloat16* __restrict__ hi,
    __nv_bfloat16* __restrict__ lo, int n4)
{
    int i = blockIdx.x * blockDim.x + threadIdx.x;
    if (i >= n4) return;
    float4 v = ((const float4*)in)[i];
    float vv[4] = {v.x, v.y, v.z, v.w};
    __nv_bfloat16 h[4], l[4];
    #pragma unroll
    for (int j = 0; j < 4; j++) split2(vv[j], h[j], l[j]);
    ((__nv_bfloat162*)hi)[2*i+0] = __nv_bfloat162{h[0], h[1]};
    ((__nv_bfloat162*)hi)[2*i+1] = __nv_bfloat162{h[2], h[3]};
    ((__nv_bfloat162*)lo)[2*i+0] = __nv_bfloat162{l[0], l[1]};
    ((__nv_bfloat162*)lo)[2*i+1] = __nv_bfloat162{l[2], l[3]};
}

// ---------------- transpose + split weights: W[K][N] -> Wt hi/lo [N][K] -----
__global__ void wsplit_t(const float* __restrict__ W,
                         __nv_bfloat16* __restrict__ th,
                         __nv_bfloat16* __restrict__ tl)
{
    __shared__ float t[32][33];
    const int k0 = blockIdx.y * 32, n0 = blockIdx.x * 32;
    for (int i = threadIdx.y; i < 32; i += 8)
        t[i][threadIdx.x] = W[(size_t)(k0 + i) * GN + n0 + threadIdx.x];
    __syncthreads();
    for (int i = threadIdx.y; i < 32; i += 8) {
        float v = t[threadIdx.x][i];
        __nv_bfloat16 h, l;
        split2(v, h, l);
        size_t o = (size_t)(n0 + i) * GK + k0 + threadIdx.x;
        th[o] = h;
        tl[o] = l;
    }
}

// ---------------- proj split (padded to RT rows, zero fill) ------------------
__global__ void psplit(const float* __restrict__ proj)
{
    int i = blockIdx.x * 256 + threadIdx.x;
    if (i >= RT * 64) return;
    int r = i >> 6, d = i & 63;
    float v = (r < RR) ? proj[r * 64 + d] : 0.0f;
    __nv_bfloat16 h, l;
    split2(v, h, l);
    g_projh[i] = h;
    g_projl[i] = l;
}

// ---------------- featmap HMMA (k only): kpT + ksum, staged stores -----------
// grid (32 n0, 64 bh), 256 threads, dyn smem FM_SMEM
__global__ __launch_bounds__(256, 2) void featmap_hmma()
{
    extern __shared__ char smem[];
    const int tid = threadIdx.x, wid = tid >> 5, lane = tid & 31;
    const int n0 = blockIdx.x * 128;
    const int bh = blockIdx.y;
    const int b = bh >> 4, h = bh & 15;
    const size_t abase = ((size_t)(b * NN + n0)) * GK + h * 64;

    const uint32_t sA_h = smem_u32(smem);
    const uint32_t sA_l = sA_h + 128 * 144;
    const uint32_t sP   = sA_h + 2 * 128 * 144;

    auto load_proj = [&](int r0i, int slot) {
        #pragma unroll
        for (int i = 0; i < 4; i++) {
            int idx = tid + i * 256;
            int row = (idx & 511) >> 3, c = idx & 7;
            uint32_t dst = sP + slot * 18432 + (idx < 512 ? 0 : 9216)
                         + row * 144 + c * 16;
            const __nv_bfloat16* src = (idx < 512 ? g_projh : g_projl)
                                       + (r0i * 64 + row) * 64 + c * 8;
            cpa16(dst, src);
        }
        asm volatile("cp.async.commit_group;" ::: "memory");
    };

    #pragma unroll
    for (int i = 0; i < 8; i++) {
        int idx = tid + i * 256;
        int row = (idx & 1023) >> 3, c = idx & 7;
        uint32_t dst = (idx < 1024 ? sA_h : sA_l) + row * 144 + c * 16;
        const __nv_bfloat16* src = (idx < 1024 ? g_kh : g_kl) + abase
                                   + (size_t)row * GK + c * 8;
        cpa16(dst, src);
    }
    load_proj(0, 0);
    load_proj(1, 1);

    const int wr = wid >> 2, wc = wid & 3;
    const int qr = lane >> 2, qc = lane & 3;

    for (int r0i = 0; r0i < 5; r0i++) {
        if (r0i < 4) { asm volatile("cp.async.wait_group 1;" ::: "memory"); }
        else         { asm volatile("cp.async.wait_group 0;" ::: "memory"); }
        __syncthreads();

        const uint32_t pH = sP + (r0i & 1) * 18432;
        const uint32_t pL = pH + 9216;

        float acc[4][2][4] = {};
        #pragma unroll
        for (int kt = 0; kt < 4; kt++) {
            uint32_t bh1[4], bl1[4];
            const int g = lane >> 3;
            const int brow = wc * 16 + (lane & 7) + (g >> 1) * 8;
            const uint32_t bk = (uint32_t)(kt * 16 + (g & 1) * 8) * 2;
            ldsm4(bh1, pH + (uint32_t)brow * 144 + bk);
            ldsm4(bl1, pL + (uint32_t)brow * 144 + bk);
            const int arow = wr * 64 + (lane & 15);
            const uint32_t ak = (uint32_t)(kt * 16 + (lane >> 4) * 8) * 2;
            #pragma unroll
            for (int mt = 0; mt < 4; mt++) {
                uint32_t ah[4], al[4];
                ldsm4(ah, sA_h + (uint32_t)(arow + mt * 16) * 144 + ak);
                ldsm4(al, sA_l + (uint32_t)(arow + mt * 16) * 144 + ak);
                #pragma unroll
                for (int nt = 0; nt < 2; nt++) {
                    mma16816(acc[mt][nt], ah, &bh1[nt * 2]);
                    mma16816(acc[mt][nt], ah, &bl1[nt * 2]);
                    mma16816(acc[mt][nt], al, &bh1[nt * 2]);
                }
            }
        }
        __syncthreads();
        if (r0i + 2 < 5) load_proj(r0i + 2, r0i & 1);

        // ---- epilogue: stage kp chunk [64r][128n] h/l in smem + ksum
        #pragma unroll
        for (int nt = 0; nt < 2; nt++) {
            int rloc = wc * 16 + nt * 8 + qc * 2;
            int rglob = r0i * 64 + rloc;
            bool valid = (rglob < RR);
            float s0 = 0.f, s1 = 0.f;
            #pragma unroll
            for (int mt = 0; mt < 4; mt++)
                #pragma unroll
                for (int hf = 0; hf < 2; hf++) {
                    int nloc = wr * 64 + mt * 16 + qr + hf * 8;
                    float v0 = acc[mt][nt][hf * 2 + 0];
                    float v1 = acc[mt][nt][hf * 2 + 1];
                    v0 = valid ? (fmaxf(v0, 0.0f) + EPSF) : 0.0f;
                    v1 = valid ? (fmaxf(v1, 0.0f) + EPSF) : 0.0f;
                    __nv_bfloat16 h0, l0, h1, l1;
                    split2(v0, h0, l0);
                    split2(v1, h1, l1);
                    *(__nv_bfloat16*)(smem + FM_STG + rloc * 272 + nloc * 2) = h0;
                    *(__nv_bfloat16*)(smem + FM_STG + (rloc + 1) * 272 + nloc * 2) = h1;
                    *(__nv_bfloat16*)(smem + FM_STG + 17408 + rloc * 272 + nloc * 2) = l0;
                    *(__nv_bfloat16*)(smem + FM_STG + 17408 + (rloc + 1) * 272 + nloc * 2) = l1;
                    s0 += v0;
                    s1 += v1;
                }
            if (valid) {
                atomicAdd(&g_ksum[bh * RP + rglob], s0);
                atomicAdd(&g_ksum[bh * RP + rglob + 1], s1);
            }
        }
        __syncthreads();

        const size_t kb = (size_t)bh * RT * NN;
        #pragma unroll
        for (int j = 0; j < 4; j++) {
            int idx = tid + j * 256;
            int rr = idx >> 4, c16 = idx & 15;
            float4 vh = *(float4*)(smem + FM_STG + rr * 272 + c16 * 16);
            float4 vl = *(float4*)(smem + FM_STG + 17408 + rr * 272 + c16 * 16);
            size_t o = kb + (size_t)(r0i * 64 + rr) * NN + n0 + c16 * 8;
            *(float4*)&g_kpTh[o] = vh;
            *(float4*)&g_kpTl[o] = vl;
        }
    }
}

// ---------------- kv HMMA: kvacc[khalf][bh][r][d] = kpT @ v ------------------
__global__ __launch_bounds__(256, 2) void kv_hmma()
{
    extern __shared__ char smem[];
    const int tid = threadIdx.x, wid = tid >> 5, lane = tid & 31;
    const int bh = blockIdx.x, rhalf = blockIdx.y, khalf = blockIdx.z;
    const int b = bh >> 4, h = bh & 15;

    const __nv_bfloat16* __restrict__ Ahb =
        g_kpTh + ((size_t)bh * RT + rhalf * 160) * NN + khalf * 2048;
    const __nv_bfloat16* __restrict__ Alb =
        g_kpTl + ((size_t)bh * RT + rhalf * 160) * NN + khalf * 2048;
    const __nv_bfloat16* __restrict__ Bhb =
        g_vh + ((size_t)(b * NN + khalf * 2048)) * GK + h * 64;
    const __nv_bfloat16* __restrict__ Blb =
        g_vl + ((size_t)(b * NN + khalf * 2048)) * GK + h * 64;

    const int wm = wid >> 2, wn = wid & 3;
    float acc[5][2][4] = {};

    auto load_stage = [&](int c, int st) {
        const int k0 = c * 32;
        char* sb = smem + st * KV_STAGE;
        #pragma unroll
        for (int i = 0; i < 7; i++) {
            int idx = tid + i * 256;
            uint32_t dst;
            const __nv_bfloat16* src;
            if (idx < 640) {
                int row = idx >> 2, cc = idx & 3;
                dst = smem_u32(sb + row * 80 + cc * 16);
                src = Ahb + (size_t)row * NN + k0 + cc * 8;
            } else if (idx < 1280) {
                int j = idx - 640; int row = j >> 2, cc = j & 3;
                dst = smem_u32(sb + 12800 + row * 80 + cc * 16);
                src = Alb + (size_t)row * NN + k0 + cc * 8;
            } else if (idx < 1536) {
                int j = idx - 1280; int row = j >> 3, cc = j & 7;
                dst = smem_u32(sb + 25600 + row * 144 + cc * 16);
                src = Bhb + (size_t)(k0 + row) * GK + cc * 8;
            } else {
                int j = idx - 1536; int row = j >> 3, cc = j & 7;
                dst = smem_u32(sb + 25600 + 4608 + row * 144 + cc * 16);
                src = Blb + (size_t)(k0 + row) * GK + cc * 8;
            }
            cpa16(dst, src);
        }
        asm volatile("cp.async.commit_group;" ::: "memory");
    };

    load_stage(0, 0);

    for (int c = 0; c < 64; c++) {
        if (c + 1 < 64) {
            load_stage(c + 1, (c + 1) & 1);
            asm volatile("cp.async.wait_group 1;" ::: "memory");
        } else {
            asm volatile("cp.async.wait_group 0;" ::: "memory");
        }
        __syncthreads();

        const int st = c & 1;
        const uint32_t aH = smem_u32(smem + st * KV_STAGE);
        const uint32_t aL = aH + 12800;
        const uint32_t bHs = aH + 25600;
        const uint32_t bLs = bHs + 4608;

        #pragma unroll
        for (int kt = 0; kt < 2; kt++) {
            uint32_t bhf[4], blf[4];
            const int g = lane >> 3;
            const int browk = kt * 16 + (g & 1) * 8 + (lane & 7);
            const uint32_t bc = (uint32_t)(wn * 16 + (g >> 1) * 8) * 2;
            ldsm4t(bhf, bHs + (uint32_t)browk * 144 + bc);
            ldsm4t(blf, bLs + (uint32_t)browk * 144 + bc);
            const int arow = wm * 80 + (lane & 15);
            const uint32_t ak = (uint32_t)(kt * 16 + (lane >> 4) * 8) * 2;
            #pragma unroll
            for (int mt = 0; mt < 5; mt++) {
                uint32_t ah[4], al[4];
                ldsm4(ah, aH + (uint32_t)(arow + mt * 16) * 80 + ak);
                ldsm4(al, aL + (uint32_t)(arow + mt * 16) * 80 + ak);
                #pragma unroll
                for (int nt = 0; nt < 2; nt++) {
                    mma16816(acc[mt][nt], ah, &bhf[nt * 2]);
                    mma16816(acc[mt][nt], ah, &blf[nt * 2]);
                    mma16816(acc[mt][nt], al, &bhf[nt * 2]);
                }
            }
        }
        __syncthreads();
    }

    const int qr = lane >> 2, qc = lane & 3;
    float* outp = g_kvacc + ((size_t)(khalf * BHN + bh)) * RT * 64;
    #pragma unroll
    for (int mt = 0; mt < 5; mt++)
        #pragma unroll
        for (int nt = 0; nt < 2; nt++) {
            int r = rhalf * 160 + wm * 80 + mt * 16 + qr;
            int d = wn * 16 + nt * 8 + qc * 2;
            #pragma unroll
            for (int hf = 0; hf < 2; hf++) {
                float2 v = {acc[mt][nt][hf * 2 + 0], acc[mt][nt][hf * 2 + 1]};
                *(float2*)&outp[(size_t)(r + hf * 8) * 64 + d] = v;
            }
        }
}

// ---------------- kv finalize: sum khalves, transpose -> kvT[d][r] h/l -------
__global__ void kv_finalize()
{
    __shared__ float t[64][65];
    const int bh = blockIdx.x, rblk = blockIdx.y;
    const int tid = threadIdx.x;
    const float* a0 = g_kvacc + ((size_t)bh * RT + rblk * 64) * 64;
    const float* a1 = g_kvacc + ((size_t)(BHN + bh) * RT + rblk * 64) * 64;
    #pragma unroll
    for (int i = 0; i < 16; i++) {
        int e = tid + i * 256;
        t[e >> 6][e & 63] = a0[e] + a1[e];
    }
    __syncthreads();
    const int d = tid >> 2, rs = (tid & 3) * 16;
    const size_t ob = ((size_t)bh * 64 + d) * RP;
    #pragma unroll
    for (int j = 0; j < 16; j += 2) {
        int rg = rblk * 64 + rs + j;
        if (rg >= RP) break;
        __nv_bfloat16 h0, l0, h1, l1;
        split2(t[rs + j][d], h0, l0);
        split2(t[rs + j + 1][d], h1, l1);
        *(__nv_bfloat162*)&g_kvTh[ob + rg] = __nv_bfloat162{h0, h1};
        *(__nv_bfloat162*)&g_kvTl[ob + rg] = __nv_bfloat162{l0, l1};
    }
}

// ---------------- qkv_fused: QP in smem, om = QP@kvT*dinv, staged stores -----
// grid (32 n0, 64 bh), 256 threads, dyn smem QF_SMEM
__global__ __launch_bounds__(256, 2) void qkv_fused()
{
    extern __shared__ char smem[];
    __shared__ float ksumS[RP];
    __shared__ float dpart[2][128];
    __shared__ float dinvS[128];
    const int tid = threadIdx.x, wid = tid >> 5, lane = tid & 31;
    const int n0 = blockIdx.x * 128;
    const int bh = blockIdx.y;
    const int b = bh >> 4, h = bh & 15;
    const uint32_t sb = smem_u32(smem);

    const size_t qbase = ((size_t)(b * NN + n0)) * GK + h * 64;
    const __nv_bfloat16* __restrict__ Bhg = g_kvTh + (size_t)bh * 64 * RP;
    const __nv_bfloat16* __restrict__ Blg = g_kvTl + (size_t)bh * 64 * RP;

    for (int i = tid; i < RP; i += 256) ksumS[i] = g_ksum[bh * RP + i];

    #pragma unroll
    for (int i = 0; i < 8; i++) {
        int idx = tid + i * 256;
        int row = (idx & 1023) >> 3, c = idx & 7;
        uint32_t dst = sb + (idx < 1024 ? QF_SQH : QF_SQL) + row * 144 + c * 16;
        const __nv_bfloat16* src = (idx < 1024 ? g_qh : g_ql) + qbase
                                   + (size_t)row * GK + c * 8;
        cpa16(dst, src);
    }

    auto load_chunk = [&](int c, int slot) {
        #pragma unroll
        for (int i = 0; i < 2; i++) {
            int idx = tid + i * 256;
            int row = (idx & 255) >> 3, cc = idx & 7;
            uint32_t dst = sb + QF_PROJ + slot * 9216 + (idx < 256 ? 0 : 4608)
                         + row * 144 + cc * 16;
            const __nv_bfloat16* src = (idx < 256 ? g_projh : g_projl)
                                       + (c * 32 + row) * 64 + cc * 8;
            cpa16(dst, src);
        }
        #pragma unroll
        for (int i = 0; i < 2; i++) {
            int idx = tid + i * 256;
            int row = (idx & 255) >> 2, cc = idx & 3;
            uint32_t dst = sb + QF_KVT + slot * 10240 + (idx < 256 ? 0 : 5120)
                         + row * 80 + cc * 16;
            const __nv_bfloat16* src = (idx < 256 ? Bhg : Blg)
                                       + (size_t)row * RP + c * 32 + cc * 8;
            cpa16(dst, src);
        }
        asm volatile("cp.async.commit_group;" ::: "memory");
    };

    load_chunk(0, 0);
    load_chunk(1, 1);

    float accO[4][2][4] = {};
    float myd = 0.f;
    const int drow = tid & 127, dhalf = tid >> 7;
    const int wrq = wid >> 1, wcq = wid & 1;
    const int wr = wid >> 2, wc = wid & 3;
    const int qr = lane >> 2, qc = lane & 3;

    for (int c = 0; c < 9; c++) {
        if (c < 8) { asm volatile("cp.async.wait_group 1;" ::: "memory"); }
        else       { asm volatile("cp.async.wait_group 0;" ::: "memory"); }
        __syncthreads();

        const uint32_t pH = sb + QF_PROJ + (c & 1) * 9216;
        const uint32_t pL = pH + 4608;

        float accQ[2][2][4] = {};
        #pragma unroll
        for (int kt = 0; kt < 4; kt++) {
            uint32_t bh1[4], bl1[4];
            const int g = lane >> 3;
            const int brow = wcq * 16 + (lane & 7) + (g >> 1) * 8;
            const uint32_t bk = (uint32_t)(kt * 16 + (g & 1) * 8) * 2;
            ldsm4(bh1, pH + (uint32_t)brow * 144 + bk);
            ldsm4(bl1, pL + (uint32_t)brow * 144 + bk);
            const int arow = wrq * 32 + (lane & 15);
            const uint32_t ak = (uint32_t)(kt * 16 + (lane >> 4) * 8) * 2;
            #pragma unroll
            for (int mt = 0; mt < 2; mt++) {
                uint32_t ah[4], al[4];
                ldsm4(ah, sb + QF_SQH + (uint32_t)(arow + mt * 16) * 144 + ak);
                ldsm4(al, sb + QF_SQL + (uint32_t)(arow + mt * 16) * 144 + ak);
                #pragma unroll
                for (int nt = 0; nt < 2; nt++) {
                    mma16816(accQ[mt][nt], ah, &bh1[nt * 2]);
                    mma16816(accQ[mt][nt], ah, &bl1[nt * 2]);
                    mma16816(accQ[mt][nt], al, &bh1[nt * 2]);
                }
            }
        }
        #pragma unroll
        for (int mt = 0; mt < 2; mt++)
            #pragma unroll
            for (int nt = 0; nt < 2; nt++) {
                int rcol = wcq * 16 + nt * 8 + qc * 2;
                #pragma unroll
                for (int hf = 0; hf < 2; hf++) {
                    int row = wrq * 32 + mt * 16 + qr + hf * 8;
                    float v0 = fmaxf(accQ[mt][nt][hf * 2 + 0], 0.0f) + EPSF;
                    float v1 = fmaxf(accQ[mt][nt][hf * 2 + 1], 0.0f) + EPSF;
                    __nv_bfloat16 h0, l0, h1, l1;
                    split2(v0, h0, l0);
                    split2(v1, h1, l1);
                    *(__nv_bfloat162*)(smem + QF_SQPH + row * 80 + rcol * 2)
                        = __nv_bfloat162{h0, h1};
                    *(__nv_bfloat162*)(smem + QF_SQPL + row * 80 + rcol * 2)
                        = __nv_bfloat162{l0, l1};
                }
            }
        __syncthreads();

        {
            const __nv_bfloat16* ph = (const __nv_bfloat16*)(smem + QF_SQPH
                                        + drow * 80 + dhalf * 32);
            const __nv_bfloat16* pl = (const __nv_bfloat16*)(smem + QF_SQPL
                                        + drow * 80 + dhalf * 32);
            const float* ksp = ksumS + c * 32 + dhalf * 16;
            #pragma unroll
            for (int kk = 0; kk < 16; kk++) {
                float v = __bfloat162float(ph[kk]) + __bfloat162float(pl[kk]);
                myd += v * ksp[kk];
            }
        }

        const uint32_t aH = sb + QF_SQPH, aL = sb + QF_SQPL;
        const uint32_t bHc = sb + QF_KVT + (c & 1) * 10240;
        const uint32_t bLc = bHc + 5120;
        #pragma unroll
        for (int kt = 0; kt < 2; kt++) {
            uint32_t bh1[4], bl1[4];
            const int g = lane >> 3;
            const int brow = wc * 16 + (lane & 7) + (g >> 1) * 8;
            const uint32_t bk = (uint32_t)(kt * 16 + (g & 1) * 8) * 2;
            ldsm4(bh1, bHc + (uint32_t)brow * 80 + bk);
            ldsm4(bl1, bLc + (uint32_t)brow * 80 + bk);
            const int arow = wr * 64 + (lane & 15);
            const uint32_t ak = (uint32_t)(kt * 16 + (lane >> 4) * 8) * 2;
            #pragma unroll
            for (int mt = 0; mt < 4; mt++) {
                uint32_t ah[4], al[4];
                ldsm4(ah, aH + (uint32_t)(arow + mt * 16) * 80 + ak);
                ldsm4(al, aL + (uint32_t)(arow + mt * 16) * 80 + ak);
                #pragma unroll
                for (int nt = 0; nt < 2; nt++) {
                    mma16816(accO[mt][nt], ah, &bh1[nt * 2]);
                    mma16816(accO[mt][nt], ah, &bl1[nt * 2]);
                    mma16816(accO[mt][nt], al, &bh1[nt * 2]);
                }
            }
        }
        __syncthreads();
        if (c + 2 < 9) load_chunk(c + 2, c & 1);
    }

    dpart[dhalf][drow] = myd;
    __syncthreads();
    if (tid < 128) dinvS[tid] = 1.0f / (dpart[0][tid] + dpart[1][tid]);
    __syncthreads();

    // ---- staged om epilogue: [128 n][64 d] h/l at pitch 144, then float4 out
    #pragma unroll
    for (int mt = 0; mt < 4; mt++)
        #pragma unroll
        for (int nt = 0; nt < 2; nt++) {
            int d = wc * 16 + nt * 8 + qc * 2;
            #pragma unroll
            for (int hf = 0; hf < 2; hf++) {
                int lrow = wr * 64 + mt * 16 + qr + hf * 8;
                float di = dinvS[lrow];
                float v0 = accO[mt][nt][hf * 2 + 0] * di;
                float v1 = accO[mt][nt][hf * 2 + 1] * di;
                __nv_bfloat16 h0, l0, h1, l1;
                split2(v0, h0, l0);
                split2(v1, h1, l1);
                *(__nv_bfloat162*)(smem + QF_STH + lrow * 144 + d * 2)
                    = __nv_bfloat162{h0, h1};
                *(__nv_bfloat162*)(smem + QF_STL + lrow * 144 + d * 2)
                    = __nv_bfloat162{l0, l1};
            }
        }
    __syncthreads();
    #pragma unroll
    for (int j = 0; j < 4; j++) {
        int idx = tid + j * 256;
        int rr = idx >> 3, c16 = idx & 7;
        float4 vh = *(float4*)(smem + QF_STH + rr * 144 + c16 * 16);
        float4 vl = *(float4*)(smem + QF_STL + rr * 144 + c16 * 16);
        size_t o = ((size_t)(b * NN + n0 + rr)) * GK + h * 64 + c16 * 8;
        *(float4*)&g_omh[o] = vh;
        *(float4*)&g_oml[o] = vl;
    }
}

// ---------------- launch -----------------------------------------------------
extern "C" void kernel_launch(void* const* d_in, const int* in_sizes, int n_in,
                              void* d_out, int out_size)
{
    const float* x    = (const float*)d_in[0];
    const float* Wq   = (const float*)d_in[1];
    const float* Wk   = (const float*)d_in[2];
    const float* Wv   = (const float*)d_in[3];
    const float* Wo   = (const float*)d_in[4];
    const float* bo   = (const float*)d_in[5];
    const float* proj = (const float*)d_in[6];

    float* ksum;
    __nv_bfloat16 *xh, *xl, *omh, *oml, *wth, *wtl;
    cudaGetSymbolAddress((void**)&ksum, g_ksum);
    cudaGetSymbolAddress((void**)&xh,   g_xh);
    cudaGetSymbolAddress((void**)&xl,   g_xl);
    cudaGetSymbolAddress((void**)&omh,  g_omh);
    cudaGetSymbolAddress((void**)&oml,  g_oml);
    cudaGetSymbolAddress((void**)&wth,  g_wth);
    cudaGetSymbolAddress((void**)&wtl,  g_wtl);

    cudaFuncSetAttribute(gemm_hmma,
                         cudaFuncAttributeMaxDynamicSharedMemorySize, SMEM_DYN);
    cudaFuncSetAttribute(featmap_hmma,
                         cudaFuncAttributeMaxDynamicSharedMemorySize, FM_SMEM);
    cudaFuncSetAttribute(kv_hmma,
                         cudaFuncAttributeMaxDynamicSharedMemorySize, KV_SMEM);
    cudaFuncSetAttribute(qkv_fused,
                         cudaFuncAttributeMaxDynamicSharedMemorySize, QF_SMEM);

    const int n4 = GM * GK / 4;

    split_kernel<<<(n4 + 255) / 256, 256>>>(x, xh, xl, n4);
    wsplit_t<<<dim3(32, 32), dim3(32, 8)>>>(Wq, wth + 0 * (size_t)GN * GK, wtl + 0 * (size_t)GN * GK);
    wsplit_t<<<dim3(32, 32), dim3(32, 8)>>>(Wk, wth + 1 * (size_t)GN * GK, wtl + 1 * (size_t)GN * GK);
    wsplit_t<<<dim3(32, 32), dim3(32, 8)>>>(Wv, wth + 2 * (size_t)GN * GK, wtl + 2 * (size_t)GN * GK);
    wsplit_t<<<dim3(32, 32), dim3(32, 8)>>>(Wo, wth + 3 * (size_t)GN * GK, wtl + 3 * (size_t)GN * GK);
    psplit<<<80, 256>>>(proj);

    cudaMemsetAsync(ksum, 0, BHN * RP * sizeof(float));

    gemm_hmma<<<dim3(24, GM / 128), 256, SMEM_DYN>>>(xh, xl, wth, wtl,
                                                     nullptr, nullptr, 0);

    featmap_hmma<<<dim3(32, 64), 256, FM_SMEM>>>();

    kv_hmma<<<dim3(BHN, 2, 2), 256, KV_SMEM>>>();

    kv_finalize<<<dim3(BHN, 5), 256>>>();

    qkv_fused<<<dim3(32, BHN), 256, QF_SMEM>>>();

    gemm_hmma<<<dim3(8, GM / 128), 256, SMEM_DYN>>>(omh, oml,
        wth + 3 * (size_t)GN * GK, wtl + 3 * (size_t)GN * GK,
        bo, (float*)d_out, 1);
}

// round 14
// speedup vs baseline: 2.3030x; 1.1196x over previous
#include <cuda_runtime.h>
#include <cuda_bf16.h>
#include <cstdint>

#define BB 4
#define NN 4096
#define CC 1024
#define HH 16
#define DH 64
#define RR 266
#define RP 288
#define RT 320
#define EPSF 1e-3f
#define BHN (BB*HH)   // 64
#define GM (BB*NN)    // 16384
#define GK 1024
#define GN 1024
#define MAT_BYTES (128*80)
// tf32 gemm: 2 matrices/stage, 64 chunks of k16
#define TSTAGE (2*MAT_BYTES)      // 20480
#define SMEMT 69632               // max(2*TSTAGE, epilogue staging 2*34816)
// featmap smem
#define FM_STG 73728
#define FM_SMEM (FM_STG + 2*64*272)   // 108544
// kv smem
#define KV_STAGE (2*160*80 + 2*32*144)   // 34816
#define KV_SMEM (2*KV_STAGE)             // 69632
// qkv_fused smem layout
#define QF_SQH  0
#define QF_SQL  18432
#define QF_SQPH 36864
#define QF_SQPL 47104
#define QF_PROJ 57344
#define QF_KVT  75776
#define QF_STF  57344          // om fp32 staging (reuses PROJ/KVT after loop)
#define QF_SMEM 96256

// ---------------- scratch (device globals; no allocation allowed) ----------
__device__ float g_ksum[BHN*RP];
__device__ float g_kvacc[(size_t)2*BHN*RT*64];
__device__ float g_xt[(size_t)GM*GK];      // x, tf32-rounded
__device__ float g_wt[(size_t)4*GN*GK];    // weights transposed [N][K], tf32-rounded
__device__ float g_om[(size_t)GM*GK];      // attention out, tf32-rounded
__device__ __nv_bfloat16 g_qh[(size_t)GM*GK];
__device__ __nv_bfloat16 g_ql[(size_t)GM*GK];
__device__ __nv_bfloat16 g_kh[(size_t)GM*GK];
__device__ __nv_bfloat16 g_kl[(size_t)GM*GK];
__device__ __nv_bfloat16 g_vh[(size_t)GM*GK];
__device__ __nv_bfloat16 g_vl[(size_t)GM*GK];
__device__ __nv_bfloat16 g_projh[RT*64];
__device__ __nv_bfloat16 g_projl[RT*64];
__device__ __nv_bfloat16 g_kpTh[(size_t)BHN*RT*NN];
__device__ __nv_bfloat16 g_kpTl[(size_t)BHN*RT*NN];
__device__ __nv_bfloat16 g_kvTh[BHN*64*RP];
__device__ __nv_bfloat16 g_kvTl[BHN*64*RP];

// ---------------- helpers ----------------------------------------------------
__device__ __forceinline__ uint32_t smem_u32(const void* p) {
    uint32_t a;
    asm("{ .reg .u64 t; cvta.to.shared.u64 t, %1; cvt.u32.u64 %0, t; }"
        : "=r"(a) : "l"(p));
    return a;
}
__device__ __forceinline__ void cpa16(uint32_t dst, const void* src) {
    asm volatile("cp.async.cg.shared.global [%0], [%1], 16;" :: "r"(dst), "l"(src));
}
__device__ __forceinline__ void ldsm4(uint32_t* r, uint32_t addr) {
    asm volatile("ldmatrix.sync.aligned.m8n8.x4.shared.b16 {%0,%1,%2,%3}, [%4];"
        : "=r"(r[0]), "=r"(r[1]), "=r"(r[2]), "=r"(r[3]) : "r"(addr));
}
__device__ __forceinline__ void ldsm4t(uint32_t* r, uint32_t addr) {
    asm volatile("ldmatrix.sync.aligned.m8n8.x4.trans.shared.b16 {%0,%1,%2,%3}, [%4];"
        : "=r"(r[0]), "=r"(r[1]), "=r"(r[2]), "=r"(r[3]) : "r"(addr));
}
__device__ __forceinline__ void mma16816(float* d, const uint32_t* a, const uint32_t* b) {
    asm volatile(
        "mma.sync.aligned.m16n8k16.row.col.f32.bf16.bf16.f32 "
        "{%0,%1,%2,%3}, {%4,%5,%6,%7}, {%8,%9}, {%0,%1,%2,%3};"
        : "+f"(d[0]), "+f"(d[1]), "+f"(d[2]), "+f"(d[3])
        : "r"(a[0]), "r"(a[1]), "r"(a[2]), "r"(a[3]), "r"(b[0]), "r"(b[1]));
}
__device__ __forceinline__ void mma_tf32(float* d, const uint32_t* a, const uint32_t* b) {
    asm volatile(
        "mma.sync.aligned.m16n8k8.row.col.f32.tf32.tf32.f32 "
        "{%0,%1,%2,%3}, {%4,%5,%6,%7}, {%8,%9}, {%0,%1,%2,%3};"
        : "+f"(d[0]), "+f"(d[1]), "+f"(d[2]), "+f"(d[3])
        : "r"(a[0]), "r"(a[1]), "r"(a[2]), "r"(a[3]), "r"(b[0]), "r"(b[1]));
}
__device__ __forceinline__ void split2(float v, __nv_bfloat16& h, __nv_bfloat16& l) {
    h = __float2bfloat16(v);
    l = __float2bfloat16(v - __bfloat162float(h));
}
__device__ __forceinline__ float tf32r(float v) {
    uint32_t r;
    asm("cvt.rna.tf32.f32 %0, %1;" : "=r"(r) : "f"(v));
    return __uint_as_float(r);
}

// ---------------- TF32 GEMM: C[M,N] = A[M,K] @ Bt[N,K]^T, 2-stage ------------
// mode 0: merged QKV (grid x = 24): outputs q/k/v bf16 h/l (staged)
// mode 1: final (grid x = 8): fp32 Cf + bias
__global__ __launch_bounds__(256, 2) void gemm_tf32(
    const float* __restrict__ A, const float* __restrict__ Bt,
    const float* __restrict__ bias, float* __restrict__ Cf, int mode)
{
    extern __shared__ char smem[];
    const int tid = threadIdx.x;
    const int wid = tid >> 5, lane = tid & 31;
    const int m0 = blockIdx.y * 128, n0 = blockIdx.x * 128;
    const int wr = wid >> 2, wc = wid & 3;

    const float* gA = A + (size_t)m0 * GK;
    const float* gB = Bt + (size_t)n0 * GK;

    float acc[4][4][4] = {};

    auto load_stage = [&](int c, int st) {
        const int k0 = c * 16;
        char* dstb = smem + st * TSTAGE;
        #pragma unroll
        for (int i = 0; i < 4; i++) {
            int idx = tid + i * 256;           // [0,1024)
            int mat = idx >> 9;
            int row = (idx >> 2) & 127;
            int c16 = idx & 3;
            uint32_t dst = smem_u32(dstb + mat * MAT_BYTES + row * 80 + c16 * 16);
            const float* g = mat ? gB : gA;
            cpa16(dst, g + (size_t)row * GK + k0 + c16 * 4);
        }
        asm volatile("cp.async.commit_group;" ::: "memory");
    };

    load_stage(0, 0);

    for (int c = 0; c < 64; c++) {
        if (c + 1 < 64) {
            load_stage(c + 1, (c + 1) & 1);
            asm volatile("cp.async.wait_group 1;" ::: "memory");
        } else {
            asm volatile("cp.async.wait_group 0;" ::: "memory");
        }
        __syncthreads();

        const int st = c & 1;
        const uint32_t aB = smem_u32(smem + st * TSTAGE);
        const uint32_t bB = aB + MAT_BYTES;

        #pragma unroll
        for (int kt = 0; kt < 2; kt++) {
            // fragments: tf32 viewed as b16 pairs -> identical ldmatrix addressing
            uint32_t bf[2][4];
            const int g = lane >> 3;
            const int brow = wc * 32 + (lane & 7) + (g >> 1) * 8;
            const uint32_t bkoff = (uint32_t)(kt * 16 + (g & 1) * 8) * 2;
            #pragma unroll
            for (int nt2 = 0; nt2 < 2; nt2++)
                ldsm4(bf[nt2], bB + (uint32_t)(brow + nt2 * 16) * 80 + bkoff);
            const int arow = wr * 64 + (lane & 15);
            const uint32_t akoff = (uint32_t)(kt * 16 + (lane >> 4) * 8) * 2;
            #pragma unroll
            for (int mt = 0; mt < 4; mt++) {
                uint32_t af[4];
                ldsm4(af, aB + (uint32_t)(arow + mt * 16) * 80 + akoff);
                #pragma unroll
                for (int nt = 0; nt < 4; nt++)
                    mma_tf32(acc[mt][nt], af, &bf[nt >> 1][(nt & 1) * 2]);
            }
        }
        __syncthreads();
    }

    const int qr = lane >> 2, qc = lane & 3;
    if (mode == 1) {
        #pragma unroll
        for (int mt = 0; mt < 4; mt++)
            #pragma unroll
            for (int nt = 0; nt < 4; nt++) {
                int row = m0 + wr * 64 + mt * 16 + qr;
                int col = n0 + wc * 32 + nt * 8 + qc * 2;
                float bx = bias[col], by = bias[col + 1];
                float2 v0 = {acc[mt][nt][0] + bx, acc[mt][nt][1] + by};
                float2 v1 = {acc[mt][nt][2] + bx, acc[mt][nt][3] + by};
                *(float2*)&Cf[(size_t)row * GN + col] = v0;
                *(float2*)&Cf[(size_t)(row + 8) * GN + col] = v1;
            }
    } else {
        __nv_bfloat16 *och, *ocl;
        int cbase;
        if (n0 < 1024)      { och = g_qh; ocl = g_ql; cbase = n0; }
        else if (n0 < 2048) { och = g_kh; ocl = g_kl; cbase = n0 - 1024; }
        else                { och = g_vh; ocl = g_vl; cbase = n0 - 2048; }
        #pragma unroll
        for (int mt = 0; mt < 4; mt++)
            #pragma unroll
            for (int nt = 0; nt < 4; nt++) {
                int coll = wc * 32 + nt * 8 + qc * 2;
                #pragma unroll
                for (int hf = 0; hf < 2; hf++) {
                    int rowl = wr * 64 + mt * 16 + qr + hf * 8;
                    __nv_bfloat16 h0, l0, h1, l1;
                    split2(acc[mt][nt][hf * 2 + 0], h0, l0);
                    split2(acc[mt][nt][hf * 2 + 1], h1, l1);
                    *(__nv_bfloat162*)(smem + rowl * 272 + coll * 2)
                        = __nv_bfloat162{h0, h1};
                    *(__nv_bfloat162*)(smem + 34816 + rowl * 272 + coll * 2)
                        = __nv_bfloat162{l0, l1};
                }
            }
        __syncthreads();
        #pragma unroll
        for (int j = 0; j < 8; j++) {
            int idx = tid + j * 256;
            int rr = idx >> 4, c16 = idx & 15;
            float4 vh = *(float4*)(smem + rr * 272 + c16 * 16);
            float4 vl = *(float4*)(smem + 34816 + rr * 272 + c16 * 16);
            *(float4*)&och[(size_t)(m0 + rr) * GN + cbase + c16 * 8] = vh;
            *(float4*)&ocl[(size_t)(m0 + rr) * GN + cbase + c16 * 8] = vl;
        }
    }
}

// ---------------- x -> tf32-rounded fp32 -------------------------------------
__global__ __launch_bounds__(256) void xcvt(const float* __restrict__ in, int n4)
{
    int i = blockIdx.x * blockDim.x + threadIdx.x;
    if (i >= n4) return;
    float4 v = ((const float4*)in)[i];
    v.x = tf32r(v.x); v.y = tf32r(v.y); v.z = tf32r(v.z); v.w = tf32r(v.w);
    ((float4*)g_xt)[i] = v;
}

// ---------------- transpose + tf32-round all 4 weights -----------------------
__global__ void wtrans(const float* __restrict__ W0, const float* __restrict__ W1,
                       const float* __restrict__ W2, const float* __restrict__ W3)
{
    __shared__ float t[32][33];
    const int z = blockIdx.z;
    const float* W = (z == 0) ? W0 : (z == 1) ? W1 : (z == 2) ? W2 : W3;
    float* out = g_wt + (size_t)z * GN * GK;
    const int k0 = blockIdx.y * 32, n0 = blockIdx.x * 32;
    for (int i = threadIdx.y; i < 32; i += 8)
        t[i][threadIdx.x] = W[(size_t)(k0 + i) * GN + n0 + threadIdx.x];
    __syncthreads();
    for (int i = threadIdx.y; i < 32; i += 8)
        out[(size_t)(n0 + i) * GK + k0 + threadIdx.x] = tf32r(t[threadIdx.x][i]);
}

// ---------------- proj split (padded to RT rows, zero fill) ------------------
__global__ void psplit(const float* __restrict__ proj)
{
    int i = blockIdx.x * 256 + threadIdx.x;
    if (i >= RT * 64) return;
    int r = i >> 6, d = i & 63;
    float v = (r < RR) ? proj[r * 64 + d] : 0.0f;
    __nv_bfloat16 h, l;
    split2(v, h, l);
    g_projh[i] = h;
    g_projl[i] = l;
}

// ---------------- featmap HMMA (k only): kpT + ksum, staged stores -----------
__global__ __launch_bounds__(256, 2) void featmap_hmma()
{
    extern __shared__ char smem[];
    const int tid = threadIdx.x, wid = tid >> 5, lane = tid & 31;
    const int n0 = blockIdx.x * 128;
    const int bh = blockIdx.y;
    const int b = bh >> 4, h = bh & 15;
    const size_t abase = ((size_t)(b * NN + n0)) * GK + h * 64;

    const uint32_t sA_h = smem_u32(smem);
    const uint32_t sA_l = sA_h + 128 * 144;
    const uint32_t sP   = sA_h + 2 * 128 * 144;

    auto load_proj = [&](int r0i, int slot) {
        #pragma unroll
        for (int i = 0; i < 4; i++) {
            int idx = tid + i * 256;
            int row = (idx & 511) >> 3, c = idx & 7;
            uint32_t dst = sP + slot * 18432 + (idx < 512 ? 0 : 9216)
                         + row * 144 + c * 16;
            const __nv_bfloat16* src = (idx < 512 ? g_projh : g_projl)
                                       + (r0i * 64 + row) * 64 + c * 8;
            cpa16(dst, src);
        }
        asm volatile("cp.async.commit_group;" ::: "memory");
    };

    #pragma unroll
    for (int i = 0; i < 8; i++) {
        int idx = tid + i * 256;
        int row = (idx & 1023) >> 3, c = idx & 7;
        uint32_t dst = (idx < 1024 ? sA_h : sA_l) + row * 144 + c * 16;
        const __nv_bfloat16* src = (idx < 1024 ? g_kh : g_kl) + abase
                                   + (size_t)row * GK + c * 8;
        cpa16(dst, src);
    }
    load_proj(0, 0);
    load_proj(1, 1);

    const int wr = wid >> 2, wc = wid & 3;
    const int qr = lane >> 2, qc = lane & 3;

    for (int r0i = 0; r0i < 5; r0i++) {
        if (r0i < 4) { asm volatile("cp.async.wait_group 1;" ::: "memory"); }
        else         { asm volatile("cp.async.wait_group 0;" ::: "memory"); }
        __syncthreads();

        const uint32_t pH = sP + (r0i & 1) * 18432;
        const uint32_t pL = pH + 9216;

        float acc[4][2][4] = {};
        #pragma unroll
        for (int kt = 0; kt < 4; kt++) {
            uint32_t bh1[4], bl1[4];
            const int g = lane >> 3;
            const int brow = wc * 16 + (lane & 7) + (g >> 1) * 8;
            const uint32_t bk = (uint32_t)(kt * 16 + (g & 1) * 8) * 2;
            ldsm4(bh1, pH + (uint32_t)brow * 144 + bk);
            ldsm4(bl1, pL + (uint32_t)brow * 144 + bk);
            const int arow = wr * 64 + (lane & 15);
            const uint32_t ak = (uint32_t)(kt * 16 + (lane >> 4) * 8) * 2;
            #pragma unroll
            for (int mt = 0; mt < 4; mt++) {
                uint32_t ah[4], al[4];
                ldsm4(ah, sA_h + (uint32_t)(arow + mt * 16) * 144 + ak);
                ldsm4(al, sA_l + (uint32_t)(arow + mt * 16) * 144 + ak);
                #pragma unroll
                for (int nt = 0; nt < 2; nt++) {
                    mma16816(acc[mt][nt], ah, &bh1[nt * 2]);
                    mma16816(acc[mt][nt], ah, &bl1[nt * 2]);
                    mma16816(acc[mt][nt], al, &bh1[nt * 2]);
                }
            }
        }
        __syncthreads();
        if (r0i + 2 < 5) load_proj(r0i + 2, r0i & 1);

        #pragma unroll
        for (int nt = 0; nt < 2; nt++) {
            int rloc = wc * 16 + nt * 8 + qc * 2;
            int rglob = r0i * 64 + rloc;
            bool valid = (rglob < RR);
            float s0 = 0.f, s1 = 0.f;
            #pragma unroll
            for (int mt = 0; mt < 4; mt++)
                #pragma unroll
                for (int hf = 0; hf < 2; hf++) {
                    int nloc = wr * 64 + mt * 16 + qr + hf * 8;
                    float v0 = acc[mt][nt][hf * 2 + 0];
                    float v1 = acc[mt][nt][hf * 2 + 1];
                    v0 = valid ? (fmaxf(v0, 0.0f) + EPSF) : 0.0f;
                    v1 = valid ? (fmaxf(v1, 0.0f) + EPSF) : 0.0f;
                    __nv_bfloat16 h0, l0, h1, l1;
                    split2(v0, h0, l0);
                    split2(v1, h1, l1);
                    *(__nv_bfloat16*)(smem + FM_STG + rloc * 272 + nloc * 2) = h0;
                    *(__nv_bfloat16*)(smem + FM_STG + (rloc + 1) * 272 + nloc * 2) = h1;
                    *(__nv_bfloat16*)(smem + FM_STG + 17408 + rloc * 272 + nloc * 2) = l0;
                    *(__nv_bfloat16*)(smem + FM_STG + 17408 + (rloc + 1) * 272 + nloc * 2) = l1;
                    s0 += v0;
                    s1 += v1;
                }
            if (valid) {
                atomicAdd(&g_ksum[bh * RP + rglob], s0);
                atomicAdd(&g_ksum[bh * RP + rglob + 1], s1);
            }
        }
        __syncthreads();

        const size_t kb = (size_t)bh * RT * NN;
        #pragma unroll
        for (int j = 0; j < 4; j++) {
            int idx = tid + j * 256;
            int rr = idx >> 4, c16 = idx & 15;
            float4 vh = *(float4*)(smem + FM_STG + rr * 272 + c16 * 16);
            float4 vl = *(float4*)(smem + FM_STG + 17408 + rr * 272 + c16 * 16);
            size_t o = kb + (size_t)(r0i * 64 + rr) * NN + n0 + c16 * 8;
            *(float4*)&g_kpTh[o] = vh;
            *(float4*)&g_kpTl[o] = vl;
        }
    }
}

// ---------------- kv HMMA: kvacc[khalf][bh][r][d] = kpT @ v ------------------
__global__ __launch_bounds__(256, 2) void kv_hmma()
{
    extern __shared__ char smem[];
    const int tid = threadIdx.x, wid = tid >> 5, lane = tid & 31;
    const int bh = blockIdx.x, rhalf = blockIdx.y, khalf = blockIdx.z;
    const int b = bh >> 4, h = bh & 15;

    const __nv_bfloat16* __restrict__ Ahb =
        g_kpTh + ((size_t)bh * RT + rhalf * 160) * NN + khalf * 2048;
    const __nv_bfloat16* __restrict__ Alb =
        g_kpTl + ((size_t)bh * RT + rhalf * 160) * NN + khalf * 2048;
    const __nv_bfloat16* __restrict__ Bhb =
        g_vh + ((size_t)(b * NN + khalf * 2048)) * GK + h * 64;
    const __nv_bfloat16* __restrict__ Blb =
        g_vl + ((size_t)(b * NN + khalf * 2048)) * GK + h * 64;

    const int wm = wid >> 2, wn = wid & 3;
    float acc[5][2][4] = {};

    auto load_stage = [&](int c, int st) {
        const int k0 = c * 32;
        char* sb = smem + st * KV_STAGE;
        #pragma unroll
        for (int i = 0; i < 7; i++) {
            int idx = tid + i * 256;
            uint32_t dst;
            const __nv_bfloat16* src;
            if (idx < 640) {
                int row = idx >> 2, cc = idx & 3;
                dst = smem_u32(sb + row * 80 + cc * 16);
                src = Ahb + (size_t)row * NN + k0 + cc * 8;
            } else if (idx < 1280) {
                int j = idx - 640; int row = j >> 2, cc = j & 3;
                dst = smem_u32(sb + 12800 + row * 80 + cc * 16);
                src = Alb + (size_t)row * NN + k0 + cc * 8;
            } else if (idx < 1536) {
                int j = idx - 1280; int row = j >> 3, cc = j & 7;
                dst = smem_u32(sb + 25600 + row * 144 + cc * 16);
                src = Bhb + (size_t)(k0 + row) * GK + cc * 8;
            } else {
                int j = idx - 1536; int row = j >> 3, cc = j & 7;
                dst = smem_u32(sb + 25600 + 4608 + row * 144 + cc * 16);
                src = Blb + (size_t)(k0 + row) * GK + cc * 8;
            }
            cpa16(dst, src);
        }
        asm volatile("cp.async.commit_group;" ::: "memory");
    };

    load_stage(0, 0);

    for (int c = 0; c < 64; c++) {
        if (c + 1 < 64) {
            load_stage(c + 1, (c + 1) & 1);
            asm volatile("cp.async.wait_group 1;" ::: "memory");
        } else {
            asm volatile("cp.async.wait_group 0;" ::: "memory");
        }
        __syncthreads();

        const int st = c & 1;
        const uint32_t aH = smem_u32(smem + st * KV_STAGE);
        const uint32_t aL = aH + 12800;
        const uint32_t bHs = aH + 25600;
        const uint32_t bLs = bHs + 4608;

        #pragma unroll
        for (int kt = 0; kt < 2; kt++) {
            uint32_t bhf[4], blf[4];
            const int g = lane >> 3;
            const int browk = kt * 16 + (g & 1) * 8 + (lane & 7);
            const uint32_t bc = (uint32_t)(wn * 16 + (g >> 1) * 8) * 2;
            ldsm4t(bhf, bHs + (uint32_t)browk * 144 + bc);
            ldsm4t(blf, bLs + (uint32_t)browk * 144 + bc);
            const int arow = wm * 80 + (lane & 15);
            const uint32_t ak = (uint32_t)(kt * 16 + (lane >> 4) * 8) * 2;
            #pragma unroll
            for (int mt = 0; mt < 5; mt++) {
                uint32_t ah[4], al[4];
                ldsm4(ah, aH + (uint32_t)(arow + mt * 16) * 80 + ak);
                ldsm4(al, aL + (uint32_t)(arow + mt * 16) * 80 + ak);
                #pragma unroll
                for (int nt = 0; nt < 2; nt++) {
                    mma16816(acc[mt][nt], ah, &bhf[nt * 2]);
                    mma16816(acc[mt][nt], ah, &blf[nt * 2]);
                    mma16816(acc[mt][nt], al, &bhf[nt * 2]);
                }
            }
        }
        __syncthreads();
    }

    const int qr = lane >> 2, qc = lane & 3;
    float* outp = g_kvacc + ((size_t)(khalf * BHN + bh)) * RT * 64;
    #pragma unroll
    for (int mt = 0; mt < 5; mt++)
        #pragma unroll
        for (int nt = 0; nt < 2; nt++) {
            int r = rhalf * 160 + wm * 80 + mt * 16 + qr;
            int d = wn * 16 + nt * 8 + qc * 2;
            #pragma unroll
            for (int hf = 0; hf < 2; hf++) {
                float2 v = {acc[mt][nt][hf * 2 + 0], acc[mt][nt][hf * 2 + 1]};
                *(float2*)&outp[(size_t)(r + hf * 8) * 64 + d] = v;
            }
        }
}

// ---------------- kv finalize: sum khalves, transpose -> kvT[d][r] h/l -------
__global__ void kv_finalize()
{
    __shared__ float t[64][65];
    const int bh = blockIdx.x, rblk = blockIdx.y;
    const int tid = threadIdx.x;
    const float* a0 = g_kvacc + ((size_t)bh * RT + rblk * 64) * 64;
    const float* a1 = g_kvacc + ((size_t)(BHN + bh) * RT + rblk * 64) * 64;
    #pragma unroll
    for (int i = 0; i < 16; i++) {
        int e = tid + i * 256;
        t[e >> 6][e & 63] = a0[e] + a1[e];
    }
    __syncthreads();
    const int d = tid >> 2, rs = (tid & 3) * 16;
    const size_t ob = ((size_t)bh * 64 + d) * RP;
    #pragma unroll
    for (int j = 0; j < 16; j += 2) {
        int rg = rblk * 64 + rs + j;
        if (rg >= RP) break;
        __nv_bfloat16 h0, l0, h1, l1;
        split2(t[rs + j][d], h0, l0);
        split2(t[rs + j + 1][d], h1, l1);
        *(__nv_bfloat162*)&g_kvTh[ob + rg] = __nv_bfloat162{h0, h1};
        *(__nv_bfloat162*)&g_kvTl[ob + rg] = __nv_bfloat162{l0, l1};
    }
}

// ---------------- qkv_fused: QP in smem, om = QP@kvT*dinv -> g_om fp32 -------
__global__ __launch_bounds__(256, 2) void qkv_fused()
{
    extern __shared__ char smem[];
    __shared__ float ksumS[RP];
    __shared__ float dpart[2][128];
    __shared__ float dinvS[128];
    const int tid = threadIdx.x, wid = tid >> 5, lane = tid & 31;
    const int n0 = blockIdx.x * 128;
    const int bh = blockIdx.y;
    const int b = bh >> 4, h = bh & 15;
    const uint32_t sb = smem_u32(smem);

    const size_t qbase = ((size_t)(b * NN + n0)) * GK + h * 64;
    const __nv_bfloat16* __restrict__ Bhg = g_kvTh + (size_t)bh * 64 * RP;
    const __nv_bfloat16* __restrict__ Blg = g_kvTl + (size_t)bh * 64 * RP;

    for (int i = tid; i < RP; i += 256) ksumS[i] = g_ksum[bh * RP + i];

    #pragma unroll
    for (int i = 0; i < 8; i++) {
        int idx = tid + i * 256;
        int row = (idx & 1023) >> 3, c = idx & 7;
        uint32_t dst = sb + (idx < 1024 ? QF_SQH : QF_SQL) + row * 144 + c * 16;
        const __nv_bfloat16* src = (idx < 1024 ? g_qh : g_ql) + qbase
                                   + (size_t)row * GK + c * 8;
        cpa16(dst, src);
    }

    auto load_chunk = [&](int c, int slot) {
        #pragma unroll
        for (int i = 0; i < 2; i++) {
            int idx = tid + i * 256;
            int row = (idx & 255) >> 3, cc = idx & 7;
            uint32_t dst = sb + QF_PROJ + slot * 9216 + (idx < 256 ? 0 : 4608)
                         + row * 144 + cc * 16;
            const __nv_bfloat16* src = (idx < 256 ? g_projh : g_projl)
                                       + (c * 32 + row) * 64 + cc * 8;
            cpa16(dst, src);
        }
        #pragma unroll
        for (int i = 0; i < 2; i++) {
            int idx = tid + i * 256;
            int row = (idx & 255) >> 2, cc = idx & 3;
            uint32_t dst = sb + QF_KVT + slot * 10240 + (idx < 256 ? 0 : 5120)
                         + row * 80 + cc * 16;
            const __nv_bfloat16* src = (idx < 256 ? Bhg : Blg)
                                       + (size_t)row * RP + c * 32 + cc * 8;
            cpa16(dst, src);
        }
        asm volatile("cp.async.commit_group;" ::: "memory");
    };

    load_chunk(0, 0);
    load_chunk(1, 1);

    float accO[4][2][4] = {};
    float myd = 0.f;
    const int drow = tid & 127, dhalf = tid >> 7;
    const int wrq = wid >> 1, wcq = wid & 1;
    const int wr = wid >> 2, wc = wid & 3;
    const int qr = lane >> 2, qc = lane & 3;

    for (int c = 0; c < 9; c++) {
        if (c < 8) { asm volatile("cp.async.wait_group 1;" ::: "memory"); }
        else       { asm volatile("cp.async.wait_group 0;" ::: "memory"); }
        __syncthreads();

        const uint32_t pH = sb + QF_PROJ + (c & 1) * 9216;
        const uint32_t pL = pH + 4608;

        float accQ[2][2][4] = {};
        #pragma unroll
        for (int kt = 0; kt < 4; kt++) {
            uint32_t bh1[4], bl1[4];
            const int g = lane >> 3;
            const int brow = wcq * 16 + (lane & 7) + (g >> 1) * 8;
            const uint32_t bk = (uint32_t)(kt * 16 + (g & 1) * 8) * 2;
            ldsm4(bh1, pH + (uint32_t)brow * 144 + bk);
            ldsm4(bl1, pL + (uint32_t)brow * 144 + bk);
            const int arow = wrq * 32 + (lane & 15);
            const uint32_t ak = (uint32_t)(kt * 16 + (lane >> 4) * 8) * 2;
            #pragma unroll
            for (int mt = 0; mt < 2; mt++) {
                uint32_t ah[4], al[4];
                ldsm4(ah, sb + QF_SQH + (uint32_t)(arow + mt * 16) * 144 + ak);
                ldsm4(al, sb + QF_SQL + (uint32_t)(arow + mt * 16) * 144 + ak);
                #pragma unroll
                for (int nt = 0; nt < 2; nt++) {
                    mma16816(accQ[mt][nt], ah, &bh1[nt * 2]);
                    mma16816(accQ[mt][nt], ah, &bl1[nt * 2]);
                    mma16816(accQ[mt][nt], al, &bh1[nt * 2]);
                }
            }
        }
        #pragma unroll
        for (int mt = 0; mt < 2; mt++)
            #pragma unroll
            for (int nt = 0; nt < 2; nt++) {
                int rcol = wcq * 16 + nt * 8 + qc * 2;
                #pragma unroll
                for (int hf = 0; hf < 2; hf++) {
                    int row = wrq * 32 + mt * 16 + qr + hf * 8;
                    float v0 = fmaxf(accQ[mt][nt][hf * 2 + 0], 0.0f) + EPSF;
                    float v1 = fmaxf(accQ[mt][nt][hf * 2 + 1], 0.0f) + EPSF;
                    __nv_bfloat16 h0, l0, h1, l1;
                    split2(v0, h0, l0);
                    split2(v1, h1, l1);
                    *(__nv_bfloat162*)(smem + QF_SQPH + row * 80 + rcol * 2)
                        = __nv_bfloat162{h0, h1};
                    *(__nv_bfloat162*)(smem + QF_SQPL + row * 80 + rcol * 2)
                        = __nv_bfloat162{l0, l1};
                }
            }
        __syncthreads();

        {
            const __nv_bfloat16* ph = (const __nv_bfloat16*)(smem + QF_SQPH
                                        + drow * 80 + dhalf * 32);
            const __nv_bfloat16* pl = (const __nv_bfloat16*)(smem + QF_SQPL
                                        + drow * 80 + dhalf * 32);
            const float* ksp = ksumS + c * 32 + dhalf * 16;
            #pragma unroll
            for (int kk = 0; kk < 16; kk++) {
                float v = __bfloat162float(ph[kk]) + __bfloat162float(pl[kk]);
                myd += v * ksp[kk];
            }
        }

        const uint32_t aH = sb + QF_SQPH, aL = sb + QF_SQPL;
        const uint32_t bHc = sb + QF_KVT + (c & 1) * 10240;
        const uint32_t bLc = bHc + 5120;
        #pragma unroll
        for (int kt = 0; kt < 2; kt++) {
            uint32_t bh1[4], bl1[4];
            const int g = lane >> 3;
            const int brow = wc * 16 + (lane & 7) + (g >> 1) * 8;
            const uint32_t bk = (uint32_t)(kt * 16 + (g & 1) * 8) * 2;
            ldsm4(bh1, bHc + (uint32_t)brow * 80 + bk);
            ldsm4(bl1, bLc + (uint32_t)brow * 80 + bk);
            const int arow = wr * 64 + (lane & 15);
            const uint32_t ak = (uint32_t)(kt * 16 + (lane >> 4) * 8) * 2;
            #pragma unroll
            for (int mt = 0; mt < 4; mt++) {
                uint32_t ah[4], al[4];
                ldsm4(ah, aH + (uint32_t)(arow + mt * 16) * 80 + ak);
                ldsm4(al, aL + (uint32_t)(arow + mt * 16) * 80 + ak);
                #pragma unroll
                for (int nt = 0; nt < 2; nt++) {
                    mma16816(accO[mt][nt], ah, &bh1[nt * 2]);
                    mma16816(accO[mt][nt], ah, &bl1[nt * 2]);
                    mma16816(accO[mt][nt], al, &bh1[nt * 2]);
                }
            }
        }
        __syncthreads();
        if (c + 2 < 9) load_chunk(c + 2, c & 1);
    }

    dpart[dhalf][drow] = myd;
    __syncthreads();
    if (tid < 128) dinvS[tid] = 1.0f / (dpart[0][tid] + dpart[1][tid]);
    __syncthreads();

    // ---- staged fp32 om epilogue (tf32-rounded for the final GEMM)
    #pragma unroll
    for (int mt = 0; mt < 4; mt++)
        #pragma unroll
        for (int nt = 0; nt < 2; nt++) {
            int d = wc * 16 + nt * 8 + qc * 2;
            #pragma unroll
            for (int hf = 0; hf < 2; hf++) {
                int lrow = wr * 64 + mt * 16 + qr + hf * 8;
                float di = dinvS[lrow];
                float2 v;
                v.x = tf32r(accO[mt][nt][hf * 2 + 0] * di);
                v.y = tf32r(accO[mt][nt][hf * 2 + 1] * di);
                *(float2*)(smem + QF_STF + lrow * 272 + d * 4) = v;
            }
        }
    __syncthreads();
    #pragma unroll
    for (int j = 0; j < 8; j++) {
        int idx = tid + j * 256;
        int rr = idx >> 4, c16 = idx & 15;
        float4 v = *(float4*)(smem + QF_STF + rr * 272 + c16 * 16);
        size_t o = ((size_t)(b * NN + n0 + rr)) * GK + h * 64 + c16 * 4;
        *(float4*)&g_om[o] = v;
    }
}

// ---------------- launch -----------------------------------------------------
extern "C" void kernel_launch(void* const* d_in, const int* in_sizes, int n_in,
                              void* d_out, int out_size)
{
    const float* x    = (const float*)d_in[0];
    const float* Wq   = (const float*)d_in[1];
    const float* Wk   = (const float*)d_in[2];
    const float* Wv   = (const float*)d_in[3];
    const float* Wo   = (const float*)d_in[4];
    const float* bo   = (const float*)d_in[5];
    const float* proj = (const float*)d_in[6];

    float *ksum, *xt, *wt, *om;
    cudaGetSymbolAddress((void**)&ksum, g_ksum);
    cudaGetSymbolAddress((void**)&xt,   g_xt);
    cudaGetSymbolAddress((void**)&wt,   g_wt);
    cudaGetSymbolAddress((void**)&om,   g_om);

    cudaFuncSetAttribute(gemm_tf32,
                         cudaFuncAttributeMaxDynamicSharedMemorySize, SMEMT);
    cudaFuncSetAttribute(featmap_hmma,
                         cudaFuncAttributeMaxDynamicSharedMemorySize, FM_SMEM);
    cudaFuncSetAttribute(kv_hmma,
                         cudaFuncAttributeMaxDynamicSharedMemorySize, KV_SMEM);
    cudaFuncSetAttribute(qkv_fused,
                         cudaFuncAttributeMaxDynamicSharedMemorySize, QF_SMEM);

    const int n4 = GM * GK / 4;

    xcvt<<<(n4 + 255) / 256, 256>>>(x, n4);
    wtrans<<<dim3(32, 32, 4), dim3(32, 8)>>>(Wq, Wk, Wv, Wo);
    psplit<<<80, 256>>>(proj);
    cudaMemsetAsync(ksum, 0, BHN * RP * sizeof(float));

    // merged Q/K/V GEMM (tf32), N = 3072
    gemm_tf32<<<dim3(24, GM / 128), 256, SMEMT>>>(xt, wt, nullptr, nullptr, 0);

    featmap_hmma<<<dim3(32, 64), 256, FM_SMEM>>>();

    kv_hmma<<<dim3(BHN, 2, 2), 256, KV_SMEM>>>();

    kv_finalize<<<dim3(BHN, 5), 256>>>();

    qkv_fused<<<dim3(32, BHN), 256, QF_SMEM>>>();

    // final GEMM (tf32) with bias
    gemm_tf32<<<dim3(8, GM / 128), 256, SMEMT>>>(om, wt + 3 * (size_t)GN * GK,
                                                 bo, (float*)d_out, 1);
}

// round 15
// speedup vs baseline: 2.4175x; 1.0497x over previous
#include <cuda_runtime.h>
#include <cuda_bf16.h>
#include <cstdint>

#define BB 4
#define NN 4096
#define CC 1024
#define HH 16
#define DH 64
#define RR 266
#define RP 288
#define RT 320
#define EPSF 1e-3f
#define BHN (BB*HH)   // 64
#define GM (BB*NN)    // 16384
#define GK 1024
#define GN 1024
// tf32 gemm: K-chunk 32, 2 matrices/stage (128 rows x 144B each)
#define TMAT 18432
#define TSTAGE (2*TMAT)           // 36864
#define SMEMT (2*TSTAGE)          // 73728 (also covers epilogue staging 69632)
// featmap smem
#define FM_STG 73728
#define FM_SMEM (FM_STG + 2*64*272)   // 108544
// kv smem
#define KV_STAGE (2*160*80 + 2*32*144)   // 34816
#define KV_SMEM (2*KV_STAGE)             // 69632
// qkv_fused smem layout
#define QF_SQH  0
#define QF_SQL  18432
#define QF_SQPH 36864
#define QF_SQPL 47104
#define QF_PROJ 57344
#define QF_KVT  75776
#define QF_STF  57344
#define QF_SMEM 96256

// ---------------- scratch (device globals; no allocation allowed) ----------
__device__ float g_ksum[BHN*RP];
__device__ float g_kvacc[(size_t)2*BHN*RT*64];
__device__ float g_xt[(size_t)GM*GK];
__device__ float g_wt[(size_t)4*GN*GK];
__device__ float g_om[(size_t)GM*GK];
__device__ __nv_bfloat16 g_qh[(size_t)GM*GK];
__device__ __nv_bfloat16 g_ql[(size_t)GM*GK];
__device__ __nv_bfloat16 g_kh[(size_t)GM*GK];
__device__ __nv_bfloat16 g_kl[(size_t)GM*GK];
__device__ __nv_bfloat16 g_vh[(size_t)GM*GK];
__device__ __nv_bfloat16 g_vl[(size_t)GM*GK];
__device__ __nv_bfloat16 g_projh[RT*64];
__device__ __nv_bfloat16 g_projl[RT*64];
__device__ __nv_bfloat16 g_kpTh[(size_t)BHN*RT*NN];
__device__ __nv_bfloat16 g_kpTl[(size_t)BHN*RT*NN];
__device__ __nv_bfloat16 g_kvTh[BHN*64*RP];
__device__ __nv_bfloat16 g_kvTl[BHN*64*RP];

// ---------------- helpers ----------------------------------------------------
__device__ __forceinline__ uint32_t smem_u32(const void* p) {
    uint32_t a;
    asm("{ .reg .u64 t; cvta.to.shared.u64 t, %1; cvt.u32.u64 %0, t; }"
        : "=r"(a) : "l"(p));
    return a;
}
__device__ __forceinline__ void cpa16(uint32_t dst, const void* src) {
    asm volatile("cp.async.cg.shared.global [%0], [%1], 16;" :: "r"(dst), "l"(src));
}
__device__ __forceinline__ void ldsm4(uint32_t* r, uint32_t addr) {
    asm volatile("ldmatrix.sync.aligned.m8n8.x4.shared.b16 {%0,%1,%2,%3}, [%4];"
        : "=r"(r[0]), "=r"(r[1]), "=r"(r[2]), "=r"(r[3]) : "r"(addr));
}
__device__ __forceinline__ void ldsm4t(uint32_t* r, uint32_t addr) {
    asm volatile("ldmatrix.sync.aligned.m8n8.x4.trans.shared.b16 {%0,%1,%2,%3}, [%4];"
        : "=r"(r[0]), "=r"(r[1]), "=r"(r[2]), "=r"(r[3]) : "r"(addr));
}
__device__ __forceinline__ void mma16816(float* d, const uint32_t* a, const uint32_t* b) {
    asm volatile(
        "mma.sync.aligned.m16n8k16.row.col.f32.bf16.bf16.f32 "
        "{%0,%1,%2,%3}, {%4,%5,%6,%7}, {%8,%9}, {%0,%1,%2,%3};"
        : "+f"(d[0]), "+f"(d[1]), "+f"(d[2]), "+f"(d[3])
        : "r"(a[0]), "r"(a[1]), "r"(a[2]), "r"(a[3]), "r"(b[0]), "r"(b[1]));
}
__device__ __forceinline__ void mma_tf32(float* d, const uint32_t* a, const uint32_t* b) {
    asm volatile(
        "mma.sync.aligned.m16n8k8.row.col.f32.tf32.tf32.f32 "
        "{%0,%1,%2,%3}, {%4,%5,%6,%7}, {%8,%9}, {%0,%1,%2,%3};"
        : "+f"(d[0]), "+f"(d[1]), "+f"(d[2]), "+f"(d[3])
        : "r"(a[0]), "r"(a[1]), "r"(a[2]), "r"(a[3]), "r"(b[0]), "r"(b[1]));
}
__device__ __forceinline__ void split2(float v, __nv_bfloat16& h, __nv_bfloat16& l) {
    h = __float2bfloat16(v);
    l = __float2bfloat16(v - __bfloat162float(h));
}
__device__ __forceinline__ float tf32r(float v) {
    uint32_t r;
    asm("cvt.rna.tf32.f32 %0, %1;" : "=r"(r) : "f"(v));
    return __uint_as_float(r);
}

// ---------------- TF32 GEMM: C[M,N] = A[M,K] @ Bt[N,K]^T, KC=32, 2-stage -----
// mode 0: merged QKV (grid x = 24); mode 1: final (grid x = 8) fp32 + bias
__global__ __launch_bounds__(256, 2) void gemm_tf32(
    const float* __restrict__ A, const float* __restrict__ Bt,
    const float* __restrict__ bias, float* __restrict__ Cf, int mode)
{
    extern __shared__ char smem[];
    const int tid = threadIdx.x;
    const int wid = tid >> 5, lane = tid & 31;
    const int m0 = blockIdx.y * 128, n0 = blockIdx.x * 128;
    const int wr = wid >> 2, wc = wid & 3;

    const float* gA = A + (size_t)m0 * GK;
    const float* gB = Bt + (size_t)n0 * GK;

    float acc[4][4][4] = {};

    auto load_stage = [&](int c, int st) {
        const int k0 = c * 32;
        char* dstb = smem + st * TSTAGE;
        #pragma unroll
        for (int i = 0; i < 8; i++) {
            int idx = tid + i * 256;           // [0,2048)
            int mat = idx >> 10;
            int row = (idx >> 3) & 127;
            int c16 = idx & 7;
            uint32_t dst = smem_u32(dstb + mat * TMAT + row * 144 + c16 * 16);
            const float* g = mat ? gB : gA;
            cpa16(dst, g + (size_t)row * GK + k0 + c16 * 4);
        }
        asm volatile("cp.async.commit_group;" ::: "memory");
    };

    load_stage(0, 0);

    for (int c = 0; c < 32; c++) {
        if (c + 1 < 32) {
            load_stage(c + 1, (c + 1) & 1);
            asm volatile("cp.async.wait_group 1;" ::: "memory");
        } else {
            asm volatile("cp.async.wait_group 0;" ::: "memory");
        }
        __syncthreads();

        const int st = c & 1;
        const uint32_t aB = smem_u32(smem + st * TSTAGE);
        const uint32_t bB = aB + TMAT;

        #pragma unroll
        for (int kt = 0; kt < 4; kt++) {       // 4 x k8
            uint32_t bf[2][4];
            const int g = lane >> 3;
            const int brow = wc * 32 + (lane & 7) + (g >> 1) * 8;
            const uint32_t bkoff = (uint32_t)(kt * 16 + (g & 1) * 8) * 2;
            #pragma unroll
            for (int nt2 = 0; nt2 < 2; nt2++)
                ldsm4(bf[nt2], bB + (uint32_t)(brow + nt2 * 16) * 144 + bkoff);
            const int arow = wr * 64 + (lane & 15);
            const uint32_t akoff = (uint32_t)(kt * 16 + (lane >> 4) * 8) * 2;
            #pragma unroll
            for (int mt = 0; mt < 4; mt++) {
                uint32_t af[4];
                ldsm4(af, aB + (uint32_t)(arow + mt * 16) * 144 + akoff);
                #pragma unroll
                for (int nt = 0; nt < 4; nt++)
                    mma_tf32(acc[mt][nt], af, &bf[nt >> 1][(nt & 1) * 2]);
            }
        }
        __syncthreads();
    }

    const int qr = lane >> 2, qc = lane & 3;
    if (mode == 1) {
        #pragma unroll
        for (int mt = 0; mt < 4; mt++)
            #pragma unroll
            for (int nt = 0; nt < 4; nt++) {
                int row = m0 + wr * 64 + mt * 16 + qr;
                int col = n0 + wc * 32 + nt * 8 + qc * 2;
                float bx = bias[col], by = bias[col + 1];
                float2 v0 = {acc[mt][nt][0] + bx, acc[mt][nt][1] + by};
                float2 v1 = {acc[mt][nt][2] + bx, acc[mt][nt][3] + by};
                *(float2*)&Cf[(size_t)row * GN + col] = v0;
                *(float2*)&Cf[(size_t)(row + 8) * GN + col] = v1;
            }
    } else {
        __nv_bfloat16 *och, *ocl;
        int cbase;
        if (n0 < 1024)      { och = g_qh; ocl = g_ql; cbase = n0; }
        else if (n0 < 2048) { och = g_kh; ocl = g_kl; cbase = n0 - 1024; }
        else                { och = g_vh; ocl = g_vl; cbase = n0 - 2048; }
        #pragma unroll
        for (int mt = 0; mt < 4; mt++)
            #pragma unroll
            for (int nt = 0; nt < 4; nt++) {
                int coll = wc * 32 + nt * 8 + qc * 2;
                #pragma unroll
                for (int hf = 0; hf < 2; hf++) {
                    int rowl = wr * 64 + mt * 16 + qr + hf * 8;
                    __nv_bfloat16 h0, l0, h1, l1;
                    split2(acc[mt][nt][hf * 2 + 0], h0, l0);
                    split2(acc[mt][nt][hf * 2 + 1], h1, l1);
                    *(__nv_bfloat162*)(smem + rowl * 272 + coll * 2)
                        = __nv_bfloat162{h0, h1};
                    *(__nv_bfloat162*)(smem + 34816 + rowl * 272 + coll * 2)
                        = __nv_bfloat162{l0, l1};
                }
            }
        __syncthreads();
        #pragma unroll
        for (int j = 0; j < 8; j++) {
            int idx = tid + j * 256;
            int rr = idx >> 4, c16 = idx & 15;
            float4 vh = *(float4*)(smem + rr * 272 + c16 * 16);
            float4 vl = *(float4*)(smem + 34816 + rr * 272 + c16 * 16);
            *(float4*)&och[(size_t)(m0 + rr) * GN + cbase + c16 * 8] = vh;
            *(float4*)&ocl[(size_t)(m0 + rr) * GN + cbase + c16 * 8] = vl;
        }
    }
}

// ---------------- x -> tf32-rounded fp32 -------------------------------------
__global__ __launch_bounds__(256) void xcvt(const float* __restrict__ in, int n4)
{
    int i = blockIdx.x * blockDim.x + threadIdx.x;
    if (i >= n4) return;
    float4 v = ((const float4*)in)[i];
    v.x = tf32r(v.x); v.y = tf32r(v.y); v.z = tf32r(v.z); v.w = tf32r(v.w);
    ((float4*)g_xt)[i] = v;
}

// ---------------- transpose + tf32-round all 4 weights -----------------------
__global__ void wtrans(const float* __restrict__ W0, const float* __restrict__ W1,
                       const float* __restrict__ W2, const float* __restrict__ W3)
{
    __shared__ float t[32][33];
    const int z = blockIdx.z;
    const float* W = (z == 0) ? W0 : (z == 1) ? W1 : (z == 2) ? W2 : W3;
    float* out = g_wt + (size_t)z * GN * GK;
    const int k0 = blockIdx.y * 32, n0 = blockIdx.x * 32;
    for (int i = threadIdx.y; i < 32; i += 8)
        t[i][threadIdx.x] = W[(size_t)(k0 + i) * GN + n0 + threadIdx.x];
    __syncthreads();
    for (int i = threadIdx.y; i < 32; i += 8)
        out[(size_t)(n0 + i) * GK + k0 + threadIdx.x] = tf32r(t[threadIdx.x][i]);
}

// ---------------- proj split (padded to RT rows, zero fill) ------------------
__global__ void psplit(const float* __restrict__ proj)
{
    int i = blockIdx.x * 256 + threadIdx.x;
    if (i >= RT * 64) return;
    int r = i >> 6, d = i & 63;
    float v = (r < RR) ? proj[r * 64 + d] : 0.0f;
    __nv_bfloat16 h, l;
    split2(v, h, l);
    g_projh[i] = h;
    g_projl[i] = l;
}

// ---------------- featmap HMMA (k only): kpT + ksum, staged stores -----------
__global__ __launch_bounds__(256, 2) void featmap_hmma()
{
    extern __shared__ char smem[];
    const int tid = threadIdx.x, wid = tid >> 5, lane = tid & 31;
    const int n0 = blockIdx.x * 128;
    const int bh = blockIdx.y;
    const int b = bh >> 4, h = bh & 15;
    const size_t abase = ((size_t)(b * NN + n0)) * GK + h * 64;

    const uint32_t sA_h = smem_u32(smem);
    const uint32_t sA_l = sA_h + 128 * 144;
    const uint32_t sP   = sA_h + 2 * 128 * 144;

    auto load_proj = [&](int r0i, int slot) {
        #pragma unroll
        for (int i = 0; i < 4; i++) {
            int idx = tid + i * 256;
            int row = (idx & 511) >> 3, c = idx & 7;
            uint32_t dst = sP + slot * 18432 + (idx < 512 ? 0 : 9216)
                         + row * 144 + c * 16;
            const __nv_bfloat16* src = (idx < 512 ? g_projh : g_projl)
                                       + (r0i * 64 + row) * 64 + c * 8;
            cpa16(dst, src);
        }
        asm volatile("cp.async.commit_group;" ::: "memory");
    };

    #pragma unroll
    for (int i = 0; i < 8; i++) {
        int idx = tid + i * 256;
        int row = (idx & 1023) >> 3, c = idx & 7;
        uint32_t dst = (idx < 1024 ? sA_h : sA_l) + row * 144 + c * 16;
        const __nv_bfloat16* src = (idx < 1024 ? g_kh : g_kl) + abase
                                   + (size_t)row * GK + c * 8;
        cpa16(dst, src);
    }
    load_proj(0, 0);
    load_proj(1, 1);

    const int wr = wid >> 2, wc = wid & 3;
    const int qr = lane >> 2, qc = lane & 3;

    for (int r0i = 0; r0i < 5; r0i++) {
        if (r0i < 4) { asm volatile("cp.async.wait_group 1;" ::: "memory"); }
        else         { asm volatile("cp.async.wait_group 0;" ::: "memory"); }
        __syncthreads();

        const uint32_t pH = sP + (r0i & 1) * 18432;
        const uint32_t pL = pH + 9216;

        float acc[4][2][4] = {};
        #pragma unroll
        for (int kt = 0; kt < 4; kt++) {
            uint32_t bh1[4], bl1[4];
            const int g = lane >> 3;
            const int brow = wc * 16 + (lane & 7) + (g >> 1) * 8;
            const uint32_t bk = (uint32_t)(kt * 16 + (g & 1) * 8) * 2;
            ldsm4(bh1, pH + (uint32_t)brow * 144 + bk);
            ldsm4(bl1, pL + (uint32_t)brow * 144 + bk);
            const int arow = wr * 64 + (lane & 15);
            const uint32_t ak = (uint32_t)(kt * 16 + (lane >> 4) * 8) * 2;
            #pragma unroll
            for (int mt = 0; mt < 4; mt++) {
                uint32_t ah[4], al[4];
                ldsm4(ah, sA_h + (uint32_t)(arow + mt * 16) * 144 + ak);
                ldsm4(al, sA_l + (uint32_t)(arow + mt * 16) * 144 + ak);
                #pragma unroll
                for (int nt = 0; nt < 2; nt++) {
                    mma16816(acc[mt][nt], ah, &bh1[nt * 2]);
                    mma16816(acc[mt][nt], ah, &bl1[nt * 2]);
                    mma16816(acc[mt][nt], al, &bh1[nt * 2]);
                }
            }
        }
        __syncthreads();
        if (r0i + 2 < 5) load_proj(r0i + 2, r0i & 1);

        #pragma unroll
        for (int nt = 0; nt < 2; nt++) {
            int rloc = wc * 16 + nt * 8 + qc * 2;
            int rglob = r0i * 64 + rloc;
            bool valid = (rglob < RR);
            float s0 = 0.f, s1 = 0.f;
            #pragma unroll
            for (int mt = 0; mt < 4; mt++)
                #pragma unroll
                for (int hf = 0; hf < 2; hf++) {
                    int nloc = wr * 64 + mt * 16 + qr + hf * 8;
                    float v0 = acc[mt][nt][hf * 2 + 0];
                    float v1 = acc[mt][nt][hf * 2 + 1];
                    v0 = valid ? (fmaxf(v0, 0.0f) + EPSF) : 0.0f;
                    v1 = valid ? (fmaxf(v1, 0.0f) + EPSF) : 0.0f;
                    __nv_bfloat16 h0, l0, h1, l1;
                    split2(v0, h0, l0);
                    split2(v1, h1, l1);
                    *(__nv_bfloat16*)(smem + FM_STG + rloc * 272 + nloc * 2) = h0;
                    *(__nv_bfloat16*)(smem + FM_STG + (rloc + 1) * 272 + nloc * 2) = h1;
                    *(__nv_bfloat16*)(smem + FM_STG + 17408 + rloc * 272 + nloc * 2) = l0;
                    *(__nv_bfloat16*)(smem + FM_STG + 17408 + (rloc + 1) * 272 + nloc * 2) = l1;
                    s0 += v0;
                    s1 += v1;
                }
            if (valid) {
                atomicAdd(&g_ksum[bh * RP + rglob], s0);
                atomicAdd(&g_ksum[bh * RP + rglob + 1], s1);
            }
        }
        __syncthreads();

        const size_t kb = (size_t)bh * RT * NN;
        #pragma unroll
        for (int j = 0; j < 4; j++) {
            int idx = tid + j * 256;
            int rr = idx >> 4, c16 = idx & 15;
            float4 vh = *(float4*)(smem + FM_STG + rr * 272 + c16 * 16);
            float4 vl = *(float4*)(smem + FM_STG + 17408 + rr * 272 + c16 * 16);
            size_t o = kb + (size_t)(r0i * 64 + rr) * NN + n0 + c16 * 8;
            *(float4*)&g_kpTh[o] = vh;
            *(float4*)&g_kpTl[o] = vl;
        }
    }
}

// ---------------- kv HMMA: kvacc[khalf][bh][r][d] = kpT @ v ------------------
__global__ __launch_bounds__(256, 2) void kv_hmma()
{
    extern __shared__ char smem[];
    const int tid = threadIdx.x, wid = tid >> 5, lane = tid & 31;
    const int bh = blockIdx.x, rhalf = blockIdx.y, khalf = blockIdx.z;
    const int b = bh >> 4, h = bh & 15;

    const __nv_bfloat16* __restrict__ Ahb =
        g_kpTh + ((size_t)bh * RT + rhalf * 160) * NN + khalf * 2048;
    const __nv_bfloat16* __restrict__ Alb =
        g_kpTl + ((size_t)bh * RT + rhalf * 160) * NN + khalf * 2048;
    const __nv_bfloat16* __restrict__ Bhb =
        g_vh + ((size_t)(b * NN + khalf * 2048)) * GK + h * 64;
    const __nv_bfloat16* __restrict__ Blb =
        g_vl + ((size_t)(b * NN + khalf * 2048)) * GK + h * 64;

    const int wm = wid >> 2, wn = wid & 3;
    float acc[5][2][4] = {};

    auto load_stage = [&](int c, int st) {
        const int k0 = c * 32;
        char* sb = smem + st * KV_STAGE;
        #pragma unroll
        for (int i = 0; i < 7; i++) {
            int idx = tid + i * 256;
            uint32_t dst;
            const __nv_bfloat16* src;
            if (idx < 640) {
                int row = idx >> 2, cc = idx & 3;
                dst = smem_u32(sb + row * 80 + cc * 16);
                src = Ahb + (size_t)row * NN + k0 + cc * 8;
            } else if (idx < 1280) {
                int j = idx - 640; int row = j >> 2, cc = j & 3;
                dst = smem_u32(sb + 12800 + row * 80 + cc * 16);
                src = Alb + (size_t)row * NN + k0 + cc * 8;
            } else if (idx < 1536) {
                int j = idx - 1280; int row = j >> 3, cc = j & 7;
                dst = smem_u32(sb + 25600 + row * 144 + cc * 16);
                src = Bhb + (size_t)(k0 + row) * GK + cc * 8;
            } else {
                int j = idx - 1536; int row = j >> 3, cc = j & 7;
                dst = smem_u32(sb + 25600 + 4608 + row * 144 + cc * 16);
                src = Blb + (size_t)(k0 + row) * GK + cc * 8;
            }
            cpa16(dst, src);
        }
        asm volatile("cp.async.commit_group;" ::: "memory");
    };

    load_stage(0, 0);

    for (int c = 0; c < 64; c++) {
        if (c + 1 < 64) {
            load_stage(c + 1, (c + 1) & 1);
            asm volatile("cp.async.wait_group 1;" ::: "memory");
        } else {
            asm volatile("cp.async.wait_group 0;" ::: "memory");
        }
        __syncthreads();

        const int st = c & 1;
        const uint32_t aH = smem_u32(smem + st * KV_STAGE);
        const uint32_t aL = aH + 12800;
        const uint32_t bHs = aH + 25600;
        const uint32_t bLs = bHs + 4608;

        #pragma unroll
        for (int kt = 0; kt < 2; kt++) {
            uint32_t bhf[4], blf[4];
            const int g = lane >> 3;
            const int browk = kt * 16 + (g & 1) * 8 + (lane & 7);
            const uint32_t bc = (uint32_t)(wn * 16 + (g >> 1) * 8) * 2;
            ldsm4t(bhf, bHs + (uint32_t)browk * 144 + bc);
            ldsm4t(blf, bLs + (uint32_t)browk * 144 + bc);
            const int arow = wm * 80 + (lane & 15);
            const uint32_t ak = (uint32_t)(kt * 16 + (lane >> 4) * 8) * 2;
            #pragma unroll
            for (int mt = 0; mt < 5; mt++) {
                uint32_t ah[4], al[4];
                ldsm4(ah, aH + (uint32_t)(arow + mt * 16) * 80 + ak);
                ldsm4(al, aL + (uint32_t)(arow + mt * 16) * 80 + ak);
                #pragma unroll
                for (int nt = 0; nt < 2; nt++) {
                    mma16816(acc[mt][nt], ah, &bhf[nt * 2]);
                    mma16816(acc[mt][nt], ah, &blf[nt * 2]);
                    mma16816(acc[mt][nt], al, &bhf[nt * 2]);
                }
            }
        }
        __syncthreads();
    }

    const int qr = lane >> 2, qc = lane & 3;
    float* outp = g_kvacc + ((size_t)(khalf * BHN + bh)) * RT * 64;
    #pragma unroll
    for (int mt = 0; mt < 5; mt++)
        #pragma unroll
        for (int nt = 0; nt < 2; nt++) {
            int r = rhalf * 160 + wm * 80 + mt * 16 + qr;
            int d = wn * 16 + nt * 8 + qc * 2;
            #pragma unroll
            for (int hf = 0; hf < 2; hf++) {
                float2 v = {acc[mt][nt][hf * 2 + 0], acc[mt][nt][hf * 2 + 1]};
                *(float2*)&outp[(size_t)(r + hf * 8) * 64 + d] = v;
            }
        }
}

// ---------------- kv finalize: sum khalves, transpose -> kvT[d][r] h/l -------
__global__ void kv_finalize()
{
    __shared__ float t[64][65];
    const int bh = blockIdx.x, rblk = blockIdx.y;
    const int tid = threadIdx.x;
    const float* a0 = g_kvacc + ((size_t)bh * RT + rblk * 64) * 64;
    const float* a1 = g_kvacc + ((size_t)(BHN + bh) * RT + rblk * 64) * 64;
    #pragma unroll
    for (int i = 0; i < 16; i++) {
        int e = tid + i * 256;
        t[e >> 6][e & 63] = a0[e] + a1[e];
    }
    __syncthreads();
    const int d = tid >> 2, rs = (tid & 3) * 16;
    const size_t ob = ((size_t)bh * 64 + d) * RP;
    #pragma unroll
    for (int j = 0; j < 16; j += 2) {
        int rg = rblk * 64 + rs + j;
        if (rg >= RP) break;
        __nv_bfloat16 h0, l0, h1, l1;
        split2(t[rs + j][d], h0, l0);
        split2(t[rs + j + 1][d], h1, l1);
        *(__nv_bfloat162*)&g_kvTh[ob + rg] = __nv_bfloat162{h0, h1};
        *(__nv_bfloat162*)&g_kvTl[ob + rg] = __nv_bfloat162{l0, l1};
    }
}

// ---------------- qkv_fused: QP in smem, om = QP@kvT*dinv -> g_om fp32 -------
__global__ __launch_bounds__(256, 2) void qkv_fused()
{
    extern __shared__ char smem[];
    __shared__ float ksumS[RP];
    __shared__ float dpart[2][128];
    __shared__ float dinvS[128];
    const int tid = threadIdx.x, wid = tid >> 5, lane = tid & 31;
    const int n0 = blockIdx.x * 128;
    const int bh = blockIdx.y;
    const int b = bh >> 4, h = bh & 15;
    const uint32_t sb = smem_u32(smem);

    const size_t qbase = ((size_t)(b * NN + n0)) * GK + h * 64;
    const __nv_bfloat16* __restrict__ Bhg = g_kvTh + (size_t)bh * 64 * RP;
    const __nv_bfloat16* __restrict__ Blg = g_kvTl + (size_t)bh * 64 * RP;

    for (int i = tid; i < RP; i += 256) ksumS[i] = g_ksum[bh * RP + i];

    #pragma unroll
    for (int i = 0; i < 8; i++) {
        int idx = tid + i * 256;
        int row = (idx & 1023) >> 3, c = idx & 7;
        uint32_t dst = sb + (idx < 1024 ? QF_SQH : QF_SQL) + row * 144 + c * 16;
        const __nv_bfloat16* src = (idx < 1024 ? g_qh : g_ql) + qbase
                                   + (size_t)row * GK + c * 8;
        cpa16(dst, src);
    }

    auto load_chunk = [&](int c, int slot) {
        #pragma unroll
        for (int i = 0; i < 2; i++) {
            int idx = tid + i * 256;
            int row = (idx & 255) >> 3, cc = idx & 7;
            uint32_t dst = sb + QF_PROJ + slot * 9216 + (idx < 256 ? 0 : 4608)
                         + row * 144 + cc * 16;
            const __nv_bfloat16* src = (idx < 256 ? g_projh : g_projl)
                                       + (c * 32 + row) * 64 + cc * 8;
            cpa16(dst, src);
        }
        #pragma unroll
        for (int i = 0; i < 2; i++) {
            int idx = tid + i * 256;
            int row = (idx & 255) >> 2, cc = idx & 3;
            uint32_t dst = sb + QF_KVT + slot * 10240 + (idx < 256 ? 0 : 5120)
                         + row * 80 + cc * 16;
            const __nv_bfloat16* src = (idx < 256 ? Bhg : Blg)
                                       + (size_t)row * RP + c * 32 + cc * 8;
            cpa16(dst, src);
        }
        asm volatile("cp.async.commit_group;" ::: "memory");
    };

    load_chunk(0, 0);
    load_chunk(1, 1);

    float accO[4][2][4] = {};
    float myd = 0.f;
    const int drow = tid & 127, dhalf = tid >> 7;
    const int wrq = wid >> 1, wcq = wid & 1;
    const int wr = wid >> 2, wc = wid & 3;
    const int qr = lane >> 2, qc = lane & 3;

    for (int c = 0; c < 9; c++) {
        if (c < 8) { asm volatile("cp.async.wait_group 1;" ::: "memory"); }
        else       { asm volatile("cp.async.wait_group 0;" ::: "memory"); }
        __syncthreads();

        const uint32_t pH = sb + QF_PROJ + (c & 1) * 9216;
        const uint32_t pL = pH + 4608;

        float accQ[2][2][4] = {};
        #pragma unroll
        for (int kt = 0; kt < 4; kt++) {
            uint32_t bh1[4], bl1[4];
            const int g = lane >> 3;
            const int brow = wcq * 16 + (lane & 7) + (g >> 1) * 8;
            const uint32_t bk = (uint32_t)(kt * 16 + (g & 1) * 8) * 2;
            ldsm4(bh1, pH + (uint32_t)brow * 144 + bk);
            ldsm4(bl1, pL + (uint32_t)brow * 144 + bk);
            const int arow = wrq * 32 + (lane & 15);
            const uint32_t ak = (uint32_t)(kt * 16 + (lane >> 4) * 8) * 2;
            #pragma unroll
            for (int mt = 0; mt < 2; mt++) {
                uint32_t ah[4], al[4];
                ldsm4(ah, sb + QF_SQH + (uint32_t)(arow + mt * 16) * 144 + ak);
                ldsm4(al, sb + QF_SQL + (uint32_t)(arow + mt * 16) * 144 + ak);
                #pragma unroll
                for (int nt = 0; nt < 2; nt++) {
                    mma16816(accQ[mt][nt], ah, &bh1[nt * 2]);
                    mma16816(accQ[mt][nt], ah, &bl1[nt * 2]);
                    mma16816(accQ[mt][nt], al, &bh1[nt * 2]);
                }
            }
        }
        #pragma unroll
        for (int mt = 0; mt < 2; mt++)
            #pragma unroll
            for (int nt = 0; nt < 2; nt++) {
                int rcol = wcq * 16 + nt * 8 + qc * 2;
                #pragma unroll
                for (int hf = 0; hf < 2; hf++) {
                    int row = wrq * 32 + mt * 16 + qr + hf * 8;
                    float v0 = fmaxf(accQ[mt][nt][hf * 2 + 0], 0.0f) + EPSF;
                    float v1 = fmaxf(accQ[mt][nt][hf * 2 + 1], 0.0f) + EPSF;
                    __nv_bfloat16 h0, l0, h1, l1;
                    split2(v0, h0, l0);
                    split2(v1, h1, l1);
                    *(__nv_bfloat162*)(smem + QF_SQPH + row * 80 + rcol * 2)
                        = __nv_bfloat162{h0, h1};
                    *(__nv_bfloat162*)(smem + QF_SQPL + row * 80 + rcol * 2)
                        = __nv_bfloat162{l0, l1};
                }
            }
        __syncthreads();

        {
            const __nv_bfloat16* ph = (const __nv_bfloat16*)(smem + QF_SQPH
                                        + drow * 80 + dhalf * 32);
            const __nv_bfloat16* pl = (const __nv_bfloat16*)(smem + QF_SQPL
                                        + drow * 80 + dhalf * 32);
            const float* ksp = ksumS + c * 32 + dhalf * 16;
            #pragma unroll
            for (int kk = 0; kk < 16; kk++) {
                float v = __bfloat162float(ph[kk]) + __bfloat162float(pl[kk]);
                myd += v * ksp[kk];
            }
        }

        const uint32_t aH = sb + QF_SQPH, aL = sb + QF_SQPL;
        const uint32_t bHc = sb + QF_KVT + (c & 1) * 10240;
        const uint32_t bLc = bHc + 5120;
        #pragma unroll
        for (int kt = 0; kt < 2; kt++) {
            uint32_t bh1[4], bl1[4];
            const int g = lane >> 3;
            const int brow = wc * 16 + (lane & 7) + (g >> 1) * 8;
            const uint32_t bk = (uint32_t)(kt * 16 + (g & 1) * 8) * 2;
            ldsm4(bh1, bHc + (uint32_t)brow * 80 + bk);
            ldsm4(bl1, bLc + (uint32_t)brow * 80 + bk);
            const int arow = wr * 64 + (lane & 15);
            const uint32_t ak = (uint32_t)(kt * 16 + (lane >> 4) * 8) * 2;
            #pragma unroll
            for (int mt = 0; mt < 4; mt++) {
                uint32_t ah[4], al[4];
                ldsm4(ah, aH + (uint32_t)(arow + mt * 16) * 80 + ak);
                ldsm4(al, aL + (uint32_t)(arow + mt * 16) * 80 + ak);
                #pragma unroll
                for (int nt = 0; nt < 2; nt++) {
                    mma16816(accO[mt][nt], ah, &bh1[nt * 2]);
                    mma16816(accO[mt][nt], ah, &bl1[nt * 2]);
                    mma16816(accO[mt][nt], al, &bh1[nt * 2]);
                }
            }
        }
        __syncthreads();
        if (c + 2 < 9) load_chunk(c + 2, c & 1);
    }

    dpart[dhalf][drow] = myd;
    __syncthreads();
    if (tid < 128) dinvS[tid] = 1.0f / (dpart[0][tid] + dpart[1][tid]);
    __syncthreads();

    #pragma unroll
    for (int mt = 0; mt < 4; mt++)
        #pragma unroll
        for (int nt = 0; nt < 2; nt++) {
            int d = wc * 16 + nt * 8 + qc * 2;
            #pragma unroll
            for (int hf = 0; hf < 2; hf++) {
                int lrow = wr * 64 + mt * 16 + qr + hf * 8;
                float di = dinvS[lrow];
                float2 v;
                v.x = tf32r(accO[mt][nt][hf * 2 + 0] * di);
                v.y = tf32r(accO[mt][nt][hf * 2 + 1] * di);
                *(float2*)(smem + QF_STF + lrow * 272 + d * 4) = v;
            }
        }
    __syncthreads();
    #pragma unroll
    for (int j = 0; j < 8; j++) {
        int idx = tid + j * 256;
        int rr = idx >> 4, c16 = idx & 15;
        float4 v = *(float4*)(smem + QF_STF + rr * 272 + c16 * 16);
        size_t o = ((size_t)(b * NN + n0 + rr)) * GK + h * 64 + c16 * 4;
        *(float4*)&g_om[o] = v;
    }
}

// ---------------- launch -----------------------------------------------------
extern "C" void kernel_launch(void* const* d_in, const int* in_sizes, int n_in,
                              void* d_out, int out_size)
{
    const float* x    = (const float*)d_in[0];
    const float* Wq   = (const float*)d_in[1];
    const float* Wk   = (const float*)d_in[2];
    const float* Wv   = (const float*)d_in[3];
    const float* Wo   = (const float*)d_in[4];
    const float* bo   = (const float*)d_in[5];
    const float* proj = (const float*)d_in[6];

    float *ksum, *xt, *wt, *om;
    cudaGetSymbolAddress((void**)&ksum, g_ksum);
    cudaGetSymbolAddress((void**)&xt,   g_xt);
    cudaGetSymbolAddress((void**)&wt,   g_wt);
    cudaGetSymbolAddress((void**)&om,   g_om);

    cudaFuncSetAttribute(gemm_tf32,
                         cudaFuncAttributeMaxDynamicSharedMemorySize, SMEMT);
    cudaFuncSetAttribute(featmap_hmma,
                         cudaFuncAttributeMaxDynamicSharedMemorySize, FM_SMEM);
    cudaFuncSetAttribute(kv_hmma,
                         cudaFuncAttributeMaxDynamicSharedMemorySize, KV_SMEM);
    cudaFuncSetAttribute(qkv_fused,
                         cudaFuncAttributeMaxDynamicSharedMemorySize, QF_SMEM);

    const int n4 = GM * GK / 4;

    xcvt<<<(n4 + 255) / 256, 256>>>(x, n4);
    wtrans<<<dim3(32, 32, 4), dim3(32, 8)>>>(Wq, Wk, Wv, Wo);
    psplit<<<80, 256>>>(proj);
    cudaMemsetAsync(ksum, 0, BHN * RP * sizeof(float));

    gemm_tf32<<<dim3(24, GM / 128), 256, SMEMT>>>(xt, wt, nullptr, nullptr, 0);

    featmap_hmma<<<dim3(32, 64), 256, FM_SMEM>>>();

    kv_hmma<<<dim3(BHN, 2, 2), 256, KV_SMEM>>>();

    kv_finalize<<<dim3(BHN, 5), 256>>>();

    qkv_fused<<<dim3(32, BHN), 256, QF_SMEM>>>();

    gemm_tf32<<<dim3(8, GM / 128), 256, SMEMT>>>(om, wt + 3 * (size_t)GN * GK,
                                                 bo, (float*)d_out, 1);
}

// round 16
// speedup vs baseline: 2.5352x; 1.0487x over previous
#include <cuda_runtime.h>
#include <cuda_bf16.h>
#include <cstdint>

#define BB 4
#define NN 4096
#define CC 1024
#define HH 16
#define DH 64
#define RR 266
#define RP 288
#define RT 320
#define EPSF 1e-3f
#define BHN (BB*HH)   // 64
#define GM (BB*NN)    // 16384
#define GK 1024
#define GN 1024
// tf32 gemm: K-chunk 32, 2 matrices/stage (128 rows x 144B each), 3 stages
#define TMAT 18432
#define TSTAGE (2*TMAT)           // 36864
#define SMEMT (3*TSTAGE)          // 110592 (covers epilogue staging 69632)
// featmap smem
#define FM_STG 73728
#define FM_SMEM (FM_STG + 2*64*272)   // 108544
// kv smem: 3 stages
#define KV_STAGE (2*160*80 + 2*32*144)   // 34816
#define KV_SMEM (3*KV_STAGE)             // 104448
// qkv_fused smem layout
#define QF_SQH  0
#define QF_SQL  18432
#define QF_SQPH 36864
#define QF_SQPL 47104
#define QF_PROJ 57344
#define QF_KVT  75776
#define QF_STF  57344
#define QF_SMEM 96256

// ---------------- scratch (device globals; no allocation allowed) ----------
__device__ float g_ksum[BHN*RP];
__device__ float g_kvacc[(size_t)2*BHN*RT*64];
__device__ float g_xt[(size_t)GM*GK];
__device__ float g_wt[(size_t)4*GN*GK];
__device__ float g_om[(size_t)GM*GK];
__device__ __nv_bfloat16 g_qh[(size_t)GM*GK];
__device__ __nv_bfloat16 g_ql[(size_t)GM*GK];
__device__ __nv_bfloat16 g_kh[(size_t)GM*GK];
__device__ __nv_bfloat16 g_kl[(size_t)GM*GK];
__device__ __nv_bfloat16 g_vh[(size_t)GM*GK];
__device__ __nv_bfloat16 g_vl[(size_t)GM*GK];
__device__ __nv_bfloat16 g_projh[RT*64];
__device__ __nv_bfloat16 g_projl[RT*64];
__device__ __nv_bfloat16 g_kpTh[(size_t)BHN*RT*NN];
__device__ __nv_bfloat16 g_kpTl[(size_t)BHN*RT*NN];
__device__ __nv_bfloat16 g_kvTh[BHN*64*RP];
__device__ __nv_bfloat16 g_kvTl[BHN*64*RP];

// ---------------- helpers ----------------------------------------------------
__device__ __forceinline__ uint32_t smem_u32(const void* p) {
    uint32_t a;
    asm("{ .reg .u64 t; cvta.to.shared.u64 t, %1; cvt.u32.u64 %0, t; }"
        : "=r"(a) : "l"(p));
    return a;
}
__device__ __forceinline__ void cpa16(uint32_t dst, const void* src) {
    asm volatile("cp.async.cg.shared.global [%0], [%1], 16;" :: "r"(dst), "l"(src));
}
__device__ __forceinline__ void ldsm4(uint32_t* r, uint32_t addr) {
    asm volatile("ldmatrix.sync.aligned.m8n8.x4.shared.b16 {%0,%1,%2,%3}, [%4];"
        : "=r"(r[0]), "=r"(r[1]), "=r"(r[2]), "=r"(r[3]) : "r"(addr));
}
__device__ __forceinline__ void ldsm4t(uint32_t* r, uint32_t addr) {
    asm volatile("ldmatrix.sync.aligned.m8n8.x4.trans.shared.b16 {%0,%1,%2,%3}, [%4];"
        : "=r"(r[0]), "=r"(r[1]), "=r"(r[2]), "=r"(r[3]) : "r"(addr));
}
__device__ __forceinline__ void mma16816(float* d, const uint32_t* a, const uint32_t* b) {
    asm volatile(
        "mma.sync.aligned.m16n8k16.row.col.f32.bf16.bf16.f32 "
        "{%0,%1,%2,%3}, {%4,%5,%6,%7}, {%8,%9}, {%0,%1,%2,%3};"
        : "+f"(d[0]), "+f"(d[1]), "+f"(d[2]), "+f"(d[3])
        : "r"(a[0]), "r"(a[1]), "r"(a[2]), "r"(a[3]), "r"(b[0]), "r"(b[1]));
}
__device__ __forceinline__ void mma_tf32(float* d, const uint32_t* a, const uint32_t* b) {
    asm volatile(
        "mma.sync.aligned.m16n8k8.row.col.f32.tf32.tf32.f32 "
        "{%0,%1,%2,%3}, {%4,%5,%6,%7}, {%8,%9}, {%0,%1,%2,%3};"
        : "+f"(d[0]), "+f"(d[1]), "+f"(d[2]), "+f"(d[3])
        : "r"(a[0]), "r"(a[1]), "r"(a[2]), "r"(a[3]), "r"(b[0]), "r"(b[1]));
}
__device__ __forceinline__ void split2(float v, __nv_bfloat16& h, __nv_bfloat16& l) {
    h = __float2bfloat16(v);
    l = __float2bfloat16(v - __bfloat162float(h));
}
__device__ __forceinline__ float tf32r(float v) {
    uint32_t r;
    asm("cvt.rna.tf32.f32 %0, %1;" : "=r"(r) : "f"(v));
    return __uint_as_float(r);
}

// ---------------- TF32 GEMM: KC=32, 3-stage, 1 sync/chunk --------------------
// mode 0: merged QKV (grid x = 24); mode 1: final (grid x = 8) fp32 + bias
__global__ __launch_bounds__(256, 2) void gemm_tf32(
    const float* __restrict__ A, const float* __restrict__ Bt,
    const float* __restrict__ bias, float* __restrict__ Cf, int mode)
{
    extern __shared__ char smem[];
    const int tid = threadIdx.x;
    const int wid = tid >> 5, lane = tid & 31;
    const int m0 = blockIdx.y * 128, n0 = blockIdx.x * 128;
    const int wr = wid >> 2, wc = wid & 3;

    const float* gA = A + (size_t)m0 * GK;
    const float* gB = Bt + (size_t)n0 * GK;

    float acc[4][4][4] = {};

    auto load_stage = [&](int c, int st) {
        const int k0 = c * 32;
        char* dstb = smem + st * TSTAGE;
        #pragma unroll
        for (int i = 0; i < 8; i++) {
            int idx = tid + i * 256;
            int mat = idx >> 10;
            int row = (idx >> 3) & 127;
            int c16 = idx & 7;
            uint32_t dst = smem_u32(dstb + mat * TMAT + row * 144 + c16 * 16);
            const float* g = mat ? gB : gA;
            cpa16(dst, g + (size_t)row * GK + k0 + c16 * 4);
        }
        asm volatile("cp.async.commit_group;" ::: "memory");
    };

    load_stage(0, 0);
    load_stage(1, 1);

    int st = 0;       // c % 3
    int nst = 2;      // (c+2) % 3
    for (int c = 0; c < 32; c++) {
        if (c + 2 < 32) { asm volatile("cp.async.wait_group 1;" ::: "memory"); }
        else            { asm volatile("cp.async.wait_group 0;" ::: "memory"); }
        __syncthreads();
        if (c + 2 < 32) load_stage(c + 2, nst);

        const uint32_t aB = smem_u32(smem + st * TSTAGE);
        const uint32_t bB = aB + TMAT;

        #pragma unroll
        for (int kt = 0; kt < 4; kt++) {
            uint32_t bf[2][4];
            const int g = lane >> 3;
            const int brow = wc * 32 + (lane & 7) + (g >> 1) * 8;
            const uint32_t bkoff = (uint32_t)(kt * 16 + (g & 1) * 8) * 2;
            #pragma unroll
            for (int nt2 = 0; nt2 < 2; nt2++)
                ldsm4(bf[nt2], bB + (uint32_t)(brow + nt2 * 16) * 144 + bkoff);
            const int arow = wr * 64 + (lane & 15);
            const uint32_t akoff = (uint32_t)(kt * 16 + (lane >> 4) * 8) * 2;
            #pragma unroll
            for (int mt = 0; mt < 4; mt++) {
                uint32_t af[4];
                ldsm4(af, aB + (uint32_t)(arow + mt * 16) * 144 + akoff);
                #pragma unroll
                for (int nt = 0; nt < 4; nt++)
                    mma_tf32(acc[mt][nt], af, &bf[nt >> 1][(nt & 1) * 2]);
            }
        }
        st = (st == 2) ? 0 : st + 1;
        nst = (nst == 2) ? 0 : nst + 1;
    }
    __syncthreads();   // protect epilogue staging vs last compute reads

    const int qr = lane >> 2, qc = lane & 3;
    if (mode == 1) {
        #pragma unroll
        for (int mt = 0; mt < 4; mt++)
            #pragma unroll
            for (int nt = 0; nt < 4; nt++) {
                int row = m0 + wr * 64 + mt * 16 + qr;
                int col = n0 + wc * 32 + nt * 8 + qc * 2;
                float bx = bias[col], by = bias[col + 1];
                float2 v0 = {acc[mt][nt][0] + bx, acc[mt][nt][1] + by};
                float2 v1 = {acc[mt][nt][2] + bx, acc[mt][nt][3] + by};
                *(float2*)&Cf[(size_t)row * GN + col] = v0;
                *(float2*)&Cf[(size_t)(row + 8) * GN + col] = v1;
            }
    } else {
        __nv_bfloat16 *och, *ocl;
        int cbase;
        if (n0 < 1024)      { och = g_qh; ocl = g_ql; cbase = n0; }
        else if (n0 < 2048) { och = g_kh; ocl = g_kl; cbase = n0 - 1024; }
        else                { och = g_vh; ocl = g_vl; cbase = n0 - 2048; }
        #pragma unroll
        for (int mt = 0; mt < 4; mt++)
            #pragma unroll
            for (int nt = 0; nt < 4; nt++) {
                int coll = wc * 32 + nt * 8 + qc * 2;
                #pragma unroll
                for (int hf = 0; hf < 2; hf++) {
                    int rowl = wr * 64 + mt * 16 + qr + hf * 8;
                    __nv_bfloat16 h0, l0, h1, l1;
                    split2(acc[mt][nt][hf * 2 + 0], h0, l0);
                    split2(acc[mt][nt][hf * 2 + 1], h1, l1);
                    *(__nv_bfloat162*)(smem + rowl * 272 + coll * 2)
                        = __nv_bfloat162{h0, h1};
                    *(__nv_bfloat162*)(smem + 34816 + rowl * 272 + coll * 2)
                        = __nv_bfloat162{l0, l1};
                }
            }
        __syncthreads();
        #pragma unroll
        for (int j = 0; j < 8; j++) {
            int idx = tid + j * 256;
            int rr = idx >> 4, c16 = idx & 15;
            float4 vh = *(float4*)(smem + rr * 272 + c16 * 16);
            float4 vl = *(float4*)(smem + 34816 + rr * 272 + c16 * 16);
            *(float4*)&och[(size_t)(m0 + rr) * GN + cbase + c16 * 8] = vh;
            *(float4*)&ocl[(size_t)(m0 + rr) * GN + cbase + c16 * 8] = vl;
        }
    }
}

// ---------------- x -> tf32-rounded fp32 -------------------------------------
__global__ __launch_bounds__(256) void xcvt(const float* __restrict__ in, int n4)
{
    int i = blockIdx.x * blockDim.x + threadIdx.x;
    if (i >= n4) return;
    float4 v = ((const float4*)in)[i];
    v.x = tf32r(v.x); v.y = tf32r(v.y); v.z = tf32r(v.z); v.w = tf32r(v.w);
    ((float4*)g_xt)[i] = v;
}

// ---------------- transpose + tf32-round all 4 weights -----------------------
__global__ void wtrans(const float* __restrict__ W0, const float* __restrict__ W1,
                       const float* __restrict__ W2, const float* __restrict__ W3)
{
    __shared__ float t[32][33];
    const int z = blockIdx.z;
    const float* W = (z == 0) ? W0 : (z == 1) ? W1 : (z == 2) ? W2 : W3;
    float* out = g_wt + (size_t)z * GN * GK;
    const int k0 = blockIdx.y * 32, n0 = blockIdx.x * 32;
    for (int i = threadIdx.y; i < 32; i += 8)
        t[i][threadIdx.x] = W[(size_t)(k0 + i) * GN + n0 + threadIdx.x];
    __syncthreads();
    for (int i = threadIdx.y; i < 32; i += 8)
        out[(size_t)(n0 + i) * GK + k0 + threadIdx.x] = tf32r(t[threadIdx.x][i]);
}

// ---------------- proj split (padded to RT rows, zero fill) ------------------
__global__ void psplit(const float* __restrict__ proj)
{
    int i = blockIdx.x * 256 + threadIdx.x;
    if (i >= RT * 64) return;
    int r = i >> 6, d = i & 63;
    float v = (r < RR) ? proj[r * 64 + d] : 0.0f;
    __nv_bfloat16 h, l;
    split2(v, h, l);
    g_projh[i] = h;
    g_projl[i] = l;
}

// ---------------- featmap HMMA (k only): kpT + ksum, staged stores -----------
__global__ __launch_bounds__(256, 2) void featmap_hmma()
{
    extern __shared__ char smem[];
    const int tid = threadIdx.x, wid = tid >> 5, lane = tid & 31;
    const int n0 = blockIdx.x * 128;
    const int bh = blockIdx.y;
    const int b = bh >> 4, h = bh & 15;
    const size_t abase = ((size_t)(b * NN + n0)) * GK + h * 64;

    const uint32_t sA_h = smem_u32(smem);
    const uint32_t sA_l = sA_h + 128 * 144;
    const uint32_t sP   = sA_h + 2 * 128 * 144;

    auto load_proj = [&](int r0i, int slot) {
        #pragma unroll
        for (int i = 0; i < 4; i++) {
            int idx = tid + i * 256;
            int row = (idx & 511) >> 3, c = idx & 7;
            uint32_t dst = sP + slot * 18432 + (idx < 512 ? 0 : 9216)
                         + row * 144 + c * 16;
            const __nv_bfloat16* src = (idx < 512 ? g_projh : g_projl)
                                       + (r0i * 64 + row) * 64 + c * 8;
            cpa16(dst, src);
        }
        asm volatile("cp.async.commit_group;" ::: "memory");
    };

    #pragma unroll
    for (int i = 0; i < 8; i++) {
        int idx = tid + i * 256;
        int row = (idx & 1023) >> 3, c = idx & 7;
        uint32_t dst = (idx < 1024 ? sA_h : sA_l) + row * 144 + c * 16;
        const __nv_bfloat16* src = (idx < 1024 ? g_kh : g_kl) + abase
                                   + (size_t)row * GK + c * 8;
        cpa16(dst, src);
    }
    load_proj(0, 0);
    load_proj(1, 1);

    const int wr = wid >> 2, wc = wid & 3;
    const int qr = lane >> 2, qc = lane & 3;

    for (int r0i = 0; r0i < 5; r0i++) {
        if (r0i < 4) { asm volatile("cp.async.wait_group 1;" ::: "memory"); }
        else         { asm volatile("cp.async.wait_group 0;" ::: "memory"); }
        __syncthreads();

        const uint32_t pH = sP + (r0i & 1) * 18432;
        const uint32_t pL = pH + 9216;

        float acc[4][2][4] = {};
        #pragma unroll
        for (int kt = 0; kt < 4; kt++) {
            uint32_t bh1[4], bl1[4];
            const int g = lane >> 3;
            const int brow = wc * 16 + (lane & 7) + (g >> 1) * 8;
            const uint32_t bk = (uint32_t)(kt * 16 + (g & 1) * 8) * 2;
            ldsm4(bh1, pH + (uint32_t)brow * 144 + bk);
            ldsm4(bl1, pL + (uint32_t)brow * 144 + bk);
            const int arow = wr * 64 + (lane & 15);
            const uint32_t ak = (uint32_t)(kt * 16 + (lane >> 4) * 8) * 2;
            #pragma unroll
            for (int mt = 0; mt < 4; mt++) {
                uint32_t ah[4], al[4];
                ldsm4(ah, sA_h + (uint32_t)(arow + mt * 16) * 144 + ak);
                ldsm4(al, sA_l + (uint32_t)(arow + mt * 16) * 144 + ak);
                #pragma unroll
                for (int nt = 0; nt < 2; nt++) {
                    mma16816(acc[mt][nt], ah, &bh1[nt * 2]);
                    mma16816(acc[mt][nt], ah, &bl1[nt * 2]);
                    mma16816(acc[mt][nt], al, &bh1[nt * 2]);
                }
            }
        }
        __syncthreads();
        if (r0i + 2 < 5) load_proj(r0i + 2, r0i & 1);

        #pragma unroll
        for (int nt = 0; nt < 2; nt++) {
            int rloc = wc * 16 + nt * 8 + qc * 2;
            int rglob = r0i * 64 + rloc;
            bool valid = (rglob < RR);
            float s0 = 0.f, s1 = 0.f;
            #pragma unroll
            for (int mt = 0; mt < 4; mt++)
                #pragma unroll
                for (int hf = 0; hf < 2; hf++) {
                    int nloc = wr * 64 + mt * 16 + qr + hf * 8;
                    float v0 = acc[mt][nt][hf * 2 + 0];
                    float v1 = acc[mt][nt][hf * 2 + 1];
                    v0 = valid ? (fmaxf(v0, 0.0f) + EPSF) : 0.0f;
                    v1 = valid ? (fmaxf(v1, 0.0f) + EPSF) : 0.0f;
                    __nv_bfloat16 h0, l0, h1, l1;
                    split2(v0, h0, l0);
                    split2(v1, h1, l1);
                    *(__nv_bfloat16*)(smem + FM_STG + rloc * 272 + nloc * 2) = h0;
                    *(__nv_bfloat16*)(smem + FM_STG + (rloc + 1) * 272 + nloc * 2) = h1;
                    *(__nv_bfloat16*)(smem + FM_STG + 17408 + rloc * 272 + nloc * 2) = l0;
                    *(__nv_bfloat16*)(smem + FM_STG + 17408 + (rloc + 1) * 272 + nloc * 2) = l1;
                    s0 += v0;
                    s1 += v1;
                }
            if (valid) {
                atomicAdd(&g_ksum[bh * RP + rglob], s0);
                atomicAdd(&g_ksum[bh * RP + rglob + 1], s1);
            }
        }
        __syncthreads();

        const size_t kb = (size_t)bh * RT * NN;
        #pragma unroll
        for (int j = 0; j < 4; j++) {
            int idx = tid + j * 256;
            int rr = idx >> 4, c16 = idx & 15;
            float4 vh = *(float4*)(smem + FM_STG + rr * 272 + c16 * 16);
            float4 vl = *(float4*)(smem + FM_STG + 17408 + rr * 272 + c16 * 16);
            size_t o = kb + (size_t)(r0i * 64 + rr) * NN + n0 + c16 * 8;
            *(float4*)&g_kpTh[o] = vh;
            *(float4*)&g_kpTl[o] = vl;
        }
    }
}

// ---------------- kv HMMA: 3-stage, 1 sync/chunk -----------------------------
__global__ __launch_bounds__(256, 2) void kv_hmma()
{
    extern __shared__ char smem[];
    const int tid = threadIdx.x, wid = tid >> 5, lane = tid & 31;
    const int bh = blockIdx.x, rhalf = blockIdx.y, khalf = blockIdx.z;
    const int b = bh >> 4, h = bh & 15;

    const __nv_bfloat16* __restrict__ Ahb =
        g_kpTh + ((size_t)bh * RT + rhalf * 160) * NN + khalf * 2048;
    const __nv_bfloat16* __restrict__ Alb =
        g_kpTl + ((size_t)bh * RT + rhalf * 160) * NN + khalf * 2048;
    const __nv_bfloat16* __restrict__ Bhb =
        g_vh + ((size_t)(b * NN + khalf * 2048)) * GK + h * 64;
    const __nv_bfloat16* __restrict__ Blb =
        g_vl + ((size_t)(b * NN + khalf * 2048)) * GK + h * 64;

    const int wm = wid >> 2, wn = wid & 3;
    float acc[5][2][4] = {};

    auto load_stage = [&](int c, int st) {
        const int k0 = c * 32;
        char* sb = smem + st * KV_STAGE;
        #pragma unroll
        for (int i = 0; i < 7; i++) {
            int idx = tid + i * 256;
            uint32_t dst;
            const __nv_bfloat16* src;
            if (idx < 640) {
                int row = idx >> 2, cc = idx & 3;
                dst = smem_u32(sb + row * 80 + cc * 16);
                src = Ahb + (size_t)row * NN + k0 + cc * 8;
            } else if (idx < 1280) {
                int j = idx - 640; int row = j >> 2, cc = j & 3;
                dst = smem_u32(sb + 12800 + row * 80 + cc * 16);
                src = Alb + (size_t)row * NN + k0 + cc * 8;
            } else if (idx < 1536) {
                int j = idx - 1280; int row = j >> 3, cc = j & 7;
                dst = smem_u32(sb + 25600 + row * 144 + cc * 16);
                src = Bhb + (size_t)(k0 + row) * GK + cc * 8;
            } else {
                int j = idx - 1536; int row = j >> 3, cc = j & 7;
                dst = smem_u32(sb + 25600 + 4608 + row * 144 + cc * 16);
                src = Blb + (size_t)(k0 + row) * GK + cc * 8;
            }
            cpa16(dst, src);
        }
        asm volatile("cp.async.commit_group;" ::: "memory");
    };

    load_stage(0, 0);
    load_stage(1, 1);

    int st = 0, nst = 2;
    for (int c = 0; c < 64; c++) {
        if (c + 2 < 64) { asm volatile("cp.async.wait_group 1;" ::: "memory"); }
        else            { asm volatile("cp.async.wait_group 0;" ::: "memory"); }
        __syncthreads();
        if (c + 2 < 64) load_stage(c + 2, nst);

        const uint32_t aH = smem_u32(smem + st * KV_STAGE);
        const uint32_t aL = aH + 12800;
        const uint32_t bHs = aH + 25600;
        const uint32_t bLs = bHs + 4608;

        #pragma unroll
        for (int kt = 0; kt < 2; kt++) {
            uint32_t bhf[4], blf[4];
            const int g = lane >> 3;
            const int browk = kt * 16 + (g & 1) * 8 + (lane & 7);
            const uint32_t bc = (uint32_t)(wn * 16 + (g >> 1) * 8) * 2;
            ldsm4t(bhf, bHs + (uint32_t)browk * 144 + bc);
            ldsm4t(blf, bLs + (uint32_t)browk * 144 + bc);
            const int arow = wm * 80 + (lane & 15);
            const uint32_t ak = (uint32_t)(kt * 16 + (lane >> 4) * 8) * 2;
            #pragma unroll
            for (int mt = 0; mt < 5; mt++) {
                uint32_t ah[4], al[4];
                ldsm4(ah, aH + (uint32_t)(arow + mt * 16) * 80 + ak);
                ldsm4(al, aL + (uint32_t)(arow + mt * 16) * 80 + ak);
                #pragma unroll
                for (int nt = 0; nt < 2; nt++) {
                    mma16816(acc[mt][nt], ah, &bhf[nt * 2]);
                    mma16816(acc[mt][nt], ah, &blf[nt * 2]);
                    mma16816(acc[mt][nt], al, &bhf[nt * 2]);
                }
            }
        }
        st = (st == 2) ? 0 : st + 1;
        nst = (nst == 2) ? 0 : nst + 1;
    }

    const int qr = lane >> 2, qc = lane & 3;
    float* outp = g_kvacc + ((size_t)(khalf * BHN + bh)) * RT * 64;
    #pragma unroll
    for (int mt = 0; mt < 5; mt++)
        #pragma unroll
        for (int nt = 0; nt < 2; nt++) {
            int r = rhalf * 160 + wm * 80 + mt * 16 + qr;
            int d = wn * 16 + nt * 8 + qc * 2;
            #pragma unroll
            for (int hf = 0; hf < 2; hf++) {
                float2 v = {acc[mt][nt][hf * 2 + 0], acc[mt][nt][hf * 2 + 1]};
                *(float2*)&outp[(size_t)(r + hf * 8) * 64 + d] = v;
            }
        }
}

// ---------------- kv finalize: sum khalves, transpose -> kvT[d][r] h/l -------
__global__ void kv_finalize()
{
    __shared__ float t[64][65];
    const int bh = blockIdx.x, rblk = blockIdx.y;
    const int tid = threadIdx.x;
    const float* a0 = g_kvacc + ((size_t)bh * RT + rblk * 64) * 64;
    const float* a1 = g_kvacc + ((size_t)(BHN + bh) * RT + rblk * 64) * 64;
    #pragma unroll
    for (int i = 0; i < 16; i++) {
        int e = tid + i * 256;
        t[e >> 6][e & 63] = a0[e] + a1[e];
    }
    __syncthreads();
    const int d = tid >> 2, rs = (tid & 3) * 16;
    const size_t ob = ((size_t)bh * 64 + d) * RP;
    #pragma unroll
    for (int j = 0; j < 16; j += 2) {
        int rg = rblk * 64 + rs + j;
        if (rg >= RP) break;
        __nv_bfloat16 h0, l0, h1, l1;
        split2(t[rs + j][d], h0, l0);
        split2(t[rs + j + 1][d], h1, l1);
        *(__nv_bfloat162*)&g_kvTh[ob + rg] = __nv_bfloat162{h0, h1};
        *(__nv_bfloat162*)&g_kvTl[ob + rg] = __nv_bfloat162{l0, l1};
    }
}

// ---------------- qkv_fused: QP in smem, om = QP@kvT*dinv -> g_om fp32 -------
__global__ __launch_bounds__(256, 2) void qkv_fused()
{
    extern __shared__ char smem[];
    __shared__ float ksumS[RP];
    __shared__ float dpart[2][128];
    __shared__ float dinvS[128];
    const int tid = threadIdx.x, wid = tid >> 5, lane = tid & 31;
    const int n0 = blockIdx.x * 128;
    const int bh = blockIdx.y;
    const int b = bh >> 4, h = bh & 15;
    const uint32_t sb = smem_u32(smem);

    const size_t qbase = ((size_t)(b * NN + n0)) * GK + h * 64;
    const __nv_bfloat16* __restrict__ Bhg = g_kvTh + (size_t)bh * 64 * RP;
    const __nv_bfloat16* __restrict__ Blg = g_kvTl + (size_t)bh * 64 * RP;

    for (int i = tid; i < RP; i += 256) ksumS[i] = g_ksum[bh * RP + i];

    #pragma unroll
    for (int i = 0; i < 8; i++) {
        int idx = tid + i * 256;
        int row = (idx & 1023) >> 3, c = idx & 7;
        uint32_t dst = sb + (idx < 1024 ? QF_SQH : QF_SQL) + row * 144 + c * 16;
        const __nv_bfloat16* src = (idx < 1024 ? g_qh : g_ql) + qbase
                                   + (size_t)row * GK + c * 8;
        cpa16(dst, src);
    }

    auto load_chunk = [&](int c, int slot) {
        #pragma unroll
        for (int i = 0; i < 2; i++) {
            int idx = tid + i * 256;
            int row = (idx & 255) >> 3, cc = idx & 7;
            uint32_t dst = sb + QF_PROJ + slot * 9216 + (idx < 256 ? 0 : 4608)
                         + row * 144 + cc * 16;
            const __nv_bfloat16* src = (idx < 256 ? g_projh : g_projl)
                                       + (c * 32 + row) * 64 + cc * 8;
            cpa16(dst, src);
        }
        #pragma unroll
        for (int i = 0; i < 2; i++) {
            int idx = tid + i * 256;
            int row = (idx & 255) >> 2, cc = idx & 3;
            uint32_t dst = sb + QF_KVT + slot * 10240 + (idx < 256 ? 0 : 5120)
                         + row * 80 + cc * 16;
            const __nv_bfloat16* src = (idx < 256 ? Bhg : Blg)
                                       + (size_t)row * RP + c * 32 + cc * 8;
            cpa16(dst, src);
        }
        asm volatile("cp.async.commit_group;" ::: "memory");
    };

    load_chunk(0, 0);
    load_chunk(1, 1);

    float accO[4][2][4] = {};
    float myd = 0.f;
    const int drow = tid & 127, dhalf = tid >> 7;
    const int wrq = wid >> 1, wcq = wid & 1;
    const int wr = wid >> 2, wc = wid & 3;
    const int qr = lane >> 2, qc = lane & 3;

    for (int c = 0; c < 9; c++) {
        if (c < 8) { asm volatile("cp.async.wait_group 1;" ::: "memory"); }
        else       { asm volatile("cp.async.wait_group 0;" ::: "memory"); }
        __syncthreads();

        const uint32_t pH = sb + QF_PROJ + (c & 1) * 9216;
        const uint32_t pL = pH + 4608;

        float accQ[2][2][4] = {};
        #pragma unroll
        for (int kt = 0; kt < 4; kt++) {
            uint32_t bh1[4], bl1[4];
            const int g = lane >> 3;
            const int brow = wcq * 16 + (lane & 7) + (g >> 1) * 8;
            const uint32_t bk = (uint32_t)(kt * 16 + (g & 1) * 8) * 2;
            ldsm4(bh1, pH + (uint32_t)brow * 144 + bk);
            ldsm4(bl1, pL + (uint32_t)brow * 144 + bk);
            const int arow = wrq * 32 + (lane & 15);
            const uint32_t ak = (uint32_t)(kt * 16 + (lane >> 4) * 8) * 2;
            #pragma unroll
            for (int mt = 0; mt < 2; mt++) {
                uint32_t ah[4], al[4];
                ldsm4(ah, sb + QF_SQH + (uint32_t)(arow + mt * 16) * 144 + ak);
                ldsm4(al, sb + QF_SQL + (uint32_t)(arow + mt * 16) * 144 + ak);
                #pragma unroll
                for (int nt = 0; nt < 2; nt++) {
                    mma16816(accQ[mt][nt], ah, &bh1[nt * 2]);
                    mma16816(accQ[mt][nt], ah, &bl1[nt * 2]);
                    mma16816(accQ[mt][nt], al, &bh1[nt * 2]);
                }
            }
        }
        #pragma unroll
        for (int mt = 0; mt < 2; mt++)
            #pragma unroll
            for (int nt = 0; nt < 2; nt++) {
                int rcol = wcq * 16 + nt * 8 + qc * 2;
                #pragma unroll
                for (int hf = 0; hf < 2; hf++) {
                    int row = wrq * 32 + mt * 16 + qr + hf * 8;
                    float v0 = fmaxf(accQ[mt][nt][hf * 2 + 0], 0.0f) + EPSF;
                    float v1 = fmaxf(accQ[mt][nt][hf * 2 + 1], 0.0f) + EPSF;
                    __nv_bfloat16 h0, l0, h1, l1;
                    split2(v0, h0, l0);
                    split2(v1, h1, l1);
                    *(__nv_bfloat162*)(smem + QF_SQPH + row * 80 + rcol * 2)
                        = __nv_bfloat162{h0, h1};
                    *(__nv_bfloat162*)(smem + QF_SQPL + row * 80 + rcol * 2)
                        = __nv_bfloat162{l0, l1};
                }
            }
        __syncthreads();

        {
            const __nv_bfloat16* ph = (const __nv_bfloat16*)(smem + QF_SQPH
                                        + drow * 80 + dhalf * 32);
            const __nv_bfloat16* pl = (const __nv_bfloat16*)(smem + QF_SQPL
                                        + drow * 80 + dhalf * 32);
            const float* ksp = ksumS + c * 32 + dhalf * 16;
            #pragma unroll
            for (int kk = 0; kk < 16; kk++) {
                float v = __bfloat162float(ph[kk]) + __bfloat162float(pl[kk]);
                myd += v * ksp[kk];
            }
        }

        const uint32_t aH = sb + QF_SQPH, aL = sb + QF_SQPL;
        const uint32_t bHc = sb + QF_KVT + (c & 1) * 10240;
        const uint32_t bLc = bHc + 5120;
        #pragma unroll
        for (int kt = 0; kt < 2; kt++) {
            uint32_t bh1[4], bl1[4];
            const int g = lane >> 3;
            const int brow = wc * 16 + (lane & 7) + (g >> 1) * 8;
            const uint32_t bk = (uint32_t)(kt * 16 + (g & 1) * 8) * 2;
            ldsm4(bh1, bHc + (uint32_t)brow * 80 + bk);
            ldsm4(bl1, bLc + (uint32_t)brow * 80 + bk);
            const int arow = wr * 64 + (lane & 15);
            const uint32_t ak = (uint32_t)(kt * 16 + (lane >> 4) * 8) * 2;
            #pragma unroll
            for (int mt = 0; mt < 4; mt++) {
                uint32_t ah[4], al[4];
                ldsm4(ah, aH + (uint32_t)(arow + mt * 16) * 80 + ak);
                ldsm4(al, aL + (uint32_t)(arow + mt * 16) * 80 + ak);
                #pragma unroll
                for (int nt = 0; nt < 2; nt++) {
                    mma16816(accO[mt][nt], ah, &bh1[nt * 2]);
                    mma16816(accO[mt][nt], ah, &bl1[nt * 2]);
                    mma16816(accO[mt][nt], al, &bh1[nt * 2]);
                }
            }
        }
        __syncthreads();
        if (c + 2 < 9) load_chunk(c + 2, c & 1);
    }

    dpart[dhalf][drow] = myd;
    __syncthreads();
    if (tid < 128) dinvS[tid] = 1.0f / (dpart[0][tid] + dpart[1][tid]);
    __syncthreads();

    #pragma unroll
    for (int mt = 0; mt < 4; mt++)
        #pragma unroll
        for (int nt = 0; nt < 2; nt++) {
            int d = wc * 16 + nt * 8 + qc * 2;
            #pragma unroll
            for (int hf = 0; hf < 2; hf++) {
                int lrow = wr * 64 + mt * 16 + qr + hf * 8;
                float di = dinvS[lrow];
                float2 v;
                v.x = tf32r(accO[mt][nt][hf * 2 + 0] * di);
                v.y = tf32r(accO[mt][nt][hf * 2 + 1] * di);
                *(float2*)(smem + QF_STF + lrow * 272 + d * 4) = v;
            }
        }
    __syncthreads();
    #pragma unroll
    for (int j = 0; j < 8; j++) {
        int idx = tid + j * 256;
        int rr = idx >> 4, c16 = idx & 15;
        float4 v = *(float4*)(smem + QF_STF + rr * 272 + c16 * 16);
        size_t o = ((size_t)(b * NN + n0 + rr)) * GK + h * 64 + c16 * 4;
        *(float4*)&g_om[o] = v;
    }
}

// ---------------- launch -----------------------------------------------------
extern "C" void kernel_launch(void* const* d_in, const int* in_sizes, int n_in,
                              void* d_out, int out_size)
{
    const float* x    = (const float*)d_in[0];
    const float* Wq   = (const float*)d_in[1];
    const float* Wk   = (const float*)d_in[2];
    const float* Wv   = (const float*)d_in[3];
    const float* Wo   = (const float*)d_in[4];
    const float* bo   = (const float*)d_in[5];
    const float* proj = (const float*)d_in[6];

    float *ksum, *xt, *wt, *om;
    cudaGetSymbolAddress((void**)&ksum, g_ksum);
    cudaGetSymbolAddress((void**)&xt,   g_xt);
    cudaGetSymbolAddress((void**)&wt,   g_wt);
    cudaGetSymbolAddress((void**)&om,   g_om);

    cudaFuncSetAttribute(gemm_tf32,
                         cudaFuncAttributeMaxDynamicSharedMemorySize, SMEMT);
    cudaFuncSetAttribute(featmap_hmma,
                         cudaFuncAttributeMaxDynamicSharedMemorySize, FM_SMEM);
    cudaFuncSetAttribute(kv_hmma,
                         cudaFuncAttributeMaxDynamicSharedMemorySize, KV_SMEM);
    cudaFuncSetAttribute(qkv_fused,
                         cudaFuncAttributeMaxDynamicSharedMemorySize, QF_SMEM);

    const int n4 = GM * GK / 4;

    xcvt<<<(n4 + 255) / 256, 256>>>(x, n4);
    wtrans<<<dim3(32, 32, 4), dim3(32, 8)>>>(Wq, Wk, Wv, Wo);
    psplit<<<80, 256>>>(proj);
    cudaMemsetAsync(ksum, 0, BHN * RP * sizeof(float));

    gemm_tf32<<<dim3(24, GM / 128), 256, SMEMT>>>(xt, wt, nullptr, nullptr, 0);

    featmap_hmma<<<dim3(32, 64), 256, FM_SMEM>>>();

    kv_hmma<<<dim3(BHN, 2, 2), 256, KV_SMEM>>>();

    kv_finalize<<<dim3(BHN, 5), 256>>>();

    qkv_fused<<<dim3(32, BHN), 256, QF_SMEM>>>();

    gemm_tf32<<<dim3(8, GM / 128), 256, SMEMT>>>(om, wt + 3 * (size_t)GN * GK,
                                                 bo, (float*)d_out, 1);
}